// round 2
// baseline (speedup 1.0000x reference)
#include <cuda_runtime.h>
#include <math.h>

#define BB      8192
#define IN_DIM  784
#define HID     1024
#define LAT     128
#define NT      10

// ---- scratch (static device globals; no allocation) ----
__device__ float g_bufA[BB * HID];   // 32 MB ping
__device__ float g_bufB[BB * HID];   // 32 MB pong
__device__ int   g_idx[BB];          // sorted-order -> original row
__device__ int   g_off[NT + 1];
__device__ int   g_cnt[NT];
__device__ int   g_fill[NT];

// ---- task grouping ----
__global__ void k_zero() {
    int i = threadIdx.x;
    if (i < NT) { g_cnt[i] = 0; g_fill[i] = 0; }
}
__global__ void k_count(const int* __restrict__ task) {
    int i = blockIdx.x * blockDim.x + threadIdx.x;
    if (i < BB) atomicAdd(&g_cnt[task[i]], 1);
}
__global__ void k_scan() {
    if (threadIdx.x == 0) {
        int s = 0;
        for (int t = 0; t < NT; t++) { g_off[t] = s; s += g_cnt[t]; }
        g_off[NT] = s;
    }
}
__global__ void k_fill(const int* __restrict__ task) {
    int i = blockIdx.x * blockDim.x + threadIdx.x;
    if (i < BB) {
        int t = task[i];
        int p = atomicAdd(&g_fill[t], 1);
        g_idx[g_off[t] + p] = i;
    }
}

// ---- tiled fp32 GEMM ----
// C[s, n] = sum_k A[row(s), k] * W[t][k, n] + bias[t][n]  (+ epilogue)
// EPI: 0 = bias+relu, 1 = bias only, 2 = bias+sigmoid, scatter rows via g_idx
#define BM 128
#define BN 128
#define BK 16

template <bool GATHER, bool PERTASK, int EPI>
__global__ __launch_bounds__(256, 2) void gemm(
    const float* __restrict__ A, int lda,
    const float* __restrict__ W, int K, int N,
    const float* __restrict__ bias,
    float* __restrict__ C, int ldc)
{
    __shared__ float As[BK][BM];
    __shared__ float Bs[BK][BN];

    int t    = PERTASK ? blockIdx.z : 0;
    int seg0 = PERTASK ? g_off[t]     : 0;
    int seg1 = PERTASK ? g_off[t + 1] : BB;
    int m0   = seg0 + blockIdx.y * BM;
    if (m0 >= seg1) return;
    int n0 = blockIdx.x * BN;

    const float* Wp = W    + (PERTASK ? (size_t)t * K * N : 0);
    const float* bp = bias + (PERTASK ? (size_t)t * N     : 0);

    int tid = threadIdx.x;

    // A-load mapping: 128 rows x 16 k, 2 threads per row, 8 k each (2x float4)
    int ar = tid & 127;
    int ak = (tid >> 7) * 8;
    int as = m0 + ar;
    bool avalid = (as < seg1);
    const float* Arow = nullptr;
    if (avalid) {
        int src = GATHER ? g_idx[as] : as;
        Arow = A + (size_t)src * lda;
    }

    // B-load mapping: 16 k-rows x 128 n, 16 threads per row, 8 n each
    int bk = tid >> 4;
    int bn = (tid & 15) * 8;

    int ty = tid >> 4;   // 0..15
    int tx = tid & 15;   // 0..15

    float acc[8][8];
#pragma unroll
    for (int i = 0; i < 8; i++)
#pragma unroll
        for (int j = 0; j < 8; j++) acc[i][j] = 0.f;

    for (int k0 = 0; k0 < K; k0 += BK) {
        // load A tile (transposed into As[k][m])
        if (avalid) {
            float4 a0 = *(const float4*)(Arow + k0 + ak);
            float4 a1 = *(const float4*)(Arow + k0 + ak + 4);
            As[ak + 0][ar] = a0.x; As[ak + 1][ar] = a0.y;
            As[ak + 2][ar] = a0.z; As[ak + 3][ar] = a0.w;
            As[ak + 4][ar] = a1.x; As[ak + 5][ar] = a1.y;
            As[ak + 6][ar] = a1.z; As[ak + 7][ar] = a1.w;
        } else {
#pragma unroll
            for (int q = 0; q < 8; q++) As[ak + q][ar] = 0.f;
        }
        // load B tile
        {
            const float* Wrow = Wp + (size_t)(k0 + bk) * N + n0 + bn;
            if (n0 + bn + 7 < N) {
                float4 b0 = *(const float4*)(Wrow);
                float4 b1 = *(const float4*)(Wrow + 4);
                Bs[bk][bn + 0] = b0.x; Bs[bk][bn + 1] = b0.y;
                Bs[bk][bn + 2] = b0.z; Bs[bk][bn + 3] = b0.w;
                Bs[bk][bn + 4] = b1.x; Bs[bk][bn + 5] = b1.y;
                Bs[bk][bn + 6] = b1.z; Bs[bk][bn + 7] = b1.w;
            } else {
#pragma unroll
                for (int q = 0; q < 8; q++)
                    Bs[bk][bn + q] = (n0 + bn + q < N) ? Wrow[q] : 0.f;
            }
        }
        __syncthreads();

#pragma unroll
        for (int k = 0; k < BK; k++) {
            float a[8], b[8];
            *(float4*)&a[0] = *(const float4*)&As[k][ty * 4];
            *(float4*)&a[4] = *(const float4*)&As[k][64 + ty * 4];
            *(float4*)&b[0] = *(const float4*)&Bs[k][tx * 4];
            *(float4*)&b[4] = *(const float4*)&Bs[k][64 + tx * 4];
#pragma unroll
            for (int i = 0; i < 8; i++)
#pragma unroll
                for (int j = 0; j < 8; j++)
                    acc[i][j] = fmaf(a[i], b[j], acc[i][j]);
        }
        __syncthreads();
    }

    // epilogue
#pragma unroll
    for (int i = 0; i < 8; i++) {
        int s = m0 + ((i < 4) ? (ty * 4 + i) : (64 + ty * 4 + i - 4));
        if (s >= seg1) continue;
        size_t outrow = (EPI == 2) ? (size_t)g_idx[s] : (size_t)s;
#pragma unroll
        for (int j = 0; j < 8; j++) {
            int n = n0 + ((j < 4) ? (tx * 4 + j) : (64 + tx * 4 + j - 4));
            if (n >= N) continue;
            float v = acc[i][j] + bp[n];
            if (EPI == 0)      v = fmaxf(v, 0.f);
            else if (EPI == 2) v = 1.f / (1.f + expf(-v));
            C[outrow * ldc + n] = v;
        }
    }
}

// reparameterization: reads enc (in g_bufB, ld 256), writes mu/log_sigma to out,
// writes z into g_bufA (ld 128)
__global__ void k_z(const float* __restrict__ eps, float* __restrict__ out) {
    int g = blockIdx.x * blockDim.x + threadIdx.x;
    if (g >= BB * LAT) return;
    int s = g >> 7;
    int j = g & 127;
    int orig = g_idx[s];
    float mu = g_bufB[(size_t)s * 256 + j];
    float ls = g_bufB[(size_t)s * 256 + 128 + j];
    size_t mu_off = (size_t)BB * IN_DIM;
    size_t ls_off = mu_off + (size_t)BB * LAT;
    out[mu_off + (size_t)orig * LAT + j] = mu;
    out[ls_off + (size_t)orig * LAT + j] = ls;
    g_bufA[(size_t)s * LAT + j] = mu + expf(ls) * eps[(size_t)orig * LAT + j];
}

extern "C" void kernel_launch(void* const* d_in, const int* in_sizes, int n_in,
                              void* d_out, int out_size) {
    const float* x    = (const float*)d_in[0];
    const int*   task = (const int*)  d_in[1];
    const float* eps  = (const float*)d_in[2];
    const float* eW1  = (const float*)d_in[3];
    const float* eb1  = (const float*)d_in[4];
    const float* eW2  = (const float*)d_in[5];
    const float* eb2  = (const float*)d_in[6];
    const float* eW3  = (const float*)d_in[7];
    const float* eb3  = (const float*)d_in[8];
    const float* eW4  = (const float*)d_in[9];
    const float* eb4  = (const float*)d_in[10];
    const float* dWs1 = (const float*)d_in[11];
    const float* dbs1 = (const float*)d_in[12];
    const float* dWs2 = (const float*)d_in[13];
    const float* dbs2 = (const float*)d_in[14];
    const float* dWh1 = (const float*)d_in[15];
    const float* dbh1 = (const float*)d_in[16];
    const float* dWh2 = (const float*)d_in[17];
    const float* dbh2 = (const float*)d_in[18];
    float* out = (float*)d_out;

    float *bufA, *bufB;
    cudaGetSymbolAddress((void**)&bufA, g_bufA);
    cudaGetSymbolAddress((void**)&bufB, g_bufB);

    // group samples by task
    k_zero<<<1, 32>>>();
    k_count<<<(BB + 255) / 256, 256>>>(task);
    k_scan<<<1, 32>>>();
    k_fill<<<(BB + 255) / 256, 256>>>(task);

    // encoder (per-task segments, activations kept in sorted order)
    gemm<true,  true, 0><<<dim3(8, 64, NT), 256>>>(x,    IN_DIM, eW1, IN_DIM, HID, eb1, bufA, HID);
    gemm<false, true, 0><<<dim3(8, 64, NT), 256>>>(bufA, HID,    eW2, HID,    HID, eb2, bufB, HID);
    gemm<false, true, 0><<<dim3(8, 64, NT), 256>>>(bufB, HID,    eW3, HID,    HID, eb3, bufA, HID);
    gemm<false, true, 1><<<dim3(2, 64, NT), 256>>>(bufA, HID,    eW4, HID, 2*LAT, eb4, bufB, 2*LAT);

    // reparameterize: mu/log_sigma -> d_out, z -> bufA
    k_z<<<(BB * LAT + 255) / 256, 256>>>(eps, out);

    // decoder
    gemm<false, false, 0><<<dim3(8, 64, 1),  256>>>(bufA, LAT, dWs1, LAT, HID, dbs1, bufB, HID);
    gemm<false, false, 0><<<dim3(8, 64, 1),  256>>>(bufB, HID, dWs2, HID, HID, dbs2, bufA, HID);
    gemm<false, true,  0><<<dim3(8, 64, NT), 256>>>(bufA, HID, dWh1, HID, HID, dbh1, bufB, HID);
    gemm<false, true,  2><<<dim3(7, 64, NT), 256>>>(bufB, HID, dWh2, HID, IN_DIM, dbh2, out, IN_DIM);
}

// round 8
// speedup vs baseline: 1.3855x; 1.3855x over previous
#include <cuda_runtime.h>
#include <math.h>
#include <cstdint>

#define BB      8192
#define IN_DIM  784
#define HID     1024
#define LAT     128
#define NT      10

// tcgen05 only exists on arch-specific targets (sm_103a). The harness also
// compiles a generic compute_103 pass, so guard the tensor path and provide a
// correct fp32 SIMT fallback in the other branch.
#if defined(__CUDA_ARCH__) && (__CUDA_ARCH__ == 1030) && \
    (defined(__CUDA_ARCH_FEAT_SM103_ALL) || \
     (defined(__CUDA_ARCH_SPECIFIC__) && (__CUDA_ARCH_SPECIFIC__ >= 1030)))
#define HAS_TC 1
#else
#define HAS_TC 0
#endif

// ---- scratch (static device globals; no allocation) ----
__device__ float g_bufA[BB * HID];
__device__ float g_bufB[BB * HID];
__device__ int   g_idx[BB];
__device__ int   g_off[NT + 1];
__device__ int   g_cnt[NT];
__device__ int   g_fill[NT];

// ---- task grouping ----
__global__ void k_zero() {
    int i = threadIdx.x;
    if (i < NT) { g_cnt[i] = 0; g_fill[i] = 0; }
}
__global__ void k_count(const int* __restrict__ task) {
    int i = blockIdx.x * blockDim.x + threadIdx.x;
    if (i < BB) atomicAdd(&g_cnt[task[i]], 1);
}
__global__ void k_scan() {
    if (threadIdx.x == 0) {
        int s = 0;
        for (int t = 0; t < NT; t++) { g_off[t] = s; s += g_cnt[t]; }
        g_off[NT] = s;
    }
}
__global__ void k_fill(const int* __restrict__ task) {
    int i = blockIdx.x * blockDim.x + threadIdx.x;
    if (i < BB) {
        int t = task[i];
        int p = atomicAdd(&g_fill[t], 1);
        g_idx[g_off[t] + p] = i;
    }
}

// ---------- tcgen05 helpers (arch-specific branch only) ----------
#if HAS_TC
__device__ __forceinline__ uint32_t smem_u32(const void* p) {
    uint32_t a;
    asm("{ .reg .u64 t; cvta.to.shared.u64 t, %1; cvt.u32.u64 %0, t; }" : "=r"(a) : "l"(p));
    return a;
}
__device__ __forceinline__ uint32_t elect1() {
    uint32_t r;
    asm volatile("{ .reg .pred p; elect.sync _|p, 0xFFFFFFFF; selp.b32 %0, 1, 0, p; }" : "=r"(r));
    return r;
}
__device__ __forceinline__ void mbar_init(uint32_t mbar, uint32_t cnt) {
    asm volatile("mbarrier.init.shared.b64 [%0], %1;" :: "r"(mbar), "r"(cnt) : "memory");
}
__device__ __forceinline__ void mbar_wait(uint32_t mbar, uint32_t parity) {
    asm volatile(
        "{\n\t.reg .pred P1;\n\t"
        "WAIT_%=:\n\t"
        "mbarrier.try_wait.parity.acquire.cta.shared::cta.b64 P1, [%0], %1, 0x989680;\n\t"
        "@P1 bra.uni DONE_%=;\n\t"
        "bra.uni WAIT_%=;\n\t"
        "DONE_%=:\n\t}"
        :: "r"(mbar), "r"(parity) : "memory");
}
__device__ __forceinline__ void mma_tf32(uint32_t d, uint64_t ad, uint64_t bd,
                                         uint32_t idesc, uint32_t en) {
    asm volatile(
        "{\n\t.reg .pred p;\n\t"
        "setp.ne.u32 p, %4, 0;\n\t"
        "tcgen05.mma.cta_group::1.kind::tf32 [%0], %1, %2, %3, {%5, %5, %5, %5}, p;\n\t}"
        :: "r"(d), "l"(ad), "l"(bd), "r"(idesc), "r"(en), "r"(0u) : "memory");
}
__device__ __forceinline__ void tc_commit(uint32_t mbar) {
    asm volatile("tcgen05.commit.cta_group::1.mbarrier::arrive::one.shared::cluster.b64 [%0];"
                 :: "r"(mbar) : "memory");
}
__device__ __forceinline__ float tf32_hi(float v) {
    uint32_t b;
    asm("cvt.rna.tf32.f32 %0, %1;" : "=r"(b) : "f"(v));
    return __uint_as_float(b);
}

#define TC_LD32(r, addr) \
    asm volatile( \
        "tcgen05.ld.sync.aligned.32x32b.x32.b32 " \
        "{%0, %1, %2, %3, %4, %5, %6, %7, " \
        " %8, %9, %10, %11, %12, %13, %14, %15, " \
        " %16, %17, %18, %19, %20, %21, %22, %23, " \
        " %24, %25, %26, %27, %28, %29, %30, %31}, [%32];" \
        : "=r"((r)[0]),  "=r"((r)[1]),  "=r"((r)[2]),  "=r"((r)[3]), \
          "=r"((r)[4]),  "=r"((r)[5]),  "=r"((r)[6]),  "=r"((r)[7]), \
          "=r"((r)[8]),  "=r"((r)[9]),  "=r"((r)[10]), "=r"((r)[11]), \
          "=r"((r)[12]), "=r"((r)[13]), "=r"((r)[14]), "=r"((r)[15]), \
          "=r"((r)[16]), "=r"((r)[17]), "=r"((r)[18]), "=r"((r)[19]), \
          "=r"((r)[20]), "=r"((r)[21]), "=r"((r)[22]), "=r"((r)[23]), \
          "=r"((r)[24]), "=r"((r)[25]), "=r"((r)[26]), "=r"((r)[27]), \
          "=r"((r)[28]), "=r"((r)[29]), "=r"((r)[30]), "=r"((r)[31]) \
        : "r"(addr))

// SW128 K-major descriptor: layout=2, version=1, SBO=64 (1024B group), LBO=1
static constexpr uint64_t DESC_BASE =
    (2ull << 61) | (1ull << 46) | (64ull << 32) | (1ull << 16);
__device__ __forceinline__ uint64_t mkdesc(uint32_t a) {
    return DESC_BASE | ((uint64_t)(a >> 4) & 0x3FFF);
}
#endif  // HAS_TC

#define SWZ(o) ((o) ^ (((o) >> 3) & 0x70))

// ---------- grouped GEMM: 128 x 256 tile per CTA ----------
#define NTILE 256
#define KC    32
#define SMEM_TMEM 0
#define SMEM_MB   16
#define SA_OFF    1024
// plain stage: A 16K @ +0, B 32K @ +16K  -> 48K/stage
// split stage: Ahi 16K, Alo 16K, Bhi 32K, Blo 32K -> 96K/stage
#define STAGE_P   49152
#define STAGE_S   98304
#define SMEM_TOT_P (SA_OFF + 2 * STAGE_P)   //  99328
#define SMEM_TOT_S (SA_OFF + 2 * STAGE_S)   // 197632

// idesc: dtype f32(1)<<4 | atype tf32(2)<<7 | btype tf32(2)<<10 | (N/8)<<17 | (M/16)<<24
static constexpr uint32_t IDESC =
    (1u << 4) | (2u << 7) | (2u << 10) | ((NTILE / 8) << 17) | ((128 / 16) << 24);

// EPI: 0 bias+relu, 1 bias only, 2 bias+sigmoid+row-scatter via g_idx
// SPLIT: 3xTF32 emulated-fp32 (encoder layers feeding mu/log_sigma)
template <bool GATHER, bool PERTASK, int EPI, bool SPLIT>
__global__ __launch_bounds__(256, SPLIT ? 1 : 2) void tgemm(
    const float* __restrict__ A, int lda,
    const float* __restrict__ W, int K, int N,
    const float* __restrict__ bias,
    float* __restrict__ C, int ldc)
{
    extern __shared__ __align__(1024) char smem[];

    int t    = PERTASK ? blockIdx.z : 0;
    int seg0 = PERTASK ? g_off[t]     : 0;
    int seg1 = PERTASK ? g_off[t + 1] : BB;
    int m0   = seg0 + blockIdx.y * 128;
    if (m0 >= seg1) return;
    int n0 = blockIdx.x * NTILE;

    const float* Wp = W    + (PERTASK ? (size_t)t * K * N : 0);
    const float* bp = bias + (PERTASK ? (size_t)t * N     : 0);

    int tid = threadIdx.x;

#if HAS_TC
    // ================= tcgen05 tf32 path =================
    const int STAGE_B = SPLIT ? STAGE_S : STAGE_P;
    uint32_t sb = smem_u32(smem);
    int wid = tid >> 5;
    int lid = tid & 31;

    if (wid == 0) {
        asm volatile("tcgen05.alloc.cta_group::1.sync.aligned.shared::cta.b32 [%0], %1;"
                     :: "r"(sb + SMEM_TMEM), "r"(256u) : "memory");
        asm volatile("tcgen05.relinquish_alloc_permit.cta_group::1.sync.aligned;");
    }
    if (tid == 0) { mbar_init(sb + SMEM_MB, 1); mbar_init(sb + SMEM_MB + 8, 1); }
    __syncthreads();
    uint32_t tmem;
    asm volatile("ld.shared.b32 %0, [%1];" : "=r"(tmem) : "r"(sb + SMEM_TMEM));

    int nch = (K + KC - 1) / KC;
    int ph[2] = {0, 0};

    int a_k4 = (tid & 7) * 4;
    int a_mb = tid >> 3;
    int b_n4 = (tid & 63) * 4;
    int b_kb = tid >> 6;

    for (int c = 0; c < nch; c++) {
        int s = c & 1;
        if (c >= 2) { mbar_wait(sb + SMEM_MB + 8 * s, ph[s]); ph[s] ^= 1; }
        int k0 = c * KC;
        char* sAh = smem + SA_OFF + s * STAGE_B;
        char* sAl = sAh + 16384;                     // SPLIT only
        char* sBh = smem + SA_OFF + (SPLIT ? 32768 : 16384) + s * STAGE_B;
        char* sBl = sBh + 32768;                     // SPLIT only

        // A tile [m=128][k=32] floats, SW128-swizzled, K-major
#pragma unroll
        for (int p = 0; p < 4; p++) {
            int m = p * 32 + a_mb;
            float4 v = make_float4(0.f, 0.f, 0.f, 0.f);
            if (k0 + a_k4 < K) {   // K % 4 == 0 for all layers
                int gs = m0 + m;
                int src = (gs < seg1) ? (GATHER ? g_idx[gs] : gs)
                                      : (GATHER ? g_idx[seg0] : seg0);
                v = *(const float4*)(A + (size_t)src * lda + k0 + a_k4);
            }
            uint32_t off = SWZ((uint32_t)(m * KC + a_k4) * 4);
            if (SPLIT) {
                float4 h, l;
                h.x = tf32_hi(v.x); l.x = v.x - h.x;
                h.y = tf32_hi(v.y); l.y = v.y - h.y;
                h.z = tf32_hi(v.z); l.z = v.z - h.z;
                h.w = tf32_hi(v.w); l.w = v.w - h.w;
                *(float4*)(sAh + off) = h;
                *(float4*)(sAl + off) = l;
            } else {
                *(float4*)(sAh + off) = v;
            }
        }
        // B tile [n=256][k=32] floats from W[k][n] (transpose in STS)
#pragma unroll
        for (int p = 0; p < 8; p++) {
            int k = p * 4 + b_kb;
            float4 v = make_float4(0.f, 0.f, 0.f, 0.f);
            if (k0 + k < K && n0 + b_n4 < N)   // N % 4 == 0 for all layers
                v = *(const float4*)(Wp + (size_t)(k0 + k) * N + n0 + b_n4);
            uint32_t o0 = SWZ((uint32_t)((b_n4 + 0) * KC + k) * 4);
            uint32_t o1 = SWZ((uint32_t)((b_n4 + 1) * KC + k) * 4);
            uint32_t o2 = SWZ((uint32_t)((b_n4 + 2) * KC + k) * 4);
            uint32_t o3 = SWZ((uint32_t)((b_n4 + 3) * KC + k) * 4);
            if (SPLIT) {
                float hx = tf32_hi(v.x), hy = tf32_hi(v.y);
                float hz = tf32_hi(v.z), hw = tf32_hi(v.w);
                *(float*)(sBh + o0) = hx; *(float*)(sBl + o0) = v.x - hx;
                *(float*)(sBh + o1) = hy; *(float*)(sBl + o1) = v.y - hy;
                *(float*)(sBh + o2) = hz; *(float*)(sBl + o2) = v.z - hz;
                *(float*)(sBh + o3) = hw; *(float*)(sBl + o3) = v.w - hw;
            } else {
                *(float*)(sBh + o0) = v.x;
                *(float*)(sBh + o1) = v.y;
                *(float*)(sBh + o2) = v.z;
                *(float*)(sBh + o3) = v.w;
            }
        }
        asm volatile("fence.proxy.async.shared::cta;" ::: "memory");
        __syncthreads();

        if (wid == 0) {
            if (elect1()) {
                uint64_t adh = mkdesc(smem_u32(sAh));
                uint64_t bdh = mkdesc(smem_u32(sBh));
                if (SPLIT) {
                    uint64_t adl = mkdesc(smem_u32(sAl));
                    uint64_t bdl = mkdesc(smem_u32(sBl));
#pragma unroll
                    for (int j = 0; j < 4; j++) {
                        // small terms first, hi*hi last
                        mma_tf32(tmem, adl + j * 2, bdh + j * 2, IDESC,
                                 (c > 0 || j > 0) ? 1u : 0u);
                        mma_tf32(tmem, adh + j * 2, bdl + j * 2, IDESC, 1u);
                        mma_tf32(tmem, adh + j * 2, bdh + j * 2, IDESC, 1u);
                    }
                } else {
#pragma unroll
                    for (int j = 0; j < 4; j++)
                        mma_tf32(tmem, adh + j * 2, bdh + j * 2, IDESC,
                                 (c > 0 || j > 0) ? 1u : 0u);
                }
                tc_commit(sb + SMEM_MB + 8 * s);
            }
        }
    }

    int sl = (nch - 1) & 1;
    mbar_wait(sb + SMEM_MB + 8 * sl, ph[sl]);
    asm volatile("tcgen05.fence::after_thread_sync;" ::: "memory");

    // epilogue: warp w -> rows (w&3)*32+lid (its TMEM subpartition), cols (w>>2)*128
    int rw = wid & 3;
    int chh = wid >> 2;
    int row = m0 + rw * 32 + lid;
    bool rvalid = row < seg1;
    size_t orow = 0;
    if (rvalid) orow = (EPI == 2) ? (size_t)g_idx[row] : (size_t)row;

#pragma unroll
    for (int i = 0; i < 4; i++) {
        uint32_t r[32];
        TC_LD32(r, tmem + chh * 128 + i * 32);
        asm volatile("tcgen05.wait::ld.sync.aligned;" ::: "memory");
        if (rvalid) {
            int nb = n0 + chh * 128 + i * 32;
#pragma unroll
            for (int c2 = 0; c2 < 32; c2++) {
                int n = nb + c2;
                if (n < N) {
                    float v = __uint_as_float(r[c2]) + bp[n];
                    if (EPI == 0)      v = fmaxf(v, 0.f);
                    else if (EPI == 2) v = 1.f / (1.f + expf(-v));
                    C[orow * ldc + n] = v;
                }
            }
        }
    }

    asm volatile("tcgen05.fence::before_thread_sync;" ::: "memory");
    __syncthreads();
    if (wid == 0)
        asm volatile("tcgen05.dealloc.cta_group::1.sync.aligned.b32 %0, %1;"
                     :: "r"(tmem), "r"(256u));

#else
    // ================= fp32 SIMT fallback (verified round-2 code) =================
    const int BK = 16;
    float* As = (float*)smem;                   // [BK][128]
    float* Bs = (float*)(smem + BK * 128 * 4);  // [BK][128]

    int ar = tid & 127;
    int ak = (tid >> 7) * 8;
    int as_ = m0 + ar;
    bool avalid = (as_ < seg1);
    const float* Arow = nullptr;
    if (avalid) {
        int src = GATHER ? g_idx[as_] : as_;
        Arow = A + (size_t)src * lda;
    }
    int bk = tid >> 4;
    int bn = (tid & 15) * 8;
    int ty = tid >> 4;
    int tx = tid & 15;

    for (int half = 0; half < 2; half++) {
        int n0h = n0 + half * 128;
        if (n0h >= N) break;

        float acc[8][8];
#pragma unroll
        for (int i = 0; i < 8; i++)
#pragma unroll
            for (int j = 0; j < 8; j++) acc[i][j] = 0.f;

        for (int k0 = 0; k0 < K; k0 += BK) {
            if (avalid) {
                float4 a0 = *(const float4*)(Arow + k0 + ak);
                float4 a1 = *(const float4*)(Arow + k0 + ak + 4);
                As[(ak + 0) * 128 + ar] = a0.x; As[(ak + 1) * 128 + ar] = a0.y;
                As[(ak + 2) * 128 + ar] = a0.z; As[(ak + 3) * 128 + ar] = a0.w;
                As[(ak + 4) * 128 + ar] = a1.x; As[(ak + 5) * 128 + ar] = a1.y;
                As[(ak + 6) * 128 + ar] = a1.z; As[(ak + 7) * 128 + ar] = a1.w;
            } else {
#pragma unroll
                for (int q = 0; q < 8; q++) As[(ak + q) * 128 + ar] = 0.f;
            }
            {
                const float* Wrow = Wp + (size_t)(k0 + bk) * N + n0h + bn;
                if (n0h + bn + 7 < N) {
                    float4 b0 = *(const float4*)(Wrow);
                    float4 b1 = *(const float4*)(Wrow + 4);
                    Bs[bk * 128 + bn + 0] = b0.x; Bs[bk * 128 + bn + 1] = b0.y;
                    Bs[bk * 128 + bn + 2] = b0.z; Bs[bk * 128 + bn + 3] = b0.w;
                    Bs[bk * 128 + bn + 4] = b1.x; Bs[bk * 128 + bn + 5] = b1.y;
                    Bs[bk * 128 + bn + 6] = b1.z; Bs[bk * 128 + bn + 7] = b1.w;
                } else {
#pragma unroll
                    for (int q = 0; q < 8; q++)
                        Bs[bk * 128 + bn + q] = (n0h + bn + q < N) ? Wrow[q] : 0.f;
                }
            }
            __syncthreads();
#pragma unroll
            for (int k = 0; k < BK; k++) {
                float a[8], b[8];
                *(float4*)&a[0] = *(const float4*)&As[k * 128 + ty * 4];
                *(float4*)&a[4] = *(const float4*)&As[k * 128 + 64 + ty * 4];
                *(float4*)&b[0] = *(const float4*)&Bs[k * 128 + tx * 4];
                *(float4*)&b[4] = *(const float4*)&Bs[k * 128 + 64 + tx * 4];
#pragma unroll
                for (int i = 0; i < 8; i++)
#pragma unroll
                    for (int j = 0; j < 8; j++)
                        acc[i][j] = fmaf(a[i], b[j], acc[i][j]);
            }
            __syncthreads();
        }

#pragma unroll
        for (int i = 0; i < 8; i++) {
            int s = m0 + ((i < 4) ? (ty * 4 + i) : (64 + ty * 4 + i - 4));
            if (s >= seg1) continue;
            size_t outrow = (EPI == 2) ? (size_t)g_idx[s] : (size_t)s;
#pragma unroll
            for (int j = 0; j < 8; j++) {
                int n = n0h + ((j < 4) ? (tx * 4 + j) : (64 + tx * 4 + j - 4));
                if (n >= N) continue;
                float v = acc[i][j] + bp[n];
                if (EPI == 0)      v = fmaxf(v, 0.f);
                else if (EPI == 2) v = 1.f / (1.f + expf(-v));
                C[outrow * ldc + n] = v;
            }
        }
        __syncthreads();
    }
#endif
}

// reparameterization: enc (bufB, ld 256) -> mu/log_sigma in out, z -> bufA (ld 128)
__global__ void k_z(const float* __restrict__ eps, float* __restrict__ out) {
    int g = blockIdx.x * blockDim.x + threadIdx.x;
    if (g >= BB * LAT) return;
    int s = g >> 7;
    int j = g & 127;
    int orig = g_idx[s];
    float mu = g_bufB[(size_t)s * 256 + j];
    float ls = g_bufB[(size_t)s * 256 + 128 + j];
    size_t mu_off = (size_t)BB * IN_DIM;
    size_t ls_off = mu_off + (size_t)BB * LAT;
    out[mu_off + (size_t)orig * LAT + j] = mu;
    out[ls_off + (size_t)orig * LAT + j] = ls;
    g_bufA[(size_t)s * LAT + j] = mu + expf(ls) * eps[(size_t)orig * LAT + j];
}

extern "C" void kernel_launch(void* const* d_in, const int* in_sizes, int n_in,
                              void* d_out, int out_size) {
    const float* x    = (const float*)d_in[0];
    const int*   task = (const int*)  d_in[1];
    const float* eps  = (const float*)d_in[2];
    const float* eW1  = (const float*)d_in[3];
    const float* eb1  = (const float*)d_in[4];
    const float* eW2  = (const float*)d_in[5];
    const float* eb2  = (const float*)d_in[6];
    const float* eW3  = (const float*)d_in[7];
    const float* eb3  = (const float*)d_in[8];
    const float* eW4  = (const float*)d_in[9];
    const float* eb4  = (const float*)d_in[10];
    const float* dWs1 = (const float*)d_in[11];
    const float* dbs1 = (const float*)d_in[12];
    const float* dWs2 = (const float*)d_in[13];
    const float* dbs2 = (const float*)d_in[14];
    const float* dWh1 = (const float*)d_in[15];
    const float* dbh1 = (const float*)d_in[16];
    const float* dWh2 = (const float*)d_in[17];
    const float* dbh2 = (const float*)d_in[18];
    float* out = (float*)d_out;

    float *bufA, *bufB;
    cudaGetSymbolAddress((void**)&bufA, g_bufA);
    cudaGetSymbolAddress((void**)&bufB, g_bufB);

    // encoder (3xTF32 split) instances
    cudaFuncSetAttribute(tgemm<true,  true,  0, true>,  cudaFuncAttributeMaxDynamicSharedMemorySize, SMEM_TOT_S);
    cudaFuncSetAttribute(tgemm<false, true,  0, true>,  cudaFuncAttributeMaxDynamicSharedMemorySize, SMEM_TOT_S);
    cudaFuncSetAttribute(tgemm<false, true,  1, true>,  cudaFuncAttributeMaxDynamicSharedMemorySize, SMEM_TOT_S);
    // decoder (plain TF32) instances
    cudaFuncSetAttribute(tgemm<false, false, 0, false>, cudaFuncAttributeMaxDynamicSharedMemorySize, SMEM_TOT_P);
    cudaFuncSetAttribute(tgemm<false, true,  0, false>, cudaFuncAttributeMaxDynamicSharedMemorySize, SMEM_TOT_P);
    cudaFuncSetAttribute(tgemm<false, true,  2, false>, cudaFuncAttributeMaxDynamicSharedMemorySize, SMEM_TOT_P);

    // group samples by task
    k_zero<<<1, 32>>>();
    k_count<<<(BB + 255) / 256, 256>>>(task);
    k_scan<<<1, 32>>>();
    k_fill<<<(BB + 255) / 256, 256>>>(task);

    // encoder (per-task segments, activations kept in sorted order) — 3xTF32
    tgemm<true,  true, 0, true><<<dim3(4, 64, NT), 256, SMEM_TOT_S>>>(x,    IN_DIM, eW1, IN_DIM, HID,   eb1, bufA, HID);
    tgemm<false, true, 0, true><<<dim3(4, 64, NT), 256, SMEM_TOT_S>>>(bufA, HID,    eW2, HID,    HID,   eb2, bufB, HID);
    tgemm<false, true, 0, true><<<dim3(4, 64, NT), 256, SMEM_TOT_S>>>(bufB, HID,    eW3, HID,    HID,   eb3, bufA, HID);
    tgemm<false, true, 1, true><<<dim3(1, 64, NT), 256, SMEM_TOT_S>>>(bufA, HID,    eW4, HID,    2*LAT, eb4, bufB, 2*LAT);

    // reparameterize: mu/log_sigma -> d_out, z -> bufA
    k_z<<<(BB * LAT + 255) / 256, 256>>>(eps, out);

    // decoder — plain TF32
    tgemm<false, false, 0, false><<<dim3(4, 64, 1),  256, SMEM_TOT_P>>>(bufA, LAT, dWs1, LAT, HID,    dbs1, bufB, HID);
    tgemm<false, false, 0, false><<<dim3(4, 64, 1),  256, SMEM_TOT_P>>>(bufB, HID, dWs2, HID, HID,    dbs2, bufA, HID);
    tgemm<false, true,  0, false><<<dim3(4, 64, NT), 256, SMEM_TOT_P>>>(bufA, HID, dWh1, HID, HID,    dbh1, bufB, HID);
    tgemm<false, true,  2, false><<<dim3(4, 64, NT), 256, SMEM_TOT_P>>>(bufB, HID, dWh2, HID, IN_DIM, dbh2, out, IN_DIM);
}

// round 9
// speedup vs baseline: 2.4458x; 1.7653x over previous
#include <cuda_runtime.h>
#include <math.h>
#include <cstdint>

#define BB      8192
#define IN_DIM  784
#define HID     1024
#define LAT     128
#define NT      10

// tcgen05 only exists on arch-specific targets (sm_103a). The harness also
// compiles a generic compute_103 pass, so guard the tensor path and provide a
// correct fp32 SIMT fallback in the other branch.
#if defined(__CUDA_ARCH__) && (__CUDA_ARCH__ == 1030) && \
    (defined(__CUDA_ARCH_FEAT_SM103_ALL) || \
     (defined(__CUDA_ARCH_SPECIFIC__) && (__CUDA_ARCH_SPECIFIC__ >= 1030)))
#define HAS_TC 1
#else
#define HAS_TC 0
#endif

// ---- scratch (static device globals; no allocation) ----
__device__ float g_bufA[BB * HID];
__device__ float g_bufB[BB * HID];
__device__ int   g_idx[BB];
__device__ int   g_off[NT + 1];
__device__ int   g_cnt[NT];
__device__ int   g_fill[NT];

// ---- task grouping ----
__global__ void k_zero() {
    int i = threadIdx.x;
    if (i < NT) { g_cnt[i] = 0; g_fill[i] = 0; }
}
__global__ void k_count(const int* __restrict__ task) {
    int i = blockIdx.x * blockDim.x + threadIdx.x;
    if (i < BB) atomicAdd(&g_cnt[task[i]], 1);
}
__global__ void k_scan() {
    if (threadIdx.x == 0) {
        int s = 0;
        for (int t = 0; t < NT; t++) { g_off[t] = s; s += g_cnt[t]; }
        g_off[NT] = s;
    }
}
__global__ void k_fill(const int* __restrict__ task) {
    int i = blockIdx.x * blockDim.x + threadIdx.x;
    if (i < BB) {
        int t = task[i];
        int p = atomicAdd(&g_fill[t], 1);
        g_idx[g_off[t] + p] = i;
    }
}

// ---------- tcgen05 helpers (arch-specific branch only) ----------
#if HAS_TC
__device__ __forceinline__ uint32_t smem_u32(const void* p) {
    uint32_t a;
    asm("{ .reg .u64 t; cvta.to.shared.u64 t, %1; cvt.u32.u64 %0, t; }" : "=r"(a) : "l"(p));
    return a;
}
__device__ __forceinline__ uint32_t elect1() {
    uint32_t r;
    asm volatile("{ .reg .pred p; elect.sync _|p, 0xFFFFFFFF; selp.b32 %0, 1, 0, p; }" : "=r"(r));
    return r;
}
__device__ __forceinline__ void mbar_init(uint32_t mbar, uint32_t cnt) {
    asm volatile("mbarrier.init.shared.b64 [%0], %1;" :: "r"(mbar), "r"(cnt) : "memory");
}
__device__ __forceinline__ void mbar_wait(uint32_t mbar, uint32_t parity) {
    asm volatile(
        "{\n\t.reg .pred P1;\n\t"
        "WAIT_%=:\n\t"
        "mbarrier.try_wait.parity.acquire.cta.shared::cta.b64 P1, [%0], %1, 0x989680;\n\t"
        "@P1 bra.uni DONE_%=;\n\t"
        "bra.uni WAIT_%=;\n\t"
        "DONE_%=:\n\t}"
        :: "r"(mbar), "r"(parity) : "memory");
}
__device__ __forceinline__ void mma_tf32(uint32_t d, uint64_t ad, uint64_t bd,
                                         uint32_t idesc, uint32_t en) {
    asm volatile(
        "{\n\t.reg .pred p;\n\t"
        "setp.ne.u32 p, %4, 0;\n\t"
        "tcgen05.mma.cta_group::1.kind::tf32 [%0], %1, %2, %3, {%5, %5, %5, %5}, p;\n\t}"
        :: "r"(d), "l"(ad), "l"(bd), "r"(idesc), "r"(en), "r"(0u) : "memory");
}
__device__ __forceinline__ void tc_commit(uint32_t mbar) {
    asm volatile("tcgen05.commit.cta_group::1.mbarrier::arrive::one.shared::cluster.b64 [%0];"
                 :: "r"(mbar) : "memory");
}
__device__ __forceinline__ float tf32_hi(float v) {
    uint32_t b;
    asm("cvt.rna.tf32.f32 %0, %1;" : "=r"(b) : "f"(v));
    return __uint_as_float(b);
}

#define TC_LD32(r, addr) \
    asm volatile( \
        "tcgen05.ld.sync.aligned.32x32b.x32.b32 " \
        "{%0, %1, %2, %3, %4, %5, %6, %7, " \
        " %8, %9, %10, %11, %12, %13, %14, %15, " \
        " %16, %17, %18, %19, %20, %21, %22, %23, " \
        " %24, %25, %26, %27, %28, %29, %30, %31}, [%32];" \
        : "=r"((r)[0]),  "=r"((r)[1]),  "=r"((r)[2]),  "=r"((r)[3]), \
          "=r"((r)[4]),  "=r"((r)[5]),  "=r"((r)[6]),  "=r"((r)[7]), \
          "=r"((r)[8]),  "=r"((r)[9]),  "=r"((r)[10]), "=r"((r)[11]), \
          "=r"((r)[12]), "=r"((r)[13]), "=r"((r)[14]), "=r"((r)[15]), \
          "=r"((r)[16]), "=r"((r)[17]), "=r"((r)[18]), "=r"((r)[19]), \
          "=r"((r)[20]), "=r"((r)[21]), "=r"((r)[22]), "=r"((r)[23]), \
          "=r"((r)[24]), "=r"((r)[25]), "=r"((r)[26]), "=r"((r)[27]), \
          "=r"((r)[28]), "=r"((r)[29]), "=r"((r)[30]), "=r"((r)[31]) \
        : "r"(addr))

// SW128 K-major descriptor: layout=2, version=1, SBO=64 (1024B group), LBO=1
static constexpr uint64_t DESC_BASE =
    (2ull << 61) | (1ull << 46) | (64ull << 32) | (1ull << 16);
__device__ __forceinline__ uint64_t mkdesc(uint32_t a) {
    return DESC_BASE | ((uint64_t)(a >> 4) & 0x3FFF);
}
#endif  // HAS_TC

#define SWZ(o) ((o) ^ (((o) >> 3) & 0x70))

// ---------- grouped GEMM: 128 x 256 tile per CTA ----------
#define NTILE 256
#define KC    32
#define SMEM_TMEM 0
#define SMEM_MB   16
#define SA_OFF    1024
// plain stage: A 16K @ +0, B 32K @ +16K  -> 48K/stage
// split stage: Ahi 16K, Alo 16K, Bhi 32K, Blo 32K -> 96K/stage
#define STAGE_P   49152
#define STAGE_S   98304
#define SMEM_TOT_P (SA_OFF + 2 * STAGE_P)   //  99328
#define SMEM_TOT_S (SA_OFF + 2 * STAGE_S)   // 197632

// idesc: dtype f32(1)<<4 | atype tf32(2)<<7 | btype tf32(2)<<10 | (N/8)<<17 | (M/16)<<24
static constexpr uint32_t IDESC =
    (1u << 4) | (2u << 7) | (2u << 10) | ((NTILE / 8) << 17) | ((128 / 16) << 24);

// EPI: 0 bias+relu, 1 bias only, 2 bias+sigmoid+row-scatter via g_idx
// SPLIT: 3xTF32 emulated-fp32 (encoder layers feeding mu/log_sigma)
template <bool GATHER, bool PERTASK, int EPI, bool SPLIT>
__global__ __launch_bounds__(256, SPLIT ? 1 : 2) void tgemm(
    const float* __restrict__ A, int lda,
    const float* __restrict__ W, int K, int N,
    const float* __restrict__ bias,
    float* __restrict__ C, int ldc)
{
    extern __shared__ __align__(1024) char smem[];

    int t    = PERTASK ? blockIdx.z : 0;
    int seg0 = PERTASK ? g_off[t]     : 0;
    int seg1 = PERTASK ? g_off[t + 1] : BB;
    int m0   = seg0 + blockIdx.y * 128;
    if (m0 >= seg1) return;
    int n0 = blockIdx.x * NTILE;

    const float* Wp = W    + (PERTASK ? (size_t)t * K * N : 0);
    const float* bp = bias + (PERTASK ? (size_t)t * N     : 0);

    int tid = threadIdx.x;

#if HAS_TC
    // ================= tcgen05 tf32 path =================
    const int STAGE_B = SPLIT ? STAGE_S : STAGE_P;
    uint32_t sb = smem_u32(smem);
    int wid = tid >> 5;
    int lid = tid & 31;

    if (wid == 0) {
        asm volatile("tcgen05.alloc.cta_group::1.sync.aligned.shared::cta.b32 [%0], %1;"
                     :: "r"(sb + SMEM_TMEM), "r"(256u) : "memory");
        asm volatile("tcgen05.relinquish_alloc_permit.cta_group::1.sync.aligned;");
    }
    if (tid == 0) { mbar_init(sb + SMEM_MB, 1); mbar_init(sb + SMEM_MB + 8, 1); }
    __syncthreads();
    uint32_t tmem;
    asm volatile("ld.shared.b32 %0, [%1];" : "=r"(tmem) : "r"(sb + SMEM_TMEM));

    int nch = (K + KC - 1) / KC;
    int ph[2] = {0, 0};

    // A fill mapping (conflict-free: lanes vary k at fixed m)
    int a_k4 = (tid & 7) * 4;
    int a_mb = tid >> 3;
    // B fill mapping: thread owns ONE column n = n0 + tid, walks k.
    // Loads: at fixed k, lanes read consecutive n -> coalesced 128B.
    // Stores: STS.128 at o = n*128 + 16*kg; within an 8-lane phase n&7 spans
    // 0..7 -> banks k^0,k^4,...,k^28 -> conflict-free (this was the round-8
    // bottleneck: the old mapping had 16-way STS conflicts).
    int b_n = tid;                       // 0..255 == NTILE
    bool b_nv = (n0 + b_n < N);
    const float* Wcol = Wp + n0 + b_n;

    for (int c = 0; c < nch; c++) {
        int s = c & 1;
        if (c >= 2) { mbar_wait(sb + SMEM_MB + 8 * s, ph[s]); ph[s] ^= 1; }
        int k0 = c * KC;
        char* sAh = smem + SA_OFF + s * STAGE_B;
        char* sAl = sAh + 16384;                     // SPLIT only
        char* sBh = smem + SA_OFF + (SPLIT ? 32768 : 16384) + s * STAGE_B;
        char* sBl = sBh + 32768;                     // SPLIT only

        // A tile [m=128][k=32] floats, SW128-swizzled, K-major
#pragma unroll
        for (int p = 0; p < 4; p++) {
            int m = p * 32 + a_mb;
            float4 v = make_float4(0.f, 0.f, 0.f, 0.f);
            if (k0 + a_k4 < K) {   // K % 4 == 0 for all layers
                int gs = m0 + m;
                int src = (gs < seg1) ? (GATHER ? g_idx[gs] : gs)
                                      : (GATHER ? g_idx[seg0] : seg0);
                v = *(const float4*)(A + (size_t)src * lda + k0 + a_k4);
            }
            uint32_t off = SWZ((uint32_t)(m * KC + a_k4) * 4);
            if (SPLIT) {
                float4 h, l;
                h.x = tf32_hi(v.x); l.x = v.x - h.x;
                h.y = tf32_hi(v.y); l.y = v.y - h.y;
                h.z = tf32_hi(v.z); l.z = v.z - h.z;
                h.w = tf32_hi(v.w); l.w = v.w - h.w;
                *(float4*)(sAh + off) = h;
                *(float4*)(sAl + off) = l;
            } else {
                *(float4*)(sAh + off) = v;
            }
        }
        // B tile [n=256][k=32] floats from W[k][n] — column-per-thread, STS.128
#pragma unroll
        for (int kg = 0; kg < 8; kg++) {
            float v0 = 0.f, v1 = 0.f, v2 = 0.f, v3 = 0.f;
            if (b_nv) {
                int k = k0 + kg * 4;
                // K is a multiple of 4 for all layers, so k+3 < K iff k < K
                if (k < K) {
                    v0 = Wcol[(size_t)(k + 0) * N];
                    v1 = Wcol[(size_t)(k + 1) * N];
                    v2 = Wcol[(size_t)(k + 2) * N];
                    v3 = Wcol[(size_t)(k + 3) * N];
                }
            }
            uint32_t off = SWZ((uint32_t)(b_n * KC + kg * 4) * 4);
            if (SPLIT) {
                float4 h, l;
                h.x = tf32_hi(v0); l.x = v0 - h.x;
                h.y = tf32_hi(v1); l.y = v1 - h.y;
                h.z = tf32_hi(v2); l.z = v2 - h.z;
                h.w = tf32_hi(v3); l.w = v3 - h.w;
                *(float4*)(sBh + off) = h;
                *(float4*)(sBl + off) = l;
            } else {
                *(float4*)(sBh + off) = make_float4(v0, v1, v2, v3);
            }
        }
        asm volatile("fence.proxy.async.shared::cta;" ::: "memory");
        __syncthreads();

        if (wid == 0) {
            if (elect1()) {
                uint64_t adh = mkdesc(smem_u32(sAh));
                uint64_t bdh = mkdesc(smem_u32(sBh));
                if (SPLIT) {
                    uint64_t adl = mkdesc(smem_u32(sAl));
                    uint64_t bdl = mkdesc(smem_u32(sBl));
#pragma unroll
                    for (int j = 0; j < 4; j++) {
                        // small terms first, hi*hi last
                        mma_tf32(tmem, adl + j * 2, bdh + j * 2, IDESC,
                                 (c > 0 || j > 0) ? 1u : 0u);
                        mma_tf32(tmem, adh + j * 2, bdl + j * 2, IDESC, 1u);
                        mma_tf32(tmem, adh + j * 2, bdh + j * 2, IDESC, 1u);
                    }
                } else {
#pragma unroll
                    for (int j = 0; j < 4; j++)
                        mma_tf32(tmem, adh + j * 2, bdh + j * 2, IDESC,
                                 (c > 0 || j > 0) ? 1u : 0u);
                }
                tc_commit(sb + SMEM_MB + 8 * s);
            }
        }
    }

    int sl = (nch - 1) & 1;
    mbar_wait(sb + SMEM_MB + 8 * sl, ph[sl]);
    asm volatile("tcgen05.fence::after_thread_sync;" ::: "memory");

    // epilogue: warp w -> rows (w&3)*32+lid (its TMEM subpartition), cols (w>>2)*128
    int rw = wid & 3;
    int chh = wid >> 2;
    int row = m0 + rw * 32 + lid;
    bool rvalid = row < seg1;
    size_t orow = 0;
    if (rvalid) orow = (EPI == 2) ? (size_t)g_idx[row] : (size_t)row;

#pragma unroll
    for (int i = 0; i < 4; i++) {
        uint32_t r[32];
        TC_LD32(r, tmem + chh * 128 + i * 32);
        asm volatile("tcgen05.wait::ld.sync.aligned;" ::: "memory");
        if (rvalid) {
            int nb = n0 + chh * 128 + i * 32;
#pragma unroll
            for (int c2 = 0; c2 < 32; c2++) {
                int n = nb + c2;
                if (n < N) {
                    float v = __uint_as_float(r[c2]) + bp[n];
                    if (EPI == 0)      v = fmaxf(v, 0.f);
                    else if (EPI == 2) v = 1.f / (1.f + expf(-v));
                    C[orow * ldc + n] = v;
                }
            }
        }
    }

    asm volatile("tcgen05.fence::before_thread_sync;" ::: "memory");
    __syncthreads();
    if (wid == 0)
        asm volatile("tcgen05.dealloc.cta_group::1.sync.aligned.b32 %0, %1;"
                     :: "r"(tmem), "r"(256u));

#else
    // ================= fp32 SIMT fallback (verified round-2 code) =================
    const int BK = 16;
    float* As = (float*)smem;                   // [BK][128]
    float* Bs = (float*)(smem + BK * 128 * 4);  // [BK][128]

    int ar = tid & 127;
    int ak = (tid >> 7) * 8;
    int as_ = m0 + ar;
    bool avalid = (as_ < seg1);
    const float* Arow = nullptr;
    if (avalid) {
        int src = GATHER ? g_idx[as_] : as_;
        Arow = A + (size_t)src * lda;
    }
    int bk = tid >> 4;
    int bn = (tid & 15) * 8;
    int ty = tid >> 4;
    int tx = tid & 15;

    for (int half = 0; half < 2; half++) {
        int n0h = n0 + half * 128;
        if (n0h >= N) break;

        float acc[8][8];
#pragma unroll
        for (int i = 0; i < 8; i++)
#pragma unroll
            for (int j = 0; j < 8; j++) acc[i][j] = 0.f;

        for (int k0 = 0; k0 < K; k0 += BK) {
            if (avalid) {
                float4 a0 = *(const float4*)(Arow + k0 + ak);
                float4 a1 = *(const float4*)(Arow + k0 + ak + 4);
                As[(ak + 0) * 128 + ar] = a0.x; As[(ak + 1) * 128 + ar] = a0.y;
                As[(ak + 2) * 128 + ar] = a0.z; As[(ak + 3) * 128 + ar] = a0.w;
                As[(ak + 4) * 128 + ar] = a1.x; As[(ak + 5) * 128 + ar] = a1.y;
                As[(ak + 6) * 128 + ar] = a1.z; As[(ak + 7) * 128 + ar] = a1.w;
            } else {
#pragma unroll
                for (int q = 0; q < 8; q++) As[(ak + q) * 128 + ar] = 0.f;
            }
            {
                const float* Wrow = Wp + (size_t)(k0 + bk) * N + n0h + bn;
                if (n0h + bn + 7 < N) {
                    float4 b0 = *(const float4*)(Wrow);
                    float4 b1 = *(const float4*)(Wrow + 4);
                    Bs[bk * 128 + bn + 0] = b0.x; Bs[bk * 128 + bn + 1] = b0.y;
                    Bs[bk * 128 + bn + 2] = b0.z; Bs[bk * 128 + bn + 3] = b0.w;
                    Bs[bk * 128 + bn + 4] = b1.x; Bs[bk * 128 + bn + 5] = b1.y;
                    Bs[bk * 128 + bn + 6] = b1.z; Bs[bk * 128 + bn + 7] = b1.w;
                } else {
#pragma unroll
                    for (int q = 0; q < 8; q++)
                        Bs[bk * 128 + bn + q] = (n0h + bn + q < N) ? Wrow[q] : 0.f;
                }
            }
            __syncthreads();
#pragma unroll
            for (int k = 0; k < BK; k++) {
                float a[8], b[8];
                *(float4*)&a[0] = *(const float4*)&As[k * 128 + ty * 4];
                *(float4*)&a[4] = *(const float4*)&As[k * 128 + 64 + ty * 4];
                *(float4*)&b[0] = *(const float4*)&Bs[k * 128 + tx * 4];
                *(float4*)&b[4] = *(const float4*)&Bs[k * 128 + 64 + tx * 4];
#pragma unroll
                for (int i = 0; i < 8; i++)
#pragma unroll
                    for (int j = 0; j < 8; j++)
                        acc[i][j] = fmaf(a[i], b[j], acc[i][j]);
            }
            __syncthreads();
        }

#pragma unroll
        for (int i = 0; i < 8; i++) {
            int s = m0 + ((i < 4) ? (ty * 4 + i) : (64 + ty * 4 + i - 4));
            if (s >= seg1) continue;
            size_t outrow = (EPI == 2) ? (size_t)g_idx[s] : (size_t)s;
#pragma unroll
            for (int j = 0; j < 8; j++) {
                int n = n0h + ((j < 4) ? (tx * 4 + j) : (64 + tx * 4 + j - 4));
                if (n >= N) continue;
                float v = acc[i][j] + bp[n];
                if (EPI == 0)      v = fmaxf(v, 0.f);
                else if (EPI == 2) v = 1.f / (1.f + expf(-v));
                C[outrow * ldc + n] = v;
            }
        }
        __syncthreads();
    }
#endif
}

// reparameterization: enc (bufB, ld 256) -> mu/log_sigma in out, z -> bufA (ld 128)
__global__ void k_z(const float* __restrict__ eps, float* __restrict__ out) {
    int g = blockIdx.x * blockDim.x + threadIdx.x;
    if (g >= BB * LAT) return;
    int s = g >> 7;
    int j = g & 127;
    int orig = g_idx[s];
    float mu = g_bufB[(size_t)s * 256 + j];
    float ls = g_bufB[(size_t)s * 256 + 128 + j];
    size_t mu_off = (size_t)BB * IN_DIM;
    size_t ls_off = mu_off + (size_t)BB * LAT;
    out[mu_off + (size_t)orig * LAT + j] = mu;
    out[ls_off + (size_t)orig * LAT + j] = ls;
    g_bufA[(size_t)s * LAT + j] = mu + expf(ls) * eps[(size_t)orig * LAT + j];
}

extern "C" void kernel_launch(void* const* d_in, const int* in_sizes, int n_in,
                              void* d_out, int out_size) {
    const float* x    = (const float*)d_in[0];
    const int*   task = (const int*)  d_in[1];
    const float* eps  = (const float*)d_in[2];
    const float* eW1  = (const float*)d_in[3];
    const float* eb1  = (const float*)d_in[4];
    const float* eW2  = (const float*)d_in[5];
    const float* eb2  = (const float*)d_in[6];
    const float* eW3  = (const float*)d_in[7];
    const float* eb3  = (const float*)d_in[8];
    const float* eW4  = (const float*)d_in[9];
    const float* eb4  = (const float*)d_in[10];
    const float* dWs1 = (const float*)d_in[11];
    const float* dbs1 = (const float*)d_in[12];
    const float* dWs2 = (const float*)d_in[13];
    const float* dbs2 = (const float*)d_in[14];
    const float* dWh1 = (const float*)d_in[15];
    const float* dbh1 = (const float*)d_in[16];
    const float* dWh2 = (const float*)d_in[17];
    const float* dbh2 = (const float*)d_in[18];
    float* out = (float*)d_out;

    float *bufA, *bufB;
    cudaGetSymbolAddress((void**)&bufA, g_bufA);
    cudaGetSymbolAddress((void**)&bufB, g_bufB);

    // encoder (3xTF32 split) instances
    cudaFuncSetAttribute(tgemm<true,  true,  0, true>,  cudaFuncAttributeMaxDynamicSharedMemorySize, SMEM_TOT_S);
    cudaFuncSetAttribute(tgemm<false, true,  0, true>,  cudaFuncAttributeMaxDynamicSharedMemorySize, SMEM_TOT_S);
    cudaFuncSetAttribute(tgemm<false, true,  1, true>,  cudaFuncAttributeMaxDynamicSharedMemorySize, SMEM_TOT_S);
    // decoder (plain TF32) instances
    cudaFuncSetAttribute(tgemm<false, false, 0, false>, cudaFuncAttributeMaxDynamicSharedMemorySize, SMEM_TOT_P);
    cudaFuncSetAttribute(tgemm<false, true,  0, false>, cudaFuncAttributeMaxDynamicSharedMemorySize, SMEM_TOT_P);
    cudaFuncSetAttribute(tgemm<false, true,  2, false>, cudaFuncAttributeMaxDynamicSharedMemorySize, SMEM_TOT_P);

    // group samples by task
    k_zero<<<1, 32>>>();
    k_count<<<(BB + 255) / 256, 256>>>(task);
    k_scan<<<1, 32>>>();
    k_fill<<<(BB + 255) / 256, 256>>>(task);

    // encoder (per-task segments, activations kept in sorted order) — 3xTF32
    tgemm<true,  true, 0, true><<<dim3(4, 64, NT), 256, SMEM_TOT_S>>>(x,    IN_DIM, eW1, IN_DIM, HID,   eb1, bufA, HID);
    tgemm<false, true, 0, true><<<dim3(4, 64, NT), 256, SMEM_TOT_S>>>(bufA, HID,    eW2, HID,    HID,   eb2, bufB, HID);
    tgemm<false, true, 0, true><<<dim3(4, 64, NT), 256, SMEM_TOT_S>>>(bufB, HID,    eW3, HID,    HID,   eb3, bufA, HID);
    tgemm<false, true, 1, true><<<dim3(1, 64, NT), 256, SMEM_TOT_S>>>(bufA, HID,    eW4, HID,    2*LAT, eb4, bufB, 2*LAT);

    // reparameterize: mu/log_sigma -> d_out, z -> bufA
    k_z<<<(BB * LAT + 255) / 256, 256>>>(eps, out);

    // decoder — plain TF32
    tgemm<false, false, 0, false><<<dim3(4, 64, 1),  256, SMEM_TOT_P>>>(bufA, LAT, dWs1, LAT, HID,    dbs1, bufB, HID);
    tgemm<false, false, 0, false><<<dim3(4, 64, 1),  256, SMEM_TOT_P>>>(bufB, HID, dWs2, HID, HID,    dbs2, bufA, HID);
    tgemm<false, true,  0, false><<<dim3(4, 64, NT), 256, SMEM_TOT_P>>>(bufA, HID, dWh1, HID, HID,    dbh1, bufB, HID);
    tgemm<false, true,  2, false><<<dim3(4, 64, NT), 256, SMEM_TOT_P>>>(bufB, HID, dWh2, HID, IN_DIM, dbh2, out, IN_DIM);
}

// round 10
// speedup vs baseline: 3.2477x; 1.3279x over previous
#include <cuda_runtime.h>
#include <math.h>
#include <cstdint>

#define BB      8192
#define IN_DIM  784
#define HID     1024
#define LAT     128
#define NT      10

// tcgen05 only exists on arch-specific targets (sm_103a). The harness also
// compiles a generic compute_103 pass, so guard the tensor path and provide a
// correct fp32 SIMT fallback in the other branch.
#if defined(__CUDA_ARCH__) && (__CUDA_ARCH__ == 1030) && \
    (defined(__CUDA_ARCH_FEAT_SM103_ALL) || \
     (defined(__CUDA_ARCH_SPECIFIC__) && (__CUDA_ARCH_SPECIFIC__ >= 1030)))
#define HAS_TC 1
#else
#define HAS_TC 0
#endif

// ---- scratch (static device globals; no allocation) ----
__device__ float g_bufA[BB * HID];
__device__ float g_bufB[BB * HID];
__device__ int   g_idx[BB];
__device__ int   g_off[NT + 1];
__device__ int   g_cnt[NT];
__device__ int   g_fill[NT];

// ---- task grouping ----
__global__ void k_zero() {
    int i = threadIdx.x;
    if (i < NT) { g_cnt[i] = 0; g_fill[i] = 0; }
}
__global__ void k_count(const int* __restrict__ task) {
    int i = blockIdx.x * blockDim.x + threadIdx.x;
    if (i < BB) atomicAdd(&g_cnt[task[i]], 1);
}
__global__ void k_scan() {
    if (threadIdx.x == 0) {
        int s = 0;
        for (int t = 0; t < NT; t++) { g_off[t] = s; s += g_cnt[t]; }
        g_off[NT] = s;
    }
}
__global__ void k_fill(const int* __restrict__ task) {
    int i = blockIdx.x * blockDim.x + threadIdx.x;
    if (i < BB) {
        int t = task[i];
        int p = atomicAdd(&g_fill[t], 1);
        g_idx[g_off[t] + p] = i;
    }
}

// ---------- tcgen05 helpers (arch-specific branch only) ----------
#if HAS_TC
__device__ __forceinline__ uint32_t smem_u32(const void* p) {
    uint32_t a;
    asm("{ .reg .u64 t; cvta.to.shared.u64 t, %1; cvt.u32.u64 %0, t; }" : "=r"(a) : "l"(p));
    return a;
}
__device__ __forceinline__ uint32_t elect1() {
    uint32_t r;
    asm volatile("{ .reg .pred p; elect.sync _|p, 0xFFFFFFFF; selp.b32 %0, 1, 0, p; }" : "=r"(r));
    return r;
}
__device__ __forceinline__ void mbar_init(uint32_t mbar, uint32_t cnt) {
    asm volatile("mbarrier.init.shared.b64 [%0], %1;" :: "r"(mbar), "r"(cnt) : "memory");
}
__device__ __forceinline__ void mbar_wait(uint32_t mbar, uint32_t parity) {
    asm volatile(
        "{\n\t.reg .pred P1;\n\t"
        "WAIT_%=:\n\t"
        "mbarrier.try_wait.parity.acquire.cta.shared::cta.b64 P1, [%0], %1, 0x989680;\n\t"
        "@P1 bra.uni DONE_%=;\n\t"
        "bra.uni WAIT_%=;\n\t"
        "DONE_%=:\n\t}"
        :: "r"(mbar), "r"(parity) : "memory");
}
__device__ __forceinline__ void mma_tf32(uint32_t d, uint64_t ad, uint64_t bd,
                                         uint32_t idesc, uint32_t en) {
    asm volatile(
        "{\n\t.reg .pred p;\n\t"
        "setp.ne.u32 p, %4, 0;\n\t"
        "tcgen05.mma.cta_group::1.kind::tf32 [%0], %1, %2, %3, {%5, %5, %5, %5}, p;\n\t}"
        :: "r"(d), "l"(ad), "l"(bd), "r"(idesc), "r"(en), "r"(0u) : "memory");
}
__device__ __forceinline__ void tc_commit(uint32_t mbar) {
    asm volatile("tcgen05.commit.cta_group::1.mbarrier::arrive::one.shared::cluster.b64 [%0];"
                 :: "r"(mbar) : "memory");
}
__device__ __forceinline__ float tf32_hi(float v) {
    uint32_t b;
    asm("cvt.rna.tf32.f32 %0, %1;" : "=r"(b) : "f"(v));
    return __uint_as_float(b);
}

#define TC_LD32(r, addr) \
    asm volatile( \
        "tcgen05.ld.sync.aligned.32x32b.x32.b32 " \
        "{%0, %1, %2, %3, %4, %5, %6, %7, " \
        " %8, %9, %10, %11, %12, %13, %14, %15, " \
        " %16, %17, %18, %19, %20, %21, %22, %23, " \
        " %24, %25, %26, %27, %28, %29, %30, %31}, [%32];" \
        : "=r"((r)[0]),  "=r"((r)[1]),  "=r"((r)[2]),  "=r"((r)[3]), \
          "=r"((r)[4]),  "=r"((r)[5]),  "=r"((r)[6]),  "=r"((r)[7]), \
          "=r"((r)[8]),  "=r"((r)[9]),  "=r"((r)[10]), "=r"((r)[11]), \
          "=r"((r)[12]), "=r"((r)[13]), "=r"((r)[14]), "=r"((r)[15]), \
          "=r"((r)[16]), "=r"((r)[17]), "=r"((r)[18]), "=r"((r)[19]), \
          "=r"((r)[20]), "=r"((r)[21]), "=r"((r)[22]), "=r"((r)[23]), \
          "=r"((r)[24]), "=r"((r)[25]), "=r"((r)[26]), "=r"((r)[27]), \
          "=r"((r)[28]), "=r"((r)[29]), "=r"((r)[30]), "=r"((r)[31]) \
        : "r"(addr))

// SW128 K-major descriptor: layout=2, version=1, SBO=64 (1024B group), LBO=1
static constexpr uint64_t DESC_BASE =
    (2ull << 61) | (1ull << 46) | (64ull << 32) | (1ull << 16);
__device__ __forceinline__ uint64_t mkdesc(uint32_t a) {
    return DESC_BASE | ((uint64_t)(a >> 4) & 0x3FFF);
}
#endif  // HAS_TC

#define SWZ(o) ((o) ^ (((o) >> 3) & 0x70))

// ---------- grouped GEMM: 128 x 256 tile per CTA ----------
#define NTILE 256
#define KC    32
#define SMEM_TMEM 0
#define SMEM_MB   16
#define SA_OFF    1024
// plain stage: A 16K @ +0, B 32K @ +16K  -> 48K/stage
// split stage: Ahi 16K, Alo 16K, Bhi 32K, Blo 32K -> 96K/stage
#define STAGE_P   49152
#define STAGE_S   98304
#define SMEM_TOT_P (SA_OFF + 2 * STAGE_P)   //  99328
#define SMEM_TOT_S (SA_OFF + 2 * STAGE_S)   // 197632
// epilogue staging tile: 128 rows x 132-float pitch = 67584 B (fits in stage area)
#define EPI_PITCH 132

// idesc: dtype f32(1)<<4 | atype tf32(2)<<7 | btype tf32(2)<<10 | (N/8)<<17 | (M/16)<<24
static constexpr uint32_t IDESC =
    (1u << 4) | (2u << 7) | (2u << 10) | ((NTILE / 8) << 17) | ((128 / 16) << 24);

// EPI: 0 bias+relu, 1 bias only, 2 bias+sigmoid+row-scatter via g_idx
// SPLIT: 3xTF32 emulated-fp32 (encoder layers feeding mu/log_sigma)
template <bool GATHER, bool PERTASK, int EPI, bool SPLIT>
__global__ __launch_bounds__(256, SPLIT ? 1 : 2) void tgemm(
    const float* __restrict__ A, int lda,
    const float* __restrict__ W, int K, int N,
    const float* __restrict__ bias,
    float* __restrict__ C, int ldc)
{
    extern __shared__ __align__(1024) char smem[];

    int t    = PERTASK ? blockIdx.z : 0;
    int seg0 = PERTASK ? g_off[t]     : 0;
    int seg1 = PERTASK ? g_off[t + 1] : BB;
    int m0   = seg0 + blockIdx.y * 128;
    if (m0 >= seg1) return;
    int n0 = blockIdx.x * NTILE;

    const float* Wp = W    + (PERTASK ? (size_t)t * K * N : 0);
    const float* bp = bias + (PERTASK ? (size_t)t * N     : 0);

    int tid = threadIdx.x;

#if HAS_TC
    // ================= tcgen05 tf32 path =================
    const int STAGE_B = SPLIT ? STAGE_S : STAGE_P;
    uint32_t sb = smem_u32(smem);
    int wid = tid >> 5;
    int lid = tid & 31;

    if (wid == 0) {
        asm volatile("tcgen05.alloc.cta_group::1.sync.aligned.shared::cta.b32 [%0], %1;"
                     :: "r"(sb + SMEM_TMEM), "r"(256u) : "memory");
        asm volatile("tcgen05.relinquish_alloc_permit.cta_group::1.sync.aligned;");
    }
    if (tid == 0) { mbar_init(sb + SMEM_MB, 1); mbar_init(sb + SMEM_MB + 8, 1); }
    __syncthreads();
    uint32_t tmem;
    asm volatile("ld.shared.b32 %0, [%1];" : "=r"(tmem) : "r"(sb + SMEM_TMEM));

    int nch = (K + KC - 1) / KC;
    int ph[2] = {0, 0};

    // A fill mapping (conflict-free: lanes vary k at fixed m) — pointers hoisted
    int a_k4 = (tid & 7) * 4;
    int a_mb = tid >> 3;
    const float* Ar[4];
#pragma unroll
    for (int p = 0; p < 4; p++) {
        int gs = m0 + p * 32 + a_mb;
        int src = (gs < seg1) ? (GATHER ? g_idx[gs] : gs)
                              : (GATHER ? g_idx[seg0] : seg0);
        Ar[p] = A + (size_t)src * lda + a_k4;
    }
    // B fill: thread owns ONE column n = n0 + tid, walks k (conflict-free STS.128)
    int b_n = tid;
    bool b_nv = (n0 + b_n < N);
    const float* Wcol = Wp + n0 + b_n;

    for (int c = 0; c < nch; c++) {
        int s = c & 1;
        if (c >= 2) { mbar_wait(sb + SMEM_MB + 8 * s, ph[s]); ph[s] ^= 1; }
        int k0 = c * KC;
        char* sAh = smem + SA_OFF + s * STAGE_B;
        char* sAl = sAh + 16384;                     // SPLIT only
        char* sBh = smem + SA_OFF + (SPLIT ? 32768 : 16384) + s * STAGE_B;
        char* sBl = sBh + 32768;                     // SPLIT only

        // A tile [m=128][k=32] floats, SW128-swizzled, K-major
#pragma unroll
        for (int p = 0; p < 4; p++) {
            int m = p * 32 + a_mb;
            float4 v = make_float4(0.f, 0.f, 0.f, 0.f);
            if (k0 + a_k4 < K)   // K % 4 == 0 for all layers
                v = *(const float4*)(Ar[p] + k0);
            uint32_t off = SWZ((uint32_t)(m * KC + a_k4) * 4);
            if (SPLIT) {
                float4 h, l;
                h.x = tf32_hi(v.x); l.x = v.x - h.x;
                h.y = tf32_hi(v.y); l.y = v.y - h.y;
                h.z = tf32_hi(v.z); l.z = v.z - h.z;
                h.w = tf32_hi(v.w); l.w = v.w - h.w;
                *(float4*)(sAh + off) = h;
                *(float4*)(sAl + off) = l;
            } else {
                *(float4*)(sAh + off) = v;
            }
        }
        // B tile [n=256][k=32] floats from W[k][n] — column-per-thread, STS.128
#pragma unroll
        for (int kg = 0; kg < 8; kg++) {
            float v0 = 0.f, v1 = 0.f, v2 = 0.f, v3 = 0.f;
            if (b_nv) {
                int k = k0 + kg * 4;
                if (k < K) {
                    v0 = Wcol[(size_t)(k + 0) * N];
                    v1 = Wcol[(size_t)(k + 1) * N];
                    v2 = Wcol[(size_t)(k + 2) * N];
                    v3 = Wcol[(size_t)(k + 3) * N];
                }
            }
            uint32_t off = SWZ((uint32_t)(b_n * KC + kg * 4) * 4);
            if (SPLIT) {
                float4 h, l;
                h.x = tf32_hi(v0); l.x = v0 - h.x;
                h.y = tf32_hi(v1); l.y = v1 - h.y;
                h.z = tf32_hi(v2); l.z = v2 - h.z;
                h.w = tf32_hi(v3); l.w = v3 - h.w;
                *(float4*)(sBh + off) = h;
                *(float4*)(sBl + off) = l;
            } else {
                *(float4*)(sBh + off) = make_float4(v0, v1, v2, v3);
            }
        }
        asm volatile("fence.proxy.async.shared::cta;" ::: "memory");
        __syncthreads();

        if (wid == 0) {
            if (elect1()) {
                uint64_t adh = mkdesc(smem_u32(sAh));
                uint64_t bdh = mkdesc(smem_u32(sBh));
                if (SPLIT) {
                    uint64_t adl = mkdesc(smem_u32(sAl));
                    uint64_t bdl = mkdesc(smem_u32(sBl));
#pragma unroll
                    for (int j = 0; j < 4; j++) {
                        // small terms first, hi*hi last
                        mma_tf32(tmem, adl + j * 2, bdh + j * 2, IDESC,
                                 (c > 0 || j > 0) ? 1u : 0u);
                        mma_tf32(tmem, adh + j * 2, bdl + j * 2, IDESC, 1u);
                        mma_tf32(tmem, adh + j * 2, bdh + j * 2, IDESC, 1u);
                    }
                } else {
#pragma unroll
                    for (int j = 0; j < 4; j++)
                        mma_tf32(tmem, adh + j * 2, bdh + j * 2, IDESC,
                                 (c > 0 || j > 0) ? 1u : 0u);
                }
                tc_commit(sb + SMEM_MB + 8 * s);
            }
        }
    }

    // final commit covers all MMAs -> stage buffers are free for reuse
    int sl = (nch - 1) & 1;
    mbar_wait(sb + SMEM_MB + 8 * sl, ph[sl]);
    asm volatile("tcgen05.fence::after_thread_sync;" ::: "memory");
    __syncthreads();

    // ---- staged transpose epilogue (coalesced STG) ----
    // Phase 1: LDTM -> SMEM tile [128][EPI_PITCH]. Warp w: rows (w&3)*32+lid
    // (its TMEM subpartition), 64-col slice cq=(w>>2) of each 128-col half.
    // Phase 2: warp w owns rows w*16..w*16+15; lanes store 4 consecutive cols
    // -> 512B contiguous STG.128 per row (row-scatter via g_idx stays coalesced
    // within the row).
    float* stg = (float*)(smem + SA_OFF);
    int rw = wid & 3;
    int cq = wid >> 2;
    for (int half = 0; half < 2; half++) {
#pragma unroll
        for (int i = 0; i < 2; i++) {
            uint32_t r[32];
            TC_LD32(r, tmem + half * 128 + cq * 64 + i * 32);
            asm volatile("tcgen05.wait::ld.sync.aligned;" ::: "memory");
            float* dst = stg + (rw * 32 + lid) * EPI_PITCH + cq * 64 + i * 32;
#pragma unroll
            for (int q = 0; q < 8; q++)
                *(float4*)(dst + q * 4) = make_float4(
                    __uint_as_float(r[q * 4 + 0]), __uint_as_float(r[q * 4 + 1]),
                    __uint_as_float(r[q * 4 + 2]), __uint_as_float(r[q * 4 + 3]));
        }
        __syncthreads();

        int nb = n0 + half * 128 + lid * 4;
        bool nv = nb < N;   // N % 4 == 0 for all layers
        float4 bz = make_float4(0.f, 0.f, 0.f, 0.f);
        if (nv) bz = *(const float4*)(bp + nb);
#pragma unroll
        for (int rr = 0; rr < 16; rr++) {
            int r = wid * 16 + rr;
            int grow = m0 + r;
            if (grow < seg1 && nv) {
                float4 v = *(float4*)(stg + r * EPI_PITCH + lid * 4);
                v.x += bz.x; v.y += bz.y; v.z += bz.z; v.w += bz.w;
                if (EPI == 0) {
                    v.x = fmaxf(v.x, 0.f); v.y = fmaxf(v.y, 0.f);
                    v.z = fmaxf(v.z, 0.f); v.w = fmaxf(v.w, 0.f);
                } else if (EPI == 2) {
                    v.x = 1.f / (1.f + expf(-v.x));
                    v.y = 1.f / (1.f + expf(-v.y));
                    v.z = 1.f / (1.f + expf(-v.z));
                    v.w = 1.f / (1.f + expf(-v.w));
                }
                size_t orow = (EPI == 2) ? (size_t)g_idx[grow] : (size_t)grow;
                *(float4*)(C + orow * ldc + nb) = v;
            }
        }
        __syncthreads();
    }

    asm volatile("tcgen05.fence::before_thread_sync;" ::: "memory");
    __syncthreads();
    if (wid == 0)
        asm volatile("tcgen05.dealloc.cta_group::1.sync.aligned.b32 %0, %1;"
                     :: "r"(tmem), "r"(256u));

#else
    // ================= fp32 SIMT fallback (verified round-2 code) =================
    const int BK = 16;
    float* As = (float*)smem;                   // [BK][128]
    float* Bs = (float*)(smem + BK * 128 * 4);  // [BK][128]

    int ar = tid & 127;
    int ak = (tid >> 7) * 8;
    int as_ = m0 + ar;
    bool avalid = (as_ < seg1);
    const float* Arow = nullptr;
    if (avalid) {
        int src = GATHER ? g_idx[as_] : as_;
        Arow = A + (size_t)src * lda;
    }
    int bk = tid >> 4;
    int bn = (tid & 15) * 8;
    int ty = tid >> 4;
    int tx = tid & 15;

    for (int half = 0; half < 2; half++) {
        int n0h = n0 + half * 128;
        if (n0h >= N) break;

        float acc[8][8];
#pragma unroll
        for (int i = 0; i < 8; i++)
#pragma unroll
            for (int j = 0; j < 8; j++) acc[i][j] = 0.f;

        for (int k0 = 0; k0 < K; k0 += BK) {
            if (avalid) {
                float4 a0 = *(const float4*)(Arow + k0 + ak);
                float4 a1 = *(const float4*)(Arow + k0 + ak + 4);
                As[(ak + 0) * 128 + ar] = a0.x; As[(ak + 1) * 128 + ar] = a0.y;
                As[(ak + 2) * 128 + ar] = a0.z; As[(ak + 3) * 128 + ar] = a0.w;
                As[(ak + 4) * 128 + ar] = a1.x; As[(ak + 5) * 128 + ar] = a1.y;
                As[(ak + 6) * 128 + ar] = a1.z; As[(ak + 7) * 128 + ar] = a1.w;
            } else {
#pragma unroll
                for (int q = 0; q < 8; q++) As[(ak + q) * 128 + ar] = 0.f;
            }
            {
                const float* Wrow = Wp + (size_t)(k0 + bk) * N + n0h + bn;
                if (n0h + bn + 7 < N) {
                    float4 b0 = *(const float4*)(Wrow);
                    float4 b1 = *(const float4*)(Wrow + 4);
                    Bs[bk * 128 + bn + 0] = b0.x; Bs[bk * 128 + bn + 1] = b0.y;
                    Bs[bk * 128 + bn + 2] = b0.z; Bs[bk * 128 + bn + 3] = b0.w;
                    Bs[bk * 128 + bn + 4] = b1.x; Bs[bk * 128 + bn + 5] = b1.y;
                    Bs[bk * 128 + bn + 6] = b1.z; Bs[bk * 128 + bn + 7] = b1.w;
                } else {
#pragma unroll
                    for (int q = 0; q < 8; q++)
                        Bs[bk * 128 + bn + q] = (n0h + bn + q < N) ? Wrow[q] : 0.f;
                }
            }
            __syncthreads();
#pragma unroll
            for (int k = 0; k < BK; k++) {
                float a[8], b[8];
                *(float4*)&a[0] = *(const float4*)&As[k * 128 + ty * 4];
                *(float4*)&a[4] = *(const float4*)&As[k * 128 + 64 + ty * 4];
                *(float4*)&b[0] = *(const float4*)&Bs[k * 128 + tx * 4];
                *(float4*)&b[4] = *(const float4*)&Bs[k * 128 + 64 + tx * 4];
#pragma unroll
                for (int i = 0; i < 8; i++)
#pragma unroll
                    for (int j = 0; j < 8; j++)
                        acc[i][j] = fmaf(a[i], b[j], acc[i][j]);
            }
            __syncthreads();
        }

#pragma unroll
        for (int i = 0; i < 8; i++) {
            int s = m0 + ((i < 4) ? (ty * 4 + i) : (64 + ty * 4 + i - 4));
            if (s >= seg1) continue;
            size_t outrow = (EPI == 2) ? (size_t)g_idx[s] : (size_t)s;
#pragma unroll
            for (int j = 0; j < 8; j++) {
                int n = n0h + ((j < 4) ? (tx * 4 + j) : (64 + tx * 4 + j - 4));
                if (n >= N) continue;
                float v = acc[i][j] + bp[n];
                if (EPI == 0)      v = fmaxf(v, 0.f);
                else if (EPI == 2) v = 1.f / (1.f + expf(-v));
                C[outrow * ldc + n] = v;
            }
        }
        __syncthreads();
    }
#endif
}

// reparameterization: enc (bufB, ld 256) -> mu/log_sigma in out, z -> bufA (ld 128)
__global__ void k_z(const float* __restrict__ eps, float* __restrict__ out) {
    int g = blockIdx.x * blockDim.x + threadIdx.x;
    if (g >= BB * LAT) return;
    int s = g >> 7;
    int j = g & 127;
    int orig = g_idx[s];
    float mu = g_bufB[(size_t)s * 256 + j];
    float ls = g_bufB[(size_t)s * 256 + 128 + j];
    size_t mu_off = (size_t)BB * IN_DIM;
    size_t ls_off = mu_off + (size_t)BB * LAT;
    out[mu_off + (size_t)orig * LAT + j] = mu;
    out[ls_off + (size_t)orig * LAT + j] = ls;
    g_bufA[(size_t)s * LAT + j] = mu + expf(ls) * eps[(size_t)orig * LAT + j];
}

extern "C" void kernel_launch(void* const* d_in, const int* in_sizes, int n_in,
                              void* d_out, int out_size) {
    const float* x    = (const float*)d_in[0];
    const int*   task = (const int*)  d_in[1];
    const float* eps  = (const float*)d_in[2];
    const float* eW1  = (const float*)d_in[3];
    const float* eb1  = (const float*)d_in[4];
    const float* eW2  = (const float*)d_in[5];
    const float* eb2  = (const float*)d_in[6];
    const float* eW3  = (const float*)d_in[7];
    const float* eb3  = (const float*)d_in[8];
    const float* eW4  = (const float*)d_in[9];
    const float* eb4  = (const float*)d_in[10];
    const float* dWs1 = (const float*)d_in[11];
    const float* dbs1 = (const float*)d_in[12];
    const float* dWs2 = (const float*)d_in[13];
    const float* dbs2 = (const float*)d_in[14];
    const float* dWh1 = (const float*)d_in[15];
    const float* dbh1 = (const float*)d_in[16];
    const float* dWh2 = (const float*)d_in[17];
    const float* dbh2 = (const float*)d_in[18];
    float* out = (float*)d_out;

    float *bufA, *bufB;
    cudaGetSymbolAddress((void**)&bufA, g_bufA);
    cudaGetSymbolAddress((void**)&bufB, g_bufB);

    // encoder (3xTF32 split) instances
    cudaFuncSetAttribute(tgemm<true,  true,  0, true>,  cudaFuncAttributeMaxDynamicSharedMemorySize, SMEM_TOT_S);
    cudaFuncSetAttribute(tgemm<false, true,  0, true>,  cudaFuncAttributeMaxDynamicSharedMemorySize, SMEM_TOT_S);
    cudaFuncSetAttribute(tgemm<false, true,  1, true>,  cudaFuncAttributeMaxDynamicSharedMemorySize, SMEM_TOT_S);
    // decoder (plain TF32) instances
    cudaFuncSetAttribute(tgemm<false, false, 0, false>, cudaFuncAttributeMaxDynamicSharedMemorySize, SMEM_TOT_P);
    cudaFuncSetAttribute(tgemm<false, true,  0, false>, cudaFuncAttributeMaxDynamicSharedMemorySize, SMEM_TOT_P);
    cudaFuncSetAttribute(tgemm<false, true,  2, false>, cudaFuncAttributeMaxDynamicSharedMemorySize, SMEM_TOT_P);

    // group samples by task
    k_zero<<<1, 32>>>();
    k_count<<<(BB + 255) / 256, 256>>>(task);
    k_scan<<<1, 32>>>();
    k_fill<<<(BB + 255) / 256, 256>>>(task);

    // encoder (per-task segments, activations kept in sorted order) — 3xTF32
    tgemm<true,  true, 0, true><<<dim3(4, 64, NT), 256, SMEM_TOT_S>>>(x,    IN_DIM, eW1, IN_DIM, HID,   eb1, bufA, HID);
    tgemm<false, true, 0, true><<<dim3(4, 64, NT), 256, SMEM_TOT_S>>>(bufA, HID,    eW2, HID,    HID,   eb2, bufB, HID);
    tgemm<false, true, 0, true><<<dim3(4, 64, NT), 256, SMEM_TOT_S>>>(bufB, HID,    eW3, HID,    HID,   eb3, bufA, HID);
    tgemm<false, true, 1, true><<<dim3(1, 64, NT), 256, SMEM_TOT_S>>>(bufA, HID,    eW4, HID,    2*LAT, eb4, bufB, 2*LAT);

    // reparameterize: mu/log_sigma -> d_out, z -> bufA
    k_z<<<(BB * LAT + 255) / 256, 256>>>(eps, out);

    // decoder — plain TF32
    tgemm<false, false, 0, false><<<dim3(4, 64, 1),  256, SMEM_TOT_P>>>(bufA, LAT, dWs1, LAT, HID,    dbs1, bufB, HID);
    tgemm<false, false, 0, false><<<dim3(4, 64, 1),  256, SMEM_TOT_P>>>(bufB, HID, dWs2, HID, HID,    dbs2, bufA, HID);
    tgemm<false, true,  0, false><<<dim3(4, 64, NT), 256, SMEM_TOT_P>>>(bufA, HID, dWh1, HID, HID,    dbh1, bufB, HID);
    tgemm<false, true,  2, false><<<dim3(4, 64, NT), 256, SMEM_TOT_P>>>(bufB, HID, dWh2, HID, IN_DIM, dbh2, out, IN_DIM);
}

// round 11
// speedup vs baseline: 4.2628x; 1.3126x over previous
#include <cuda_runtime.h>
#include <cuda_bf16.h>
#include <math.h>
#include <cstdint>

#define BB      8192
#define IN_DIM  784
#define HID     1024
#define LAT     128
#define NT      10

// tcgen05 only exists on arch-specific targets (sm_103a). The harness also
// compiles a generic compute_103 pass, so guard the tensor path and provide a
// correct fp32 SIMT fallback in the other branch.
#if defined(__CUDA_ARCH__) && (__CUDA_ARCH__ == 1030) && \
    (defined(__CUDA_ARCH_FEAT_SM103_ALL) || \
     (defined(__CUDA_ARCH_SPECIFIC__) && (__CUDA_ARCH_SPECIFIC__ >= 1030)))
#define HAS_TC 1
#else
#define HAS_TC 0
#endif

// ---- scratch (static device globals; no allocation) ----
__device__ float g_bufA[BB * HID];
__device__ float g_bufB[BB * HID];
__device__ int   g_idx[BB];
__device__ int   g_off[NT + 1];
__device__ int   g_cnt[NT];
__device__ int   g_fill[NT];

// ---- task grouping ----
__global__ void k_zero() {
    int i = threadIdx.x;
    if (i < NT) { g_cnt[i] = 0; g_fill[i] = 0; }
}
__global__ void k_count(const int* __restrict__ task) {
    int i = blockIdx.x * blockDim.x + threadIdx.x;
    if (i < BB) atomicAdd(&g_cnt[task[i]], 1);
}
__global__ void k_scan() {
    if (threadIdx.x == 0) {
        int s = 0;
        for (int t = 0; t < NT; t++) { g_off[t] = s; s += g_cnt[t]; }
        g_off[NT] = s;
    }
}
__global__ void k_fill(const int* __restrict__ task) {
    int i = blockIdx.x * blockDim.x + threadIdx.x;
    if (i < BB) {
        int t = task[i];
        int p = atomicAdd(&g_fill[t], 1);
        g_idx[g_off[t] + p] = i;
    }
}

// ---------- tcgen05 helpers (arch-specific branch only) ----------
#if HAS_TC
__device__ __forceinline__ uint32_t smem_u32(const void* p) {
    uint32_t a;
    asm("{ .reg .u64 t; cvta.to.shared.u64 t, %1; cvt.u32.u64 %0, t; }" : "=r"(a) : "l"(p));
    return a;
}
__device__ __forceinline__ uint32_t elect1() {
    uint32_t r;
    asm volatile("{ .reg .pred p; elect.sync _|p, 0xFFFFFFFF; selp.b32 %0, 1, 0, p; }" : "=r"(r));
    return r;
}
__device__ __forceinline__ void mbar_init(uint32_t mbar, uint32_t cnt) {
    asm volatile("mbarrier.init.shared.b64 [%0], %1;" :: "r"(mbar), "r"(cnt) : "memory");
}
__device__ __forceinline__ void mbar_wait(uint32_t mbar, uint32_t parity) {
    asm volatile(
        "{\n\t.reg .pred P1;\n\t"
        "WAIT_%=:\n\t"
        "mbarrier.try_wait.parity.acquire.cta.shared::cta.b64 P1, [%0], %1, 0x989680;\n\t"
        "@P1 bra.uni DONE_%=;\n\t"
        "bra.uni WAIT_%=;\n\t"
        "DONE_%=:\n\t}"
        :: "r"(mbar), "r"(parity) : "memory");
}
__device__ __forceinline__ void mma_tf32(uint32_t d, uint64_t ad, uint64_t bd,
                                         uint32_t idesc, uint32_t en) {
    asm volatile(
        "{\n\t.reg .pred p;\n\t"
        "setp.ne.u32 p, %4, 0;\n\t"
        "tcgen05.mma.cta_group::1.kind::tf32 [%0], %1, %2, %3, {%5, %5, %5, %5}, p;\n\t}"
        :: "r"(d), "l"(ad), "l"(bd), "r"(idesc), "r"(en), "r"(0u) : "memory");
}
__device__ __forceinline__ void mma_f16(uint32_t d, uint64_t ad, uint64_t bd,
                                        uint32_t idesc, uint32_t en) {
    asm volatile(
        "{\n\t.reg .pred p;\n\t"
        "setp.ne.u32 p, %4, 0;\n\t"
        "tcgen05.mma.cta_group::1.kind::f16 [%0], %1, %2, %3, {%5, %5, %5, %5}, p;\n\t}"
        :: "r"(d), "l"(ad), "l"(bd), "r"(idesc), "r"(en), "r"(0u) : "memory");
}
__device__ __forceinline__ void tc_commit(uint32_t mbar) {
    asm volatile("tcgen05.commit.cta_group::1.mbarrier::arrive::one.shared::cluster.b64 [%0];"
                 :: "r"(mbar) : "memory");
}
// pack (v0, v1) -> bf16x2 hi pair + residual lo pair (v0 at lower address)
__device__ __forceinline__ void bf16_split2(float v0, float v1,
                                            uint32_t& hp, uint32_t& lp) {
    asm("cvt.rn.bf16x2.f32 %0, %1, %2;" : "=r"(hp) : "f"(v1), "f"(v0));
    float h0 = __uint_as_float(hp << 16);
    float h1 = __uint_as_float(hp & 0xFFFF0000u);
    float l0 = v0 - h0, l1 = v1 - h1;
    asm("cvt.rn.bf16x2.f32 %0, %1, %2;" : "=r"(lp) : "f"(l1), "f"(l0));
}

#define TC_LD32(r, addr) \
    asm volatile( \
        "tcgen05.ld.sync.aligned.32x32b.x32.b32 " \
        "{%0, %1, %2, %3, %4, %5, %6, %7, " \
        " %8, %9, %10, %11, %12, %13, %14, %15, " \
        " %16, %17, %18, %19, %20, %21, %22, %23, " \
        " %24, %25, %26, %27, %28, %29, %30, %31}, [%32];" \
        : "=r"((r)[0]),  "=r"((r)[1]),  "=r"((r)[2]),  "=r"((r)[3]), \
          "=r"((r)[4]),  "=r"((r)[5]),  "=r"((r)[6]),  "=r"((r)[7]), \
          "=r"((r)[8]),  "=r"((r)[9]),  "=r"((r)[10]), "=r"((r)[11]), \
          "=r"((r)[12]), "=r"((r)[13]), "=r"((r)[14]), "=r"((r)[15]), \
          "=r"((r)[16]), "=r"((r)[17]), "=r"((r)[18]), "=r"((r)[19]), \
          "=r"((r)[20]), "=r"((r)[21]), "=r"((r)[22]), "=r"((r)[23]), \
          "=r"((r)[24]), "=r"((r)[25]), "=r"((r)[26]), "=r"((r)[27]), \
          "=r"((r)[28]), "=r"((r)[29]), "=r"((r)[30]), "=r"((r)[31]) \
        : "r"(addr))

// SW128 K-major descriptor: layout=2, version=1, SBO=64 (1024B group), LBO=1
static constexpr uint64_t DESC_BASE =
    (2ull << 61) | (1ull << 46) | (64ull << 32) | (1ull << 16);
__device__ __forceinline__ uint64_t mkdesc(uint32_t a) {
    return DESC_BASE | ((uint64_t)(a >> 4) & 0x3FFF);
}
#endif  // HAS_TC

#define SWZ(o) ((o) ^ (((o) >> 3) & 0x70))

// ---------- grouped GEMM: 128 x 256 tile per CTA ----------
#define NTILE 256
#define KC    32            // tf32 plain chunk (32 fp32 = 128B rows)
#define KCB   64            // bf16 split chunk (64 bf16 = 128B rows)
#define SMEM_TMEM 0
#define SMEM_MB   16
#define SA_OFF    1024
// plain(tf32) stage: A 16K, B 32K           -> 48K/stage
// split(bf16) stage: Ahi 16K, Alo 16K, Bhi 32K, Blo 32K -> 96K/stage
#define STAGE_P   49152
#define STAGE_S   98304
#define SMEM_TOT_P (SA_OFF + 2 * STAGE_P)   //  99328
#define SMEM_TOT_S (SA_OFF + 2 * STAGE_S)   // 197632
// epilogue staging tile: 128 rows x 132-float pitch = 67584 B (fits in stage area)
#define EPI_PITCH 132

// idesc: dtype f32(1)<<4 | atype<<7 | btype<<10 | (N/8)<<17 | (M/16)<<24
static constexpr uint32_t IDESC_TF32 =
    (1u << 4) | (2u << 7) | (2u << 10) | ((NTILE / 8) << 17) | ((128 / 16) << 24);
static constexpr uint32_t IDESC_BF16 =
    (1u << 4) | (1u << 7) | (1u << 10) | ((NTILE / 8) << 17) | ((128 / 16) << 24);

// EPI: 0 bias+relu, 1 bias only, 2 bias+sigmoid+row-scatter via g_idx
// SPLIT: bf16x3 emulated-fp32 (encoder layers feeding mu/log_sigma)
template <bool GATHER, bool PERTASK, int EPI, bool SPLIT>
__global__ __launch_bounds__(256, SPLIT ? 1 : 2) void tgemm(
    const float* __restrict__ A, int lda,
    const float* __restrict__ W, int K, int N,
    const float* __restrict__ bias,
    float* __restrict__ C, int ldc)
{
    extern __shared__ __align__(1024) char smem[];

    int t    = PERTASK ? blockIdx.z : 0;
    int seg0 = PERTASK ? g_off[t]     : 0;
    int seg1 = PERTASK ? g_off[t + 1] : BB;
    int m0   = seg0 + blockIdx.y * 128;
    if (m0 >= seg1) return;
    int n0 = blockIdx.x * NTILE;

    const float* Wp = W    + (PERTASK ? (size_t)t * K * N : 0);
    const float* bp = bias + (PERTASK ? (size_t)t * N     : 0);

    int tid = threadIdx.x;

#if HAS_TC
    // ================= tcgen05 path =================
    const int STAGE_B = SPLIT ? STAGE_S : STAGE_P;
    const int KCC     = SPLIT ? KCB : KC;      // k elements per chunk (both = 128B rows)
    uint32_t sb = smem_u32(smem);
    int wid = tid >> 5;
    int lid = tid & 31;

    if (wid == 0) {
        asm volatile("tcgen05.alloc.cta_group::1.sync.aligned.shared::cta.b32 [%0], %1;"
                     :: "r"(sb + SMEM_TMEM), "r"(256u) : "memory");
        asm volatile("tcgen05.relinquish_alloc_permit.cta_group::1.sync.aligned;");
    }
    if (tid == 0) { mbar_init(sb + SMEM_MB, 1); mbar_init(sb + SMEM_MB + 8, 1); }
    __syncthreads();
    uint32_t tmem;
    asm volatile("ld.shared.b32 %0, [%1];" : "=r"(tmem) : "r"(sb + SMEM_TMEM));

    int nch = (K + KCC - 1) / KCC;
    int ph[2] = {0, 0};

    // A fill mapping (conflict-free: lanes vary k at fixed m) — pointers hoisted.
    // split: thread covers 8 k (two float4); plain: 4 k (one float4)
    int a_ke = (tid & 7) * (SPLIT ? 8 : 4);
    int a_mb = tid >> 3;
    const float* Ar[4];
#pragma unroll
    for (int p = 0; p < 4; p++) {
        int gs = m0 + p * 32 + a_mb;
        int src = (gs < seg1) ? (GATHER ? g_idx[gs] : gs)
                              : (GATHER ? g_idx[seg0] : seg0);
        Ar[p] = A + (size_t)src * lda + a_ke;
    }
    // B fill: thread owns ONE column n = n0 + tid, walks k (conflict-free STS.128)
    int b_n = tid;
    bool b_nv = (n0 + b_n < N);
    const float* Wcol = Wp + n0 + b_n;

    for (int c = 0; c < nch; c++) {
        int s = c & 1;
        if (c >= 2) { mbar_wait(sb + SMEM_MB + 8 * s, ph[s]); ph[s] ^= 1; }
        int k0 = c * KCC;
        char* sAh = smem + SA_OFF + s * STAGE_B;
        char* sAl = sAh + 16384;                                   // SPLIT only
        char* sBh = smem + SA_OFF + (SPLIT ? 32768 : 16384) + s * STAGE_B;
        char* sBl = sBh + 32768;                                   // SPLIT only

        if (SPLIT) {
            // ---- bf16x3: A tile [m=128][k=64] bf16 hi/lo, 128B rows ----
#pragma unroll
            for (int p = 0; p < 4; p++) {
                int m = p * 32 + a_mb;
                float4 v0 = make_float4(0.f, 0.f, 0.f, 0.f);
                float4 v1 = make_float4(0.f, 0.f, 0.f, 0.f);
                if (k0 + a_ke < K)     v0 = *(const float4*)(Ar[p] + k0);       // K%4==0
                if (k0 + a_ke + 4 < K) v1 = *(const float4*)(Ar[p] + k0 + 4);
                uint32_t h[4], l[4];
                bf16_split2(v0.x, v0.y, h[0], l[0]);
                bf16_split2(v0.z, v0.w, h[1], l[1]);
                bf16_split2(v1.x, v1.y, h[2], l[2]);
                bf16_split2(v1.z, v1.w, h[3], l[3]);
                uint32_t off = SWZ((uint32_t)(m * 128 + a_ke * 2));
                *(uint4*)(sAh + off) = make_uint4(h[0], h[1], h[2], h[3]);
                *(uint4*)(sAl + off) = make_uint4(l[0], l[1], l[2], l[3]);
            }
            // ---- B tile [n=256][k=64] bf16 hi/lo from W[k][n] ----
#pragma unroll
            for (int kg = 0; kg < 8; kg++) {
                float v[8];
                bool kv = b_nv && (k0 + kg * 8 < K);   // K%8==0 for all layers
#pragma unroll
                for (int q = 0; q < 8; q++)
                    v[q] = kv ? Wcol[(size_t)(k0 + kg * 8 + q) * N] : 0.f;
                uint32_t h[4], l[4];
                bf16_split2(v[0], v[1], h[0], l[0]);
                bf16_split2(v[2], v[3], h[1], l[1]);
                bf16_split2(v[4], v[5], h[2], l[2]);
                bf16_split2(v[6], v[7], h[3], l[3]);
                uint32_t off = SWZ((uint32_t)(b_n * 128 + kg * 16));
                *(uint4*)(sBh + off) = make_uint4(h[0], h[1], h[2], h[3]);
                *(uint4*)(sBl + off) = make_uint4(l[0], l[1], l[2], l[3]);
            }
        } else {
            // ---- plain tf32: A tile [m=128][k=32] fp32 ----
#pragma unroll
            for (int p = 0; p < 4; p++) {
                int m = p * 32 + a_mb;
                float4 v = make_float4(0.f, 0.f, 0.f, 0.f);
                if (k0 + a_ke < K)
                    v = *(const float4*)(Ar[p] + k0);
                *(float4*)(sAh + SWZ((uint32_t)(m * KC + a_ke) * 4)) = v;
            }
            // ---- B tile [n=256][k=32] fp32 from W[k][n] ----
#pragma unroll
            for (int kg = 0; kg < 8; kg++) {
                float v0 = 0.f, v1 = 0.f, v2 = 0.f, v3 = 0.f;
                if (b_nv) {
                    int k = k0 + kg * 4;
                    if (k < K) {
                        v0 = Wcol[(size_t)(k + 0) * N];
                        v1 = Wcol[(size_t)(k + 1) * N];
                        v2 = Wcol[(size_t)(k + 2) * N];
                        v3 = Wcol[(size_t)(k + 3) * N];
                    }
                }
                *(float4*)(sBh + SWZ((uint32_t)(b_n * KC + kg * 4) * 4)) =
                    make_float4(v0, v1, v2, v3);
            }
        }
        __syncthreads();

        if (wid == 0) {
            // single-warp proxy fence: all STS are CTA-visible after the sync
            asm volatile("fence.proxy.async.shared::cta;" ::: "memory");
            if (elect1()) {
                uint64_t adh = mkdesc(smem_u32(sAh));
                uint64_t bdh = mkdesc(smem_u32(sBh));
                if (SPLIT) {
                    uint64_t adl = mkdesc(smem_u32(sAl));
                    uint64_t bdl = mkdesc(smem_u32(sBl));
#pragma unroll
                    for (int j = 0; j < 4; j++) {   // 16 bf16 k per step
                        mma_f16(tmem, adl + j * 2, bdh + j * 2, IDESC_BF16,
                                (c > 0 || j > 0) ? 1u : 0u);
                        mma_f16(tmem, adh + j * 2, bdl + j * 2, IDESC_BF16, 1u);
                        mma_f16(tmem, adh + j * 2, bdh + j * 2, IDESC_BF16, 1u);
                    }
                } else {
#pragma unroll
                    for (int j = 0; j < 4; j++)     // 8 tf32 k per step
                        mma_tf32(tmem, adh + j * 2, bdh + j * 2, IDESC_TF32,
                                 (c > 0 || j > 0) ? 1u : 0u);
                }
                tc_commit(sb + SMEM_MB + 8 * s);
            }
        }
    }

    // final commit covers all MMAs -> stage buffers are free for reuse
    int sl = (nch - 1) & 1;
    mbar_wait(sb + SMEM_MB + 8 * sl, ph[sl]);
    asm volatile("tcgen05.fence::after_thread_sync;" ::: "memory");
    __syncthreads();

    // ---- staged transpose epilogue (coalesced STG) ----
    float* stg = (float*)(smem + SA_OFF);
    int rw = wid & 3;
    int cq = wid >> 2;
    for (int half = 0; half < 2; half++) {
#pragma unroll
        for (int i = 0; i < 2; i++) {
            uint32_t r[32];
            TC_LD32(r, tmem + half * 128 + cq * 64 + i * 32);
            asm volatile("tcgen05.wait::ld.sync.aligned;" ::: "memory");
            float* dst = stg + (rw * 32 + lid) * EPI_PITCH + cq * 64 + i * 32;
#pragma unroll
            for (int q = 0; q < 8; q++)
                *(float4*)(dst + q * 4) = make_float4(
                    __uint_as_float(r[q * 4 + 0]), __uint_as_float(r[q * 4 + 1]),
                    __uint_as_float(r[q * 4 + 2]), __uint_as_float(r[q * 4 + 3]));
        }
        __syncthreads();

        int nb = n0 + half * 128 + lid * 4;
        bool nv = nb < N;   // N % 4 == 0 for all layers
        float4 bz = make_float4(0.f, 0.f, 0.f, 0.f);
        if (nv) bz = *(const float4*)(bp + nb);
#pragma unroll
        for (int rr = 0; rr < 16; rr++) {
            int r = wid * 16 + rr;
            int grow = m0 + r;
            if (grow < seg1 && nv) {
                float4 v = *(float4*)(stg + r * EPI_PITCH + lid * 4);
                v.x += bz.x; v.y += bz.y; v.z += bz.z; v.w += bz.w;
                if (EPI == 0) {
                    v.x = fmaxf(v.x, 0.f); v.y = fmaxf(v.y, 0.f);
                    v.z = fmaxf(v.z, 0.f); v.w = fmaxf(v.w, 0.f);
                } else if (EPI == 2) {
                    v.x = 1.f / (1.f + expf(-v.x));
                    v.y = 1.f / (1.f + expf(-v.y));
                    v.z = 1.f / (1.f + expf(-v.z));
                    v.w = 1.f / (1.f + expf(-v.w));
                }
                size_t orow = (EPI == 2) ? (size_t)g_idx[grow] : (size_t)grow;
                *(float4*)(C + orow * ldc + nb) = v;
            }
        }
        __syncthreads();
    }

    asm volatile("tcgen05.fence::before_thread_sync;" ::: "memory");
    __syncthreads();
    if (wid == 0)
        asm volatile("tcgen05.dealloc.cta_group::1.sync.aligned.b32 %0, %1;"
                     :: "r"(tmem), "r"(256u));

#else
    // ================= fp32 SIMT fallback (verified round-2 code) =================
    const int BK = 16;
    float* As = (float*)smem;                   // [BK][128]
    float* Bs = (float*)(smem + BK * 128 * 4);  // [BK][128]

    int ar = tid & 127;
    int ak = (tid >> 7) * 8;
    int as_ = m0 + ar;
    bool avalid = (as_ < seg1);
    const float* Arow = nullptr;
    if (avalid) {
        int src = GATHER ? g_idx[as_] : as_;
        Arow = A + (size_t)src * lda;
    }
    int bk = tid >> 4;
    int bn = (tid & 15) * 8;
    int ty = tid >> 4;
    int tx = tid & 15;

    for (int half = 0; half < 2; half++) {
        int n0h = n0 + half * 128;
        if (n0h >= N) break;

        float acc[8][8];
#pragma unroll
        for (int i = 0; i < 8; i++)
#pragma unroll
            for (int j = 0; j < 8; j++) acc[i][j] = 0.f;

        for (int k0 = 0; k0 < K; k0 += BK) {
            if (avalid) {
                float4 a0 = *(const float4*)(Arow + k0 + ak);
                float4 a1 = *(const float4*)(Arow + k0 + ak + 4);
                As[(ak + 0) * 128 + ar] = a0.x; As[(ak + 1) * 128 + ar] = a0.y;
                As[(ak + 2) * 128 + ar] = a0.z; As[(ak + 3) * 128 + ar] = a0.w;
                As[(ak + 4) * 128 + ar] = a1.x; As[(ak + 5) * 128 + ar] = a1.y;
                As[(ak + 6) * 128 + ar] = a1.z; As[(ak + 7) * 128 + ar] = a1.w;
            } else {
#pragma unroll
                for (int q = 0; q < 8; q++) As[(ak + q) * 128 + ar] = 0.f;
            }
            {
                const float* Wrow = Wp + (size_t)(k0 + bk) * N + n0h + bn;
                if (n0h + bn + 7 < N) {
                    float4 b0 = *(const float4*)(Wrow);
                    float4 b1 = *(const float4*)(Wrow + 4);
                    Bs[bk * 128 + bn + 0] = b0.x; Bs[bk * 128 + bn + 1] = b0.y;
                    Bs[bk * 128 + bn + 2] = b0.z; Bs[bk * 128 + bn + 3] = b0.w;
                    Bs[bk * 128 + bn + 4] = b1.x; Bs[bk * 128 + bn + 5] = b1.y;
                    Bs[bk * 128 + bn + 6] = b1.z; Bs[bk * 128 + bn + 7] = b1.w;
                } else {
#pragma unroll
                    for (int q = 0; q < 8; q++)
                        Bs[bk * 128 + bn + q] = (n0h + bn + q < N) ? Wrow[q] : 0.f;
                }
            }
            __syncthreads();
#pragma unroll
            for (int k = 0; k < BK; k++) {
                float a[8], b[8];
                *(float4*)&a[0] = *(const float4*)&As[k * 128 + ty * 4];
                *(float4*)&a[4] = *(const float4*)&As[k * 128 + 64 + ty * 4];
                *(float4*)&b[0] = *(const float4*)&Bs[k * 128 + tx * 4];
                *(float4*)&b[4] = *(const float4*)&Bs[k * 128 + 64 + tx * 4];
#pragma unroll
                for (int i = 0; i < 8; i++)
#pragma unroll
                    for (int j = 0; j < 8; j++)
                        acc[i][j] = fmaf(a[i], b[j], acc[i][j]);
            }
            __syncthreads();
        }

#pragma unroll
        for (int i = 0; i < 8; i++) {
            int s = m0 + ((i < 4) ? (ty * 4 + i) : (64 + ty * 4 + i - 4));
            if (s >= seg1) continue;
            size_t outrow = (EPI == 2) ? (size_t)g_idx[s] : (size_t)s;
#pragma unroll
            for (int j = 0; j < 8; j++) {
                int n = n0h + ((j < 4) ? (tx * 4 + j) : (64 + tx * 4 + j - 4));
                if (n >= N) continue;
                float v = acc[i][j] + bp[n];
                if (EPI == 0)      v = fmaxf(v, 0.f);
                else if (EPI == 2) v = 1.f / (1.f + expf(-v));
                C[outrow * ldc + n] = v;
            }
        }
        __syncthreads();
    }
#endif
}

// reparameterization: enc (bufB, ld 256) -> mu/log_sigma in out, z -> bufA (ld 128)
__global__ void k_z(const float* __restrict__ eps, float* __restrict__ out) {
    int g = blockIdx.x * blockDim.x + threadIdx.x;
    if (g >= BB * LAT) return;
    int s = g >> 7;
    int j = g & 127;
    int orig = g_idx[s];
    float mu = g_bufB[(size_t)s * 256 + j];
    float ls = g_bufB[(size_t)s * 256 + 128 + j];
    size_t mu_off = (size_t)BB * IN_DIM;
    size_t ls_off = mu_off + (size_t)BB * LAT;
    out[mu_off + (size_t)orig * LAT + j] = mu;
    out[ls_off + (size_t)orig * LAT + j] = ls;
    g_bufA[(size_t)s * LAT + j] = mu + expf(ls) * eps[(size_t)orig * LAT + j];
}

extern "C" void kernel_launch(void* const* d_in, const int* in_sizes, int n_in,
                              void* d_out, int out_size) {
    const float* x    = (const float*)d_in[0];
    const int*   task = (const int*)  d_in[1];
    const float* eps  = (const float*)d_in[2];
    const float* eW1  = (const float*)d_in[3];
    const float* eb1  = (const float*)d_in[4];
    const float* eW2  = (const float*)d_in[5];
    const float* eb2  = (const float*)d_in[6];
    const float* eW3  = (const float*)d_in[7];
    const float* eb3  = (const float*)d_in[8];
    const float* eW4  = (const float*)d_in[9];
    const float* eb4  = (const float*)d_in[10];
    const float* dWs1 = (const float*)d_in[11];
    const float* dbs1 = (const float*)d_in[12];
    const float* dWs2 = (const float*)d_in[13];
    const float* dbs2 = (const float*)d_in[14];
    const float* dWh1 = (const float*)d_in[15];
    const float* dbh1 = (const float*)d_in[16];
    const float* dWh2 = (const float*)d_in[17];
    const float* dbh2 = (const float*)d_in[18];
    float* out = (float*)d_out;

    float *bufA, *bufB;
    cudaGetSymbolAddress((void**)&bufA, g_bufA);
    cudaGetSymbolAddress((void**)&bufB, g_bufB);

    // encoder (bf16x3 split) instances
    cudaFuncSetAttribute(tgemm<true,  true,  0, true>,  cudaFuncAttributeMaxDynamicSharedMemorySize, SMEM_TOT_S);
    cudaFuncSetAttribute(tgemm<false, true,  0, true>,  cudaFuncAttributeMaxDynamicSharedMemorySize, SMEM_TOT_S);
    cudaFuncSetAttribute(tgemm<false, true,  1, true>,  cudaFuncAttributeMaxDynamicSharedMemorySize, SMEM_TOT_S);
    // decoder (plain TF32) instances
    cudaFuncSetAttribute(tgemm<false, false, 0, false>, cudaFuncAttributeMaxDynamicSharedMemorySize, SMEM_TOT_P);
    cudaFuncSetAttribute(tgemm<false, true,  0, false>, cudaFuncAttributeMaxDynamicSharedMemorySize, SMEM_TOT_P);
    cudaFuncSetAttribute(tgemm<false, true,  2, false>, cudaFuncAttributeMaxDynamicSharedMemorySize, SMEM_TOT_P);

    // group samples by task
    k_zero<<<1, 32>>>();
    k_count<<<(BB + 255) / 256, 256>>>(task);
    k_scan<<<1, 32>>>();
    k_fill<<<(BB + 255) / 256, 256>>>(task);

    // encoder (per-task segments, activations kept in sorted order) — bf16x3
    tgemm<true,  true, 0, true><<<dim3(4, 64, NT), 256, SMEM_TOT_S>>>(x,    IN_DIM, eW1, IN_DIM, HID,   eb1, bufA, HID);
    tgemm<false, true, 0, true><<<dim3(4, 64, NT), 256, SMEM_TOT_S>>>(bufA, HID,    eW2, HID,    HID,   eb2, bufB, HID);
    tgemm<false, true, 0, true><<<dim3(4, 64, NT), 256, SMEM_TOT_S>>>(bufB, HID,    eW3, HID,    HID,   eb3, bufA, HID);
    tgemm<false, true, 1, true><<<dim3(1, 64, NT), 256, SMEM_TOT_S>>>(bufA, HID,    eW4, HID,    2*LAT, eb4, bufB, 2*LAT);

    // reparameterize: mu/log_sigma -> d_out, z -> bufA
    k_z<<<(BB * LAT + 255) / 256, 256>>>(eps, out);

    // decoder — plain TF32
    tgemm<false, false, 0, false><<<dim3(4, 64, 1),  256, SMEM_TOT_P>>>(bufA, LAT, dWs1, LAT, HID,    dbs1, bufB, HID);
    tgemm<false, false, 0, false><<<dim3(4, 64, 1),  256, SMEM_TOT_P>>>(bufB, HID, dWs2, HID, HID,    dbs2, bufA, HID);
    tgemm<false, true,  0, false><<<dim3(4, 64, NT), 256, SMEM_TOT_P>>>(bufA, HID, dWh1, HID, HID,    dbh1, bufB, HID);
    tgemm<false, true,  2, false><<<dim3(4, 64, NT), 256, SMEM_TOT_P>>>(bufB, HID, dWh2, HID, IN_DIM, dbh2, out, IN_DIM);
}

// round 12
// speedup vs baseline: 4.2819x; 1.0045x over previous
#include <cuda_runtime.h>
#include <cuda_bf16.h>
#include <math.h>
#include <cstdint>

#define BB      8192
#define IN_DIM  784
#define HID     1024
#define LAT     128
#define NT      10
#define YMAX    74   // tight bound on sum ceil(cnt_t/128): 64 + NT partials

#if defined(__CUDA_ARCH__) && (__CUDA_ARCH__ == 1030) && \
    (defined(__CUDA_ARCH_FEAT_SM103_ALL) || \
     (defined(__CUDA_ARCH_SPECIFIC__) && (__CUDA_ARCH_SPECIFIC__ >= 1030)))
#define HAS_TC 1
#else
#define HAS_TC 0
#endif

// ---- scratch (static device globals; no allocation) ----
__device__ float g_bufA[BB * HID];
__device__ float g_bufB[BB * HID];
__device__ int   g_idx[BB];
__device__ int   g_off[NT + 1];
__device__ int   g_blk[YMAX + 8];   // packed: task | (yblock<<8)
__device__ int   g_nblk;

// ---- single-launch task grouping + block map ----
__global__ void k_group(const int* __restrict__ task) {
    __shared__ int cnt[NT];
    __shared__ int fil[NT];
    int tid = threadIdx.x;
    if (tid < NT) cnt[tid] = 0;
    __syncthreads();
    for (int i = tid; i < BB; i += blockDim.x) atomicAdd(&cnt[task[i]], 1);
    __syncthreads();
    if (tid == 0) {
        int s = 0, nb = 0;
        for (int t = 0; t < NT; t++) {
            g_off[t] = s;
            fil[t] = s;
            int nby = (cnt[t] + 127) >> 7;
            for (int y = 0; y < nby; y++) g_blk[nb++] = t | (y << 8);
            s += cnt[t];
        }
        g_off[NT] = s;
        g_nblk = nb;
    }
    __syncthreads();
    for (int i = tid; i < BB; i += blockDim.x) {
        int t = task[i];
        int p = atomicAdd(&fil[t], 1);
        g_idx[p] = i;
    }
}

// ---------- tcgen05 helpers (arch-specific branch only) ----------
#if HAS_TC
__device__ __forceinline__ uint32_t smem_u32(const void* p) {
    uint32_t a;
    asm("{ .reg .u64 t; cvta.to.shared.u64 t, %1; cvt.u32.u64 %0, t; }" : "=r"(a) : "l"(p));
    return a;
}
__device__ __forceinline__ uint32_t elect1() {
    uint32_t r;
    asm volatile("{ .reg .pred p; elect.sync _|p, 0xFFFFFFFF; selp.b32 %0, 1, 0, p; }" : "=r"(r));
    return r;
}
__device__ __forceinline__ void mbar_init(uint32_t mbar, uint32_t cnt) {
    asm volatile("mbarrier.init.shared.b64 [%0], %1;" :: "r"(mbar), "r"(cnt) : "memory");
}
__device__ __forceinline__ void mbar_wait(uint32_t mbar, uint32_t parity) {
    asm volatile(
        "{\n\t.reg .pred P1;\n\t"
        "WAIT_%=:\n\t"
        "mbarrier.try_wait.parity.acquire.cta.shared::cta.b64 P1, [%0], %1, 0x989680;\n\t"
        "@P1 bra.uni DONE_%=;\n\t"
        "bra.uni WAIT_%=;\n\t"
        "DONE_%=:\n\t}"
        :: "r"(mbar), "r"(parity) : "memory");
}
__device__ __forceinline__ void mma_tf32(uint32_t d, uint64_t ad, uint64_t bd,
                                         uint32_t idesc, uint32_t en) {
    asm volatile(
        "{\n\t.reg .pred p;\n\t"
        "setp.ne.u32 p, %4, 0;\n\t"
        "tcgen05.mma.cta_group::1.kind::tf32 [%0], %1, %2, %3, {%5, %5, %5, %5}, p;\n\t}"
        :: "r"(d), "l"(ad), "l"(bd), "r"(idesc), "r"(en), "r"(0u) : "memory");
}
__device__ __forceinline__ void mma_f16(uint32_t d, uint64_t ad, uint64_t bd,
                                        uint32_t idesc, uint32_t en) {
    asm volatile(
        "{\n\t.reg .pred p;\n\t"
        "setp.ne.u32 p, %4, 0;\n\t"
        "tcgen05.mma.cta_group::1.kind::f16 [%0], %1, %2, %3, {%5, %5, %5, %5}, p;\n\t}"
        :: "r"(d), "l"(ad), "l"(bd), "r"(idesc), "r"(en), "r"(0u) : "memory");
}
__device__ __forceinline__ void tc_commit(uint32_t mbar) {
    asm volatile("tcgen05.commit.cta_group::1.mbarrier::arrive::one.shared::cluster.b64 [%0];"
                 :: "r"(mbar) : "memory");
}
__device__ __forceinline__ void bf16_split2(float v0, float v1,
                                            uint32_t& hp, uint32_t& lp) {
    asm("cvt.rn.bf16x2.f32 %0, %1, %2;" : "=r"(hp) : "f"(v1), "f"(v0));
    float h0 = __uint_as_float(hp << 16);
    float h1 = __uint_as_float(hp & 0xFFFF0000u);
    float l0 = v0 - h0, l1 = v1 - h1;
    asm("cvt.rn.bf16x2.f32 %0, %1, %2;" : "=r"(lp) : "f"(l1), "f"(l0));
}

#define TC_LD32(r, addr) \
    asm volatile( \
        "tcgen05.ld.sync.aligned.32x32b.x32.b32 " \
        "{%0, %1, %2, %3, %4, %5, %6, %7, " \
        " %8, %9, %10, %11, %12, %13, %14, %15, " \
        " %16, %17, %18, %19, %20, %21, %22, %23, " \
        " %24, %25, %26, %27, %28, %29, %30, %31}, [%32];" \
        : "=r"((r)[0]),  "=r"((r)[1]),  "=r"((r)[2]),  "=r"((r)[3]), \
          "=r"((r)[4]),  "=r"((r)[5]),  "=r"((r)[6]),  "=r"((r)[7]), \
          "=r"((r)[8]),  "=r"((r)[9]),  "=r"((r)[10]), "=r"((r)[11]), \
          "=r"((r)[12]), "=r"((r)[13]), "=r"((r)[14]), "=r"((r)[15]), \
          "=r"((r)[16]), "=r"((r)[17]), "=r"((r)[18]), "=r"((r)[19]), \
          "=r"((r)[20]), "=r"((r)[21]), "=r"((r)[22]), "=r"((r)[23]), \
          "=r"((r)[24]), "=r"((r)[25]), "=r"((r)[26]), "=r"((r)[27]), \
          "=r"((r)[28]), "=r"((r)[29]), "=r"((r)[30]), "=r"((r)[31]) \
        : "r"(addr))

static constexpr uint64_t DESC_BASE =
    (2ull << 61) | (1ull << 46) | (64ull << 32) | (1ull << 16);
__device__ __forceinline__ uint64_t mkdesc(uint32_t a) {
    return DESC_BASE | ((uint64_t)(a >> 4) & 0x3FFF);
}
#endif  // HAS_TC

#define SWZ(o) ((o) ^ (((o) >> 3) & 0x70))

// ---------- grouped GEMM: 128 x 256 tile per CTA ----------
#define NTILE 256
#define KC    32
#define KCB   64
#define SMEM_TMEM 0
#define SMEM_MB   16
#define SA_OFF    1024
#define STAGE_P   49152
#define STAGE_S   98304
#define SMEM_TOT_P (SA_OFF + 2 * STAGE_P)   //  99328
#define SMEM_TOT_S (SA_OFF + 2 * STAGE_S)   // 197632
#define EPI_PITCH 132
#define EPI_PITCH3 260      // EPI3: 256 cols staged at once; 260%32=4 -> bank-clean

static constexpr uint32_t IDESC_TF32 =
    (1u << 4) | (2u << 7) | (2u << 10) | ((NTILE / 8) << 17) | ((128 / 16) << 24);
static constexpr uint32_t IDESC_BF16 =
    (1u << 4) | (1u << 7) | (1u << 10) | ((NTILE / 8) << 17) | ((128 / 16) << 24);

// EPI: 0 bias+relu, 2 bias+sigmoid+row-scatter, 3 fused reparam (enc4):
//      mu/ls scatter -> out2, z -> C (sorted order, ldc=LAT)
// SPLIT: bf16x3 emulated-fp32
template <bool GATHER, bool PERTASK, int EPI, bool SPLIT>
__global__ __launch_bounds__(256, SPLIT ? 1 : 2) void tgemm(
    const float* __restrict__ A, int lda,
    const float* __restrict__ W, int K, int N,
    const float* __restrict__ bias,
    float* __restrict__ C, int ldc,
    const float* __restrict__ eps, float* __restrict__ out2)
{
    extern __shared__ __align__(1024) char smem[];

    int t = 0, seg0 = 0, seg1 = BB, m0;
    if (PERTASK) {
        if ((int)blockIdx.y >= g_nblk) return;
        int bv = g_blk[blockIdx.y];
        t    = bv & 255;
        seg0 = g_off[t];
        seg1 = g_off[t + 1];
        m0   = seg0 + (bv >> 8) * 128;
    } else {
        m0 = blockIdx.y * 128;
    }
    int n0 = blockIdx.x * NTILE;

    const float* Wp = W    + (PERTASK ? (size_t)t * K * N : 0);
    const float* bp = bias + (PERTASK ? (size_t)t * N     : 0);

    int tid = threadIdx.x;

#if HAS_TC
    // ================= tcgen05 path =================
    const int STAGE_B = SPLIT ? STAGE_S : STAGE_P;
    const int KCC     = SPLIT ? KCB : KC;
    uint32_t sb = smem_u32(smem);
    int wid = tid >> 5;
    int lid = tid & 31;

    if (wid == 0) {
        asm volatile("tcgen05.alloc.cta_group::1.sync.aligned.shared::cta.b32 [%0], %1;"
                     :: "r"(sb + SMEM_TMEM), "r"(256u) : "memory");
        asm volatile("tcgen05.relinquish_alloc_permit.cta_group::1.sync.aligned;");
    }
    if (tid == 0) { mbar_init(sb + SMEM_MB, 1); mbar_init(sb + SMEM_MB + 8, 1); }
    __syncthreads();
    uint32_t tmem;
    asm volatile("ld.shared.b32 %0, [%1];" : "=r"(tmem) : "r"(sb + SMEM_TMEM));

    int nch = (K + KCC - 1) / KCC;
    int ph[2] = {0, 0};

    int a_ke = (tid & 7) * (SPLIT ? 8 : 4);
    int a_mb = tid >> 3;
    const float* Ar[4];
#pragma unroll
    for (int p = 0; p < 4; p++) {
        int gs = m0 + p * 32 + a_mb;
        int src = (gs < seg1) ? (GATHER ? g_idx[gs] : gs)
                              : (GATHER ? g_idx[seg0] : seg0);
        Ar[p] = A + (size_t)src * lda + a_ke;
    }
    int b_n = tid;
    bool b_nv = (n0 + b_n < N);
    const float* Wcol = Wp + n0 + b_n;

    for (int c = 0; c < nch; c++) {
        int s = c & 1;
        if (c >= 2) { mbar_wait(sb + SMEM_MB + 8 * s, ph[s]); ph[s] ^= 1; }
        int k0 = c * KCC;
        char* sAh = smem + SA_OFF + s * STAGE_B;
        char* sAl = sAh + 16384;
        char* sBh = smem + SA_OFF + (SPLIT ? 32768 : 16384) + s * STAGE_B;
        char* sBl = sBh + 32768;

        if (SPLIT) {
#pragma unroll
            for (int p = 0; p < 4; p++) {
                int m = p * 32 + a_mb;
                float4 v0 = make_float4(0.f, 0.f, 0.f, 0.f);
                float4 v1 = make_float4(0.f, 0.f, 0.f, 0.f);
                if (k0 + a_ke < K)     v0 = *(const float4*)(Ar[p] + k0);
                if (k0 + a_ke + 4 < K) v1 = *(const float4*)(Ar[p] + k0 + 4);
                uint32_t h[4], l[4];
                bf16_split2(v0.x, v0.y, h[0], l[0]);
                bf16_split2(v0.z, v0.w, h[1], l[1]);
                bf16_split2(v1.x, v1.y, h[2], l[2]);
                bf16_split2(v1.z, v1.w, h[3], l[3]);
                uint32_t off = SWZ((uint32_t)(m * 128 + a_ke * 2));
                *(uint4*)(sAh + off) = make_uint4(h[0], h[1], h[2], h[3]);
                *(uint4*)(sAl + off) = make_uint4(l[0], l[1], l[2], l[3]);
            }
#pragma unroll
            for (int kg = 0; kg < 8; kg++) {
                float v[8];
                bool kv = b_nv && (k0 + kg * 8 < K);
#pragma unroll
                for (int q = 0; q < 8; q++)
                    v[q] = kv ? Wcol[(size_t)(k0 + kg * 8 + q) * N] : 0.f;
                uint32_t h[4], l[4];
                bf16_split2(v[0], v[1], h[0], l[0]);
                bf16_split2(v[2], v[3], h[1], l[1]);
                bf16_split2(v[4], v[5], h[2], l[2]);
                bf16_split2(v[6], v[7], h[3], l[3]);
                uint32_t off = SWZ((uint32_t)(b_n * 128 + kg * 16));
                *(uint4*)(sBh + off) = make_uint4(h[0], h[1], h[2], h[3]);
                *(uint4*)(sBl + off) = make_uint4(l[0], l[1], l[2], l[3]);
            }
        } else {
#pragma unroll
            for (int p = 0; p < 4; p++) {
                int m = p * 32 + a_mb;
                float4 v = make_float4(0.f, 0.f, 0.f, 0.f);
                if (k0 + a_ke < K)
                    v = *(const float4*)(Ar[p] + k0);
                *(float4*)(sAh + SWZ((uint32_t)(m * KC + a_ke) * 4)) = v;
            }
#pragma unroll
            for (int kg = 0; kg < 8; kg++) {
                float v0 = 0.f, v1 = 0.f, v2 = 0.f, v3 = 0.f;
                if (b_nv) {
                    int k = k0 + kg * 4;
                    if (k < K) {
                        v0 = Wcol[(size_t)(k + 0) * N];
                        v1 = Wcol[(size_t)(k + 1) * N];
                        v2 = Wcol[(size_t)(k + 2) * N];
                        v3 = Wcol[(size_t)(k + 3) * N];
                    }
                }
                *(float4*)(sBh + SWZ((uint32_t)(b_n * KC + kg * 4) * 4)) =
                    make_float4(v0, v1, v2, v3);
            }
        }
        __syncthreads();

        if (wid == 0) {
            asm volatile("fence.proxy.async.shared::cta;" ::: "memory");
            if (elect1()) {
                uint64_t adh = mkdesc(smem_u32(sAh));
                uint64_t bdh = mkdesc(smem_u32(sBh));
                if (SPLIT) {
                    uint64_t adl = mkdesc(smem_u32(sAl));
                    uint64_t bdl = mkdesc(smem_u32(sBl));
#pragma unroll
                    for (int j = 0; j < 4; j++) {
                        mma_f16(tmem, adl + j * 2, bdh + j * 2, IDESC_BF16,
                                (c > 0 || j > 0) ? 1u : 0u);
                        mma_f16(tmem, adh + j * 2, bdl + j * 2, IDESC_BF16, 1u);
                        mma_f16(tmem, adh + j * 2, bdh + j * 2, IDESC_BF16, 1u);
                    }
                } else {
#pragma unroll
                    for (int j = 0; j < 4; j++)
                        mma_tf32(tmem, adh + j * 2, bdh + j * 2, IDESC_TF32,
                                 (c > 0 || j > 0) ? 1u : 0u);
                }
                tc_commit(sb + SMEM_MB + 8 * s);
            }
        }
    }

    int sl = (nch - 1) & 1;
    mbar_wait(sb + SMEM_MB + 8 * sl, ph[sl]);
    asm volatile("tcgen05.fence::after_thread_sync;" ::: "memory");
    __syncthreads();

    float* stg = (float*)(smem + SA_OFF);
    int rw = wid & 3;
    int cq = wid >> 2;

    if (EPI == 3) {
        // ---- fused reparameterization epilogue (enc4: N == 256 == 2*LAT) ----
        // stage all 256 cols at pitch 260
#pragma unroll
        for (int half = 0; half < 2; half++)
#pragma unroll
            for (int i = 0; i < 2; i++) {
                uint32_t r[32];
                TC_LD32(r, tmem + half * 128 + cq * 64 + i * 32);
                asm volatile("tcgen05.wait::ld.sync.aligned;" ::: "memory");
                float* dst = stg + (rw * 32 + lid) * EPI_PITCH3 + half * 128 + cq * 64 + i * 32;
#pragma unroll
                for (int q = 0; q < 8; q++)
                    *(float4*)(dst + q * 4) = make_float4(
                        __uint_as_float(r[q * 4 + 0]), __uint_as_float(r[q * 4 + 1]),
                        __uint_as_float(r[q * 4 + 2]), __uint_as_float(r[q * 4 + 3]));
            }
        __syncthreads();

        int nb = lid * 4;
        float4 bmu = *(const float4*)(bp + nb);
        float4 bls = *(const float4*)(bp + 128 + nb);
        size_t mu_off = (size_t)BB * IN_DIM;
        size_t ls_off = mu_off + (size_t)BB * LAT;
#pragma unroll
        for (int rr = 0; rr < 16; rr++) {
            int r = wid * 16 + rr;
            int grow = m0 + r;
            if (grow < seg1) {
                float4 mu = *(float4*)(stg + r * EPI_PITCH3 + nb);
                float4 lv = *(float4*)(stg + r * EPI_PITCH3 + 128 + nb);
                mu.x += bmu.x; mu.y += bmu.y; mu.z += bmu.z; mu.w += bmu.w;
                lv.x += bls.x; lv.y += bls.y; lv.z += bls.z; lv.w += bls.w;
                int orig = g_idx[grow];
                float4 ep = *(const float4*)(eps + (size_t)orig * LAT + nb);
                float4 z;
                z.x = mu.x + expf(lv.x) * ep.x;
                z.y = mu.y + expf(lv.y) * ep.y;
                z.z = mu.z + expf(lv.z) * ep.z;
                z.w = mu.w + expf(lv.w) * ep.w;
                *(float4*)(out2 + mu_off + (size_t)orig * LAT + nb) = mu;
                *(float4*)(out2 + ls_off + (size_t)orig * LAT + nb) = lv;
                *(float4*)(C + (size_t)grow * ldc + nb) = z;
            }
        }
        __syncthreads();
    } else {
        // ---- staged transpose epilogue (coalesced STG) ----
        for (int half = 0; half < 2; half++) {
#pragma unroll
            for (int i = 0; i < 2; i++) {
                uint32_t r[32];
                TC_LD32(r, tmem + half * 128 + cq * 64 + i * 32);
                asm volatile("tcgen05.wait::ld.sync.aligned;" ::: "memory");
                float* dst = stg + (rw * 32 + lid) * EPI_PITCH + cq * 64 + i * 32;
#pragma unroll
                for (int q = 0; q < 8; q++)
                    *(float4*)(dst + q * 4) = make_float4(
                        __uint_as_float(r[q * 4 + 0]), __uint_as_float(r[q * 4 + 1]),
                        __uint_as_float(r[q * 4 + 2]), __uint_as_float(r[q * 4 + 3]));
            }
            __syncthreads();

            int nb = n0 + half * 128 + lid * 4;
            bool nv = nb < N;
            float4 bz = make_float4(0.f, 0.f, 0.f, 0.f);
            if (nv) bz = *(const float4*)(bp + nb);
#pragma unroll
            for (int rr = 0; rr < 16; rr++) {
                int r = wid * 16 + rr;
                int grow = m0 + r;
                if (grow < seg1 && nv) {
                    float4 v = *(float4*)(stg + r * EPI_PITCH + lid * 4);
                    v.x += bz.x; v.y += bz.y; v.z += bz.z; v.w += bz.w;
                    if (EPI == 0) {
                        v.x = fmaxf(v.x, 0.f); v.y = fmaxf(v.y, 0.f);
                        v.z = fmaxf(v.z, 0.f); v.w = fmaxf(v.w, 0.f);
                    } else if (EPI == 2) {
                        v.x = 1.f / (1.f + expf(-v.x));
                        v.y = 1.f / (1.f + expf(-v.y));
                        v.z = 1.f / (1.f + expf(-v.z));
                        v.w = 1.f / (1.f + expf(-v.w));
                    }
                    size_t orow = (EPI == 2) ? (size_t)g_idx[grow] : (size_t)grow;
                    *(float4*)(C + orow * ldc + nb) = v;
                }
            }
            __syncthreads();
        }
    }

    asm volatile("tcgen05.fence::before_thread_sync;" ::: "memory");
    __syncthreads();
    if (wid == 0)
        asm volatile("tcgen05.dealloc.cta_group::1.sync.aligned.b32 %0, %1;"
                     :: "r"(tmem), "r"(256u));

#else
    // ================= fp32 SIMT fallback =================
    const int BK = 16;
    float* As = (float*)smem;
    float* Bs = (float*)(smem + BK * 128 * 4);

    int ar = tid & 127;
    int ak = (tid >> 7) * 8;
    int as_ = m0 + ar;
    bool avalid = (as_ < seg1);
    const float* Arow = nullptr;
    if (avalid) {
        int src = GATHER ? g_idx[as_] : as_;
        Arow = A + (size_t)src * lda;
    }
    int bk = tid >> 4;
    int bn = (tid & 15) * 8;
    int ty = tid >> 4;
    int tx = tid & 15;

    float muv[8][8];   // EPI3: saved mu from half 0

    for (int half = 0; half < 2; half++) {
        int n0h = n0 + half * 128;
        if (n0h >= N) break;

        float acc[8][8];
#pragma unroll
        for (int i = 0; i < 8; i++)
#pragma unroll
            for (int j = 0; j < 8; j++) acc[i][j] = 0.f;

        for (int k0 = 0; k0 < K; k0 += BK) {
            if (avalid) {
                float4 a0 = *(const float4*)(Arow + k0 + ak);
                float4 a1 = *(const float4*)(Arow + k0 + ak + 4);
                As[(ak + 0) * 128 + ar] = a0.x; As[(ak + 1) * 128 + ar] = a0.y;
                As[(ak + 2) * 128 + ar] = a0.z; As[(ak + 3) * 128 + ar] = a0.w;
                As[(ak + 4) * 128 + ar] = a1.x; As[(ak + 5) * 128 + ar] = a1.y;
                As[(ak + 6) * 128 + ar] = a1.z; As[(ak + 7) * 128 + ar] = a1.w;
            } else {
#pragma unroll
                for (int q = 0; q < 8; q++) As[(ak + q) * 128 + ar] = 0.f;
            }
            {
                const float* Wrow = Wp + (size_t)(k0 + bk) * N + n0h + bn;
                if (n0h + bn + 7 < N) {
                    float4 b0 = *(const float4*)(Wrow);
                    float4 b1 = *(const float4*)(Wrow + 4);
                    Bs[bk * 128 + bn + 0] = b0.x; Bs[bk * 128 + bn + 1] = b0.y;
                    Bs[bk * 128 + bn + 2] = b0.z; Bs[bk * 128 + bn + 3] = b0.w;
                    Bs[bk * 128 + bn + 4] = b1.x; Bs[bk * 128 + bn + 5] = b1.y;
                    Bs[bk * 128 + bn + 6] = b1.z; Bs[bk * 128 + bn + 7] = b1.w;
                } else {
#pragma unroll
                    for (int q = 0; q < 8; q++)
                        Bs[bk * 128 + bn + q] = (n0h + bn + q < N) ? Wrow[q] : 0.f;
                }
            }
            __syncthreads();
#pragma unroll
            for (int k = 0; k < BK; k++) {
                float a[8], b[8];
                *(float4*)&a[0] = *(const float4*)&As[k * 128 + ty * 4];
                *(float4*)&a[4] = *(const float4*)&As[k * 128 + 64 + ty * 4];
                *(float4*)&b[0] = *(const float4*)&Bs[k * 128 + tx * 4];
                *(float4*)&b[4] = *(const float4*)&Bs[k * 128 + 64 + tx * 4];
#pragma unroll
                for (int i = 0; i < 8; i++)
#pragma unroll
                    for (int j = 0; j < 8; j++)
                        acc[i][j] = fmaf(a[i], b[j], acc[i][j]);
            }
            __syncthreads();
        }

#pragma unroll
        for (int i = 0; i < 8; i++) {
            int s = m0 + ((i < 4) ? (ty * 4 + i) : (64 + ty * 4 + i - 4));
            if (s >= seg1) continue;
#pragma unroll
            for (int j = 0; j < 8; j++) {
                int n = n0h + ((j < 4) ? (tx * 4 + j) : (64 + tx * 4 + j - 4));
                if (n >= N) continue;
                float v = acc[i][j] + bp[n];
                if (EPI == 3) {
                    int orig = g_idx[s];
                    int nl = n & 127;   // col within mu/ls half
                    size_t mu_off = (size_t)BB * IN_DIM;
                    size_t ls_off = mu_off + (size_t)BB * LAT;
                    if (half == 0) {
                        muv[i][j] = v;
                        out2[mu_off + (size_t)orig * LAT + nl] = v;
                    } else {
                        out2[ls_off + (size_t)orig * LAT + nl] = v;
                        float z = muv[i][j] + expf(v) * eps[(size_t)orig * LAT + nl];
                        C[(size_t)s * ldc + nl] = z;
                    }
                } else {
                    if (EPI == 0)      v = fmaxf(v, 0.f);
                    else if (EPI == 2) v = 1.f / (1.f + expf(-v));
                    size_t orow = (EPI == 2) ? (size_t)g_idx[s] : (size_t)s;
                    C[orow * ldc + n] = v;
                }
            }
        }
        __syncthreads();
    }
#endif
}

extern "C" void kernel_launch(void* const* d_in, const int* in_sizes, int n_in,
                              void* d_out, int out_size) {
    const float* x    = (const float*)d_in[0];
    const int*   task = (const int*)  d_in[1];
    const float* eps  = (const float*)d_in[2];
    const float* eW1  = (const float*)d_in[3];
    const float* eb1  = (const float*)d_in[4];
    const float* eW2  = (const float*)d_in[5];
    const float* eb2  = (const float*)d_in[6];
    const float* eW3  = (const float*)d_in[7];
    const float* eb3  = (const float*)d_in[8];
    const float* eW4  = (const float*)d_in[9];
    const float* eb4  = (const float*)d_in[10];
    const float* dWs1 = (const float*)d_in[11];
    const float* dbs1 = (const float*)d_in[12];
    const float* dWs2 = (const float*)d_in[13];
    const float* dbs2 = (const float*)d_in[14];
    const float* dWh1 = (const float*)d_in[15];
    const float* dbh1 = (const float*)d_in[16];
    const float* dWh2 = (const float*)d_in[17];
    const float* dbh2 = (const float*)d_in[18];
    float* out = (float*)d_out;

    float *bufA, *bufB;
    cudaGetSymbolAddress((void**)&bufA, g_bufA);
    cudaGetSymbolAddress((void**)&bufB, g_bufB);

    cudaFuncSetAttribute(tgemm<true,  true,  0, true>,  cudaFuncAttributeMaxDynamicSharedMemorySize, SMEM_TOT_S);
    cudaFuncSetAttribute(tgemm<false, true,  0, true>,  cudaFuncAttributeMaxDynamicSharedMemorySize, SMEM_TOT_S);
    cudaFuncSetAttribute(tgemm<false, true,  3, true>,  cudaFuncAttributeMaxDynamicSharedMemorySize, SMEM_TOT_S);
    cudaFuncSetAttribute(tgemm<false, false, 0, false>, cudaFuncAttributeMaxDynamicSharedMemorySize, SMEM_TOT_P);
    cudaFuncSetAttribute(tgemm<false, true,  0, false>, cudaFuncAttributeMaxDynamicSharedMemorySize, SMEM_TOT_P);
    cudaFuncSetAttribute(tgemm<false, true,  2, false>, cudaFuncAttributeMaxDynamicSharedMemorySize, SMEM_TOT_P);

    // grouping: one launch builds g_idx / g_off / g_blk / g_nblk
    k_group<<<1, 256>>>(task);

    // encoder (per-task exact grid via g_blk) — bf16x3
    tgemm<true,  true, 0, true><<<dim3(4, YMAX), 256, SMEM_TOT_S>>>(x,    IN_DIM, eW1, IN_DIM, HID,   eb1, bufA, HID,   nullptr, nullptr);
    tgemm<false, true, 0, true><<<dim3(4, YMAX), 256, SMEM_TOT_S>>>(bufA, HID,    eW2, HID,    HID,   eb2, bufB, HID,   nullptr, nullptr);
    tgemm<false, true, 0, true><<<dim3(4, YMAX), 256, SMEM_TOT_S>>>(bufB, HID,    eW3, HID,    HID,   eb3, bufA, HID,   nullptr, nullptr);
    // enc4 + fused reparameterization: mu/ls -> out, z -> bufB (sorted, ld LAT)
    tgemm<false, true, 3, true><<<dim3(1, YMAX), 256, SMEM_TOT_S>>>(bufA, HID,    eW4, HID,    2*LAT, eb4, bufB, LAT,   eps, out);

    // decoder — plain TF32 (z now lives in bufB, ld 128)
    tgemm<false, false, 0, false><<<dim3(4, 64), 256, SMEM_TOT_P>>>(bufB, LAT, dWs1, LAT, HID,    dbs1, bufA, HID, nullptr, nullptr);
    tgemm<false, false, 0, false><<<dim3(4, 64), 256, SMEM_TOT_P>>>(bufA, HID, dWs2, HID, HID,    dbs2, bufB, HID, nullptr, nullptr);
    tgemm<false, true,  0, false><<<dim3(4, YMAX), 256, SMEM_TOT_P>>>(bufB, HID, dWh1, HID, HID,    dbh1, bufA, HID, nullptr, nullptr);
    tgemm<false, true,  2, false><<<dim3(4, YMAX), 256, SMEM_TOT_P>>>(bufA, HID, dWh2, HID, IN_DIM, dbh2, out, IN_DIM, nullptr, nullptr);
}

// round 14
// speedup vs baseline: 4.8624x; 1.1356x over previous
#include <cuda_runtime.h>
#include <cuda_bf16.h>
#include <math.h>
#include <cstdint>

#define BB      8192
#define IN_DIM  784
#define HID     1024
#define LAT     128
#define NT      10
#define YMAX    74   // tight bound on sum ceil(cnt_t/128): 64 + NT partials

#if defined(__CUDA_ARCH__) && (__CUDA_ARCH__ == 1030) && \
    (defined(__CUDA_ARCH_FEAT_SM103_ALL) || \
     (defined(__CUDA_ARCH_SPECIFIC__) && (__CUDA_ARCH_SPECIFIC__ >= 1030)))
#define HAS_TC 1
#else
#define HAS_TC 0
#endif

// ---- scratch (static device globals; no allocation) ----
__device__ float g_bufA[BB * HID];
__device__ float g_bufB[BB * HID];
__device__ int   g_idx[BB];
__device__ int   g_off[NT + 1];
__device__ int   g_blk[YMAX + 8];   // packed: task | (yblock<<8)
__device__ int   g_nblk;

// ---- pre-packed weight tiles (byte-exact SMEM tile images) ----
// encoder (bf16 hi||lo, SW128 swizzled, 64KB/tile):
__device__ char g_pE1[(size_t)4 * 13 * 10 * 65536];   // 33.25 MB
__device__ char g_pE2[(size_t)4 * 16 * 10 * 65536];   // 40 MB
__device__ char g_pE3[(size_t)4 * 16 * 10 * 65536];   // 40 MB
__device__ char g_pE4[(size_t)1 * 16 * 10 * 65536];   // 10 MB
// decoder (fp32, SW128 swizzled, 32KB/tile):
__device__ char g_pD1[(size_t)4 * 4  * 1  * 32768];   // 0.5 MB
__device__ char g_pD2[(size_t)4 * 32 * 1  * 32768];   // 4 MB
__device__ char g_pD3[(size_t)4 * 32 * 10 * 32768];   // 40 MB
__device__ char g_pD4[(size_t)4 * 32 * 10 * 32768];   // 40 MB

#define SWZ(o) ((o) ^ (((o) >> 3) & 0x70))

// pack (v0, v1) -> bf16x2 hi pair + residual lo pair (v0 at lower address)
__device__ __forceinline__ void bf16_split2(float v0, float v1,
                                            uint32_t& hp, uint32_t& lp) {
    asm("cvt.rn.bf16x2.f32 %0, %1, %2;" : "=r"(hp) : "f"(v1), "f"(v0));
    float h0 = __uint_as_float(hp << 16);
    float h1 = __uint_as_float(hp & 0xFFFF0000u);
    float l0 = v0 - h0, l1 = v1 - h1;
    asm("cvt.rn.bf16x2.f32 %0, %1, %2;" : "=r"(lp) : "f"(l1), "f"(l0));
}

// ---- single-launch task grouping + block map ----
__global__ void k_group(const int* __restrict__ task) {
    __shared__ int cnt[NT];
    __shared__ int fil[NT];
    int tid = threadIdx.x;
    if (tid < NT) cnt[tid] = 0;
    __syncthreads();
    for (int i = tid; i < BB; i += blockDim.x) atomicAdd(&cnt[task[i]], 1);
    __syncthreads();
    if (tid == 0) {
        int s = 0, nb = 0;
        for (int t = 0; t < NT; t++) {
            g_off[t] = s;
            fil[t] = s;
            int nby = (cnt[t] + 127) >> 7;
            for (int y = 0; y < nby; y++) g_blk[nb++] = t | (y << 8);
            s += cnt[t];
        }
        g_off[NT] = s;
        g_nblk = nb;
    }
    __syncthreads();
    for (int i = tid; i < BB; i += blockDim.x) {
        int t = task[i];
        int p = atomicAdd(&fil[t], 1);
        g_idx[p] = i;
    }
}

// ---- weight pre-pack: W[t][k][n] -> swizzled [n][k] tile images ----
// grid: (NB, NC, T), 256 threads. SPLIT: bf16 hi/lo (KCC=64); else fp32 (KCC=32).
template <bool SPLIT>
__global__ void k_pack(const float* __restrict__ W, int K, int N,
                       char* __restrict__ dst) {
    int tid = threadIdx.x;
    int nb = blockIdx.x, c = blockIdx.y, t = blockIdx.z;
    int NB = gridDim.x, NC = gridDim.y;
    size_t tilesz = SPLIT ? 65536 : 32768;
    char* tb = dst + (((size_t)t * NB + nb) * NC + c) * tilesz;
    int n = nb * 256 + tid;
    bool nv = n < N;
    const float* Wc = W + (size_t)t * K * N + n;
    int k0 = c * (SPLIT ? 64 : 32);
#pragma unroll
    for (int u = 0; u < 8; u++) {
        uint32_t off = SWZ((uint32_t)(tid * 128 + u * 16));
        if (SPLIT) {
            float v[8];
#pragma unroll
            for (int q = 0; q < 8; q++) {
                int k = k0 + u * 8 + q;
                v[q] = (nv && k < K) ? Wc[(size_t)k * N] : 0.f;
            }
            uint32_t h[4], l[4];
            bf16_split2(v[0], v[1], h[0], l[0]);
            bf16_split2(v[2], v[3], h[1], l[1]);
            bf16_split2(v[4], v[5], h[2], l[2]);
            bf16_split2(v[6], v[7], h[3], l[3]);
            *(uint4*)(tb + off)         = make_uint4(h[0], h[1], h[2], h[3]);
            *(uint4*)(tb + 32768 + off) = make_uint4(l[0], l[1], l[2], l[3]);
        } else {
            float v[4];
#pragma unroll
            for (int q = 0; q < 4; q++) {
                int k = k0 + u * 4 + q;
                v[q] = (nv && k < K) ? Wc[(size_t)k * N] : 0.f;
            }
            *(float4*)(tb + off) = make_float4(v[0], v[1], v[2], v[3]);
        }
    }
}

// ---------- tcgen05 helpers (arch-specific branch only) ----------
#if HAS_TC
__device__ __forceinline__ uint32_t smem_u32(const void* p) {
    uint32_t a;
    asm("{ .reg .u64 t; cvta.to.shared.u64 t, %1; cvt.u32.u64 %0, t; }" : "=r"(a) : "l"(p));
    return a;
}
__device__ __forceinline__ uint32_t elect1() {
    uint32_t r;
    asm volatile("{ .reg .pred p; elect.sync _|p, 0xFFFFFFFF; selp.b32 %0, 1, 0, p; }" : "=r"(r));
    return r;
}
__device__ __forceinline__ void mbar_init(uint32_t mbar, uint32_t cnt) {
    asm volatile("mbarrier.init.shared.b64 [%0], %1;" :: "r"(mbar), "r"(cnt) : "memory");
}
__device__ __forceinline__ void mbar_wait(uint32_t mbar, uint32_t parity) {
    asm volatile(
        "{\n\t.reg .pred P1;\n\t"
        "WAIT_%=:\n\t"
        "mbarrier.try_wait.parity.acquire.cta.shared::cta.b64 P1, [%0], %1, 0x989680;\n\t"
        "@P1 bra.uni DONE_%=;\n\t"
        "bra.uni WAIT_%=;\n\t"
        "DONE_%=:\n\t}"
        :: "r"(mbar), "r"(parity) : "memory");
}
__device__ __forceinline__ void mma_tf32(uint32_t d, uint64_t ad, uint64_t bd,
                                         uint32_t idesc, uint32_t en) {
    asm volatile(
        "{\n\t.reg .pred p;\n\t"
        "setp.ne.u32 p, %4, 0;\n\t"
        "tcgen05.mma.cta_group::1.kind::tf32 [%0], %1, %2, %3, {%5, %5, %5, %5}, p;\n\t}"
        :: "r"(d), "l"(ad), "l"(bd), "r"(idesc), "r"(en), "r"(0u) : "memory");
}
__device__ __forceinline__ void mma_f16(uint32_t d, uint64_t ad, uint64_t bd,
                                        uint32_t idesc, uint32_t en) {
    asm volatile(
        "{\n\t.reg .pred p;\n\t"
        "setp.ne.u32 p, %4, 0;\n\t"
        "tcgen05.mma.cta_group::1.kind::f16 [%0], %1, %2, %3, {%5, %5, %5, %5}, p;\n\t}"
        :: "r"(d), "l"(ad), "l"(bd), "r"(idesc), "r"(en), "r"(0u) : "memory");
}
__device__ __forceinline__ void tc_commit(uint32_t mbar) {
    asm volatile("tcgen05.commit.cta_group::1.mbarrier::arrive::one.shared::cluster.b64 [%0];"
                 :: "r"(mbar) : "memory");
}

#define TC_LD32(r, addr) \
    asm volatile( \
        "tcgen05.ld.sync.aligned.32x32b.x32.b32 " \
        "{%0, %1, %2, %3, %4, %5, %6, %7, " \
        " %8, %9, %10, %11, %12, %13, %14, %15, " \
        " %16, %17, %18, %19, %20, %21, %22, %23, " \
        " %24, %25, %26, %27, %28, %29, %30, %31}, [%32];" \
        : "=r"((r)[0]),  "=r"((r)[1]),  "=r"((r)[2]),  "=r"((r)[3]), \
          "=r"((r)[4]),  "=r"((r)[5]),  "=r"((r)[6]),  "=r"((r)[7]), \
          "=r"((r)[8]),  "=r"((r)[9]),  "=r"((r)[10]), "=r"((r)[11]), \
          "=r"((r)[12]), "=r"((r)[13]), "=r"((r)[14]), "=r"((r)[15]), \
          "=r"((r)[16]), "=r"((r)[17]), "=r"((r)[18]), "=r"((r)[19]), \
          "=r"((r)[20]), "=r"((r)[21]), "=r"((r)[22]), "=r"((r)[23]), \
          "=r"((r)[24]), "=r"((r)[25]), "=r"((r)[26]), "=r"((r)[27]), \
          "=r"((r)[28]), "=r"((r)[29]), "=r"((r)[30]), "=r"((r)[31]) \
        : "r"(addr))

static constexpr uint64_t DESC_BASE =
    (2ull << 61) | (1ull << 46) | (64ull << 32) | (1ull << 16);
__device__ __forceinline__ uint64_t mkdesc(uint32_t a) {
    return DESC_BASE | ((uint64_t)(a >> 4) & 0x3FFF);
}
#endif  // HAS_TC

// ---------- grouped GEMM: 128 x 256 tile per CTA ----------
#define NTILE 256
#define KC    32
#define KCB   64
#define SMEM_TMEM 0
#define SMEM_MB   16
#define SA_OFF    1024
#define STAGE_P   49152
#define STAGE_S   98304
#define SMEM_TOT_P (SA_OFF + 2 * STAGE_P)   //  99328
#define SMEM_TOT_S (SA_OFF + 2 * STAGE_S)   // 197632
#define EPI_PITCH 132
#define EPI_PITCH3 260

static constexpr uint32_t IDESC_TF32 =
    (1u << 4) | (2u << 7) | (2u << 10) | ((NTILE / 8) << 17) | ((128 / 16) << 24);
static constexpr uint32_t IDESC_BF16 =
    (1u << 4) | (1u << 7) | (1u << 10) | ((NTILE / 8) << 17) | ((128 / 16) << 24);

// EPI: 0 bias+relu, 2 bias+sigmoid+row-scatter, 3 fused reparam (enc4)
// SPLIT: bf16x3 emulated-fp32 (pre-packed hi/lo tiles)
template <bool GATHER, bool PERTASK, int EPI, bool SPLIT>
__global__ __launch_bounds__(256, SPLIT ? 1 : 2) void tgemm(
    const float* __restrict__ A, int lda,
    const float* __restrict__ W, const char* __restrict__ Wpk, int K, int N,
    const float* __restrict__ bias,
    float* __restrict__ C, int ldc,
    const float* __restrict__ eps, float* __restrict__ out2)
{
    extern __shared__ __align__(1024) char smem[];

    int t = 0, seg0 = 0, seg1 = BB, m0;
    if (PERTASK) {
        if ((int)blockIdx.y >= g_nblk) return;
        int bv = g_blk[blockIdx.y];
        t    = bv & 255;
        seg0 = g_off[t];
        seg1 = g_off[t + 1];
        m0   = seg0 + (bv >> 8) * 128;
    } else {
        m0 = blockIdx.y * 128;
    }
    int n0 = blockIdx.x * NTILE;

    const float* bp = bias + (PERTASK ? (size_t)t * N : 0);

    int tid = threadIdx.x;

#if HAS_TC
    // ================= tcgen05 path =================
    const int STAGE_B = SPLIT ? STAGE_S : STAGE_P;
    const int KCC     = SPLIT ? KCB : KC;
    uint32_t sb = smem_u32(smem);
    int wid = tid >> 5;
    int lid = tid & 31;

    if (wid == 0) {
        asm volatile("tcgen05.alloc.cta_group::1.sync.aligned.shared::cta.b32 [%0], %1;"
                     :: "r"(sb + SMEM_TMEM), "r"(256u) : "memory");
        asm volatile("tcgen05.relinquish_alloc_permit.cta_group::1.sync.aligned;");
    }
    if (tid == 0) { mbar_init(sb + SMEM_MB, 1); mbar_init(sb + SMEM_MB + 8, 1); }
    __syncthreads();
    uint32_t tmem;
    asm volatile("ld.shared.b32 %0, [%1];" : "=r"(tmem) : "r"(sb + SMEM_TMEM));

    int nch = (K + KCC - 1) / KCC;
    int ph[2] = {0, 0};

    int a_ke = (tid & 7) * (SPLIT ? 8 : 4);
    int a_mb = tid >> 3;
    const float* Ar[4];
#pragma unroll
    for (int p = 0; p < 4; p++) {
        int gs = m0 + p * 32 + a_mb;
        int src = (gs < seg1) ? (GATHER ? g_idx[gs] : gs)
                              : (GATHER ? g_idx[seg0] : seg0);
        Ar[p] = A + (size_t)src * lda + a_ke;
    }
    // packed-weight tile base for this (t, n-block)
    const size_t tilesz = SPLIT ? 65536 : 32768;
    const char* tb0 = Wpk + (((size_t)t * gridDim.x + blockIdx.x) * (size_t)nch) * tilesz;

    for (int c = 0; c < nch; c++) {
        int s = c & 1;
        if (c >= 2) { mbar_wait(sb + SMEM_MB + 8 * s, ph[s]); ph[s] ^= 1; }
        int k0 = c * KCC;
        char* sAh = smem + SA_OFF + s * STAGE_B;
        char* sAl = sAh + 16384;
        char* sBh = smem + SA_OFF + (SPLIT ? 32768 : 16384) + s * STAGE_B;

        if (SPLIT) {
            // A tile [m=128][k=64] bf16 hi/lo (on-the-fly split of activations)
#pragma unroll
            for (int p = 0; p < 4; p++) {
                int m = p * 32 + a_mb;
                float4 v0 = make_float4(0.f, 0.f, 0.f, 0.f);
                float4 v1 = make_float4(0.f, 0.f, 0.f, 0.f);
                if (k0 + a_ke < K)     v0 = *(const float4*)(Ar[p] + k0);
                if (k0 + a_ke + 4 < K) v1 = *(const float4*)(Ar[p] + k0 + 4);
                uint32_t h[4], l[4];
                bf16_split2(v0.x, v0.y, h[0], l[0]);
                bf16_split2(v0.z, v0.w, h[1], l[1]);
                bf16_split2(v1.x, v1.y, h[2], l[2]);
                bf16_split2(v1.z, v1.w, h[3], l[3]);
                uint32_t off = SWZ((uint32_t)(m * 128 + a_ke * 2));
                *(uint4*)(sAh + off) = make_uint4(h[0], h[1], h[2], h[3]);
                *(uint4*)(sAl + off) = make_uint4(l[0], l[1], l[2], l[3]);
            }
            // B tile: linear 64KB copy of pre-packed hi||lo image
            const char* tb = tb0 + (size_t)c * 65536;
#pragma unroll
            for (int q = 0; q < 16; q++) {
                uint4 v = *(const uint4*)(tb + (q * 256 + tid) * 16);
                *(uint4*)(sBh + (q * 256 + tid) * 16) = v;
            }
        } else {
            // A tile [m=128][k=32] fp32
#pragma unroll
            for (int p = 0; p < 4; p++) {
                int m = p * 32 + a_mb;
                float4 v = make_float4(0.f, 0.f, 0.f, 0.f);
                if (k0 + a_ke < K)
                    v = *(const float4*)(Ar[p] + k0);
                *(float4*)(sAh + SWZ((uint32_t)(m * KC + a_ke) * 4)) = v;
            }
            // B tile: linear 32KB copy of pre-packed fp32 image
            const char* tb = tb0 + (size_t)c * 32768;
#pragma unroll
            for (int q = 0; q < 8; q++) {
                uint4 v = *(const uint4*)(tb + (q * 256 + tid) * 16);
                *(uint4*)(sBh + (q * 256 + tid) * 16) = v;
            }
        }
        __syncthreads();

        if (wid == 0) {
            asm volatile("fence.proxy.async.shared::cta;" ::: "memory");
            if (elect1()) {
                uint64_t adh = mkdesc(smem_u32(sAh));
                uint64_t bdh = mkdesc(smem_u32(sBh));
                if (SPLIT) {
                    uint64_t adl = mkdesc(smem_u32(sAl));
                    uint64_t bdl = bdh + 2048;   // lo plane at +32768 bytes = +2048 units
#pragma unroll
                    for (int j = 0; j < 4; j++) {
                        mma_f16(tmem, adl + j * 2, bdh + j * 2, IDESC_BF16,
                                (c > 0 || j > 0) ? 1u : 0u);
                        mma_f16(tmem, adh + j * 2, bdl + j * 2, IDESC_BF16, 1u);
                        mma_f16(tmem, adh + j * 2, bdh + j * 2, IDESC_BF16, 1u);
                    }
                } else {
#pragma unroll
                    for (int j = 0; j < 4; j++)
                        mma_tf32(tmem, adh + j * 2, bdh + j * 2, IDESC_TF32,
                                 (c > 0 || j > 0) ? 1u : 0u);
                }
                tc_commit(sb + SMEM_MB + 8 * s);
            }
        }
    }

    int sl = (nch - 1) & 1;
    mbar_wait(sb + SMEM_MB + 8 * sl, ph[sl]);
    asm volatile("tcgen05.fence::after_thread_sync;" ::: "memory");
    __syncthreads();

    float* stg = (float*)(smem + SA_OFF);
    int rw = wid & 3;
    int cq = wid >> 2;

    if (EPI == 3) {
        // ---- fused reparameterization epilogue (enc4: N == 256 == 2*LAT) ----
#pragma unroll
        for (int half = 0; half < 2; half++)
#pragma unroll
            for (int i = 0; i < 2; i++) {
                uint32_t r[32];
                TC_LD32(r, tmem + half * 128 + cq * 64 + i * 32);
                asm volatile("tcgen05.wait::ld.sync.aligned;" ::: "memory");
                float* dst = stg + (rw * 32 + lid) * EPI_PITCH3 + half * 128 + cq * 64 + i * 32;
#pragma unroll
                for (int q = 0; q < 8; q++)
                    *(float4*)(dst + q * 4) = make_float4(
                        __uint_as_float(r[q * 4 + 0]), __uint_as_float(r[q * 4 + 1]),
                        __uint_as_float(r[q * 4 + 2]), __uint_as_float(r[q * 4 + 3]));
            }
        __syncthreads();

        int nb = lid * 4;
        float4 bmu = *(const float4*)(bp + nb);
        float4 bls = *(const float4*)(bp + 128 + nb);
        size_t mu_off = (size_t)BB * IN_DIM;
        size_t ls_off = mu_off + (size_t)BB * LAT;
#pragma unroll
        for (int rr = 0; rr < 16; rr++) {
            int r = wid * 16 + rr;
            int grow = m0 + r;
            if (grow < seg1) {
                float4 mu = *(float4*)(stg + r * EPI_PITCH3 + nb);
                float4 lv = *(float4*)(stg + r * EPI_PITCH3 + 128 + nb);
                mu.x += bmu.x; mu.y += bmu.y; mu.z += bmu.z; mu.w += bmu.w;
                lv.x += bls.x; lv.y += bls.y; lv.z += bls.z; lv.w += bls.w;
                int orig = g_idx[grow];
                float4 ep = *(const float4*)(eps + (size_t)orig * LAT + nb);
                float4 z;
                z.x = mu.x + expf(lv.x) * ep.x;
                z.y = mu.y + expf(lv.y) * ep.y;
                z.z = mu.z + expf(lv.z) * ep.z;
                z.w = mu.w + expf(lv.w) * ep.w;
                *(float4*)(out2 + mu_off + (size_t)orig * LAT + nb) = mu;
                *(float4*)(out2 + ls_off + (size_t)orig * LAT + nb) = lv;
                *(float4*)(C + (size_t)grow * ldc + nb) = z;
            }
        }
        __syncthreads();
    } else {
        // ---- staged transpose epilogue (coalesced STG) ----
        for (int half = 0; half < 2; half++) {
#pragma unroll
            for (int i = 0; i < 2; i++) {
                uint32_t r[32];
                TC_LD32(r, tmem + half * 128 + cq * 64 + i * 32);
                asm volatile("tcgen05.wait::ld.sync.aligned;" ::: "memory");
                float* dst = stg + (rw * 32 + lid) * EPI_PITCH + cq * 64 + i * 32;
#pragma unroll
                for (int q = 0; q < 8; q++)
                    *(float4*)(dst + q * 4) = make_float4(
                        __uint_as_float(r[q * 4 + 0]), __uint_as_float(r[q * 4 + 1]),
                        __uint_as_float(r[q * 4 + 2]), __uint_as_float(r[q * 4 + 3]));
            }
            __syncthreads();

            int nb = n0 + half * 128 + lid * 4;
            bool nv = nb < N;
            float4 bz = make_float4(0.f, 0.f, 0.f, 0.f);
            if (nv) bz = *(const float4*)(bp + nb);
#pragma unroll
            for (int rr = 0; rr < 16; rr++) {
                int r = wid * 16 + rr;
                int grow = m0 + r;
                if (grow < seg1 && nv) {
                    float4 v = *(float4*)(stg + r * EPI_PITCH + lid * 4);
                    v.x += bz.x; v.y += bz.y; v.z += bz.z; v.w += bz.w;
                    if (EPI == 0) {
                        v.x = fmaxf(v.x, 0.f); v.y = fmaxf(v.y, 0.f);
                        v.z = fmaxf(v.z, 0.f); v.w = fmaxf(v.w, 0.f);
                    } else if (EPI == 2) {
                        v.x = 1.f / (1.f + expf(-v.x));
                        v.y = 1.f / (1.f + expf(-v.y));
                        v.z = 1.f / (1.f + expf(-v.z));
                        v.w = 1.f / (1.f + expf(-v.w));
                    }
                    size_t orow = (EPI == 2) ? (size_t)g_idx[grow] : (size_t)grow;
                    *(float4*)(C + orow * ldc + nb) = v;
                }
            }
            __syncthreads();
        }
    }

    asm volatile("tcgen05.fence::before_thread_sync;" ::: "memory");
    __syncthreads();
    if (wid == 0)
        asm volatile("tcgen05.dealloc.cta_group::1.sync.aligned.b32 %0, %1;"
                     :: "r"(tmem), "r"(256u));

#else
    // ================= fp32 SIMT fallback (uses original W layout) =================
    const float* Wp = W + (PERTASK ? (size_t)t * K * N : 0);
    const int BK = 16;
    float* As = (float*)smem;
    float* Bs = (float*)(smem + BK * 128 * 4);

    int ar = tid & 127;
    int ak = (tid >> 7) * 8;
    int as_ = m0 + ar;
    bool avalid = (as_ < seg1);
    const float* Arow = nullptr;
    if (avalid) {
        int src = GATHER ? g_idx[as_] : as_;
        Arow = A + (size_t)src * lda;
    }
    int bk = tid >> 4;
    int bn = (tid & 15) * 8;
    int ty = tid >> 4;
    int tx = tid & 15;

    float muv[8][8];

    for (int half = 0; half < 2; half++) {
        int n0h = n0 + half * 128;
        if (n0h >= N) break;

        float acc[8][8];
#pragma unroll
        for (int i = 0; i < 8; i++)
#pragma unroll
            for (int j = 0; j < 8; j++) acc[i][j] = 0.f;

        for (int k0 = 0; k0 < K; k0 += BK) {
            if (avalid) {
                float4 a0 = *(const float4*)(Arow + k0 + ak);
                float4 a1 = *(const float4*)(Arow + k0 + ak + 4);
                As[(ak + 0) * 128 + ar] = a0.x; As[(ak + 1) * 128 + ar] = a0.y;
                As[(ak + 2) * 128 + ar] = a0.z; As[(ak + 3) * 128 + ar] = a0.w;
                As[(ak + 4) * 128 + ar] = a1.x; As[(ak + 5) * 128 + ar] = a1.y;
                As[(ak + 6) * 128 + ar] = a1.z; As[(ak + 7) * 128 + ar] = a1.w;
            } else {
#pragma unroll
                for (int q = 0; q < 8; q++) As[(ak + q) * 128 + ar] = 0.f;
            }
            {
                const float* Wrow = Wp + (size_t)(k0 + bk) * N + n0h + bn;
                if (n0h + bn + 7 < N) {
                    float4 b0 = *(const float4*)(Wrow);
                    float4 b1 = *(const float4*)(Wrow + 4);
                    Bs[bk * 128 + bn + 0] = b0.x; Bs[bk * 128 + bn + 1] = b0.y;
                    Bs[bk * 128 + bn + 2] = b0.z; Bs[bk * 128 + bn + 3] = b0.w;
                    Bs[bk * 128 + bn + 4] = b1.x; Bs[bk * 128 + bn + 5] = b1.y;
                    Bs[bk * 128 + bn + 6] = b1.z; Bs[bk * 128 + bn + 7] = b1.w;
                } else {
#pragma unroll
                    for (int q = 0; q < 8; q++)
                        Bs[bk * 128 + bn + q] = (n0h + bn + q < N) ? Wrow[q] : 0.f;
                }
            }
            __syncthreads();
#pragma unroll
            for (int k = 0; k < BK; k++) {
                float a[8], b[8];
                *(float4*)&a[0] = *(const float4*)&As[k * 128 + ty * 4];
                *(float4*)&a[4] = *(const float4*)&As[k * 128 + 64 + ty * 4];
                *(float4*)&b[0] = *(const float4*)&Bs[k * 128 + tx * 4];
                *(float4*)&b[4] = *(const float4*)&Bs[k * 128 + 64 + tx * 4];
#pragma unroll
                for (int i = 0; i < 8; i++)
#pragma unroll
                    for (int j = 0; j < 8; j++)
                        acc[i][j] = fmaf(a[i], b[j], acc[i][j]);
            }
            __syncthreads();
        }

#pragma unroll
        for (int i = 0; i < 8; i++) {
            int s = m0 + ((i < 4) ? (ty * 4 + i) : (64 + ty * 4 + i - 4));
            if (s >= seg1) continue;
#pragma unroll
            for (int j = 0; j < 8; j++) {
                int n = n0h + ((j < 4) ? (tx * 4 + j) : (64 + tx * 4 + j - 4));
                if (n >= N) continue;
                float v = acc[i][j] + bp[n];
                if (EPI == 3) {
                    int orig = g_idx[s];
                    int nl = n & 127;
                    size_t mu_off = (size_t)BB * IN_DIM;
                    size_t ls_off = mu_off + (size_t)BB * LAT;
                    if (half == 0) {
                        muv[i][j] = v;
                        out2[mu_off + (size_t)orig * LAT + nl] = v;
                    } else {
                        out2[ls_off + (size_t)orig * LAT + nl] = v;
                        float z = muv[i][j] + expf(v) * eps[(size_t)orig * LAT + nl];
                        C[(size_t)s * ldc + nl] = z;
                    }
                } else {
                    if (EPI == 0)      v = fmaxf(v, 0.f);
                    else if (EPI == 2) v = 1.f / (1.f + expf(-v));
                    size_t orow = (EPI == 2) ? (size_t)g_idx[s] : (size_t)s;
                    C[orow * ldc + n] = v;
                }
            }
        }
        __syncthreads();
    }
#endif
}

extern "C" void kernel_launch(void* const* d_in, const int* in_sizes, int n_in,
                              void* d_out, int out_size) {
    const float* x    = (const float*)d_in[0];
    const int*   task = (const int*)  d_in[1];
    const float* eps  = (const float*)d_in[2];
    const float* eW1  = (const float*)d_in[3];
    const float* eb1  = (const float*)d_in[4];
    const float* eW2  = (const float*)d_in[5];
    const float* eb2  = (const float*)d_in[6];
    const float* eW3  = (const float*)d_in[7];
    const float* eb3  = (const float*)d_in[8];
    const float* eW4  = (const float*)d_in[9];
    const float* eb4  = (const float*)d_in[10];
    const float* dWs1 = (const float*)d_in[11];
    const float* dbs1 = (const float*)d_in[12];
    const float* dWs2 = (const float*)d_in[13];
    const float* dbs2 = (const float*)d_in[14];
    const float* dWh1 = (const float*)d_in[15];
    const float* dbh1 = (const float*)d_in[16];
    const float* dWh2 = (const float*)d_in[17];
    const float* dbh2 = (const float*)d_in[18];
    float* out = (float*)d_out;

    float *bufA, *bufB;
    cudaGetSymbolAddress((void**)&bufA, g_bufA);
    cudaGetSymbolAddress((void**)&bufB, g_bufB);
    char *pE1, *pE2, *pE3, *pE4, *pD1, *pD2, *pD3, *pD4;
    cudaGetSymbolAddress((void**)&pE1, g_pE1);
    cudaGetSymbolAddress((void**)&pE2, g_pE2);
    cudaGetSymbolAddress((void**)&pE3, g_pE3);
    cudaGetSymbolAddress((void**)&pE4, g_pE4);
    cudaGetSymbolAddress((void**)&pD1, g_pD1);
    cudaGetSymbolAddress((void**)&pD2, g_pD2);
    cudaGetSymbolAddress((void**)&pD3, g_pD3);
    cudaGetSymbolAddress((void**)&pD4, g_pD4);

    cudaFuncSetAttribute(tgemm<true,  true,  0, true>,  cudaFuncAttributeMaxDynamicSharedMemorySize, SMEM_TOT_S);
    cudaFuncSetAttribute(tgemm<false, true,  0, true>,  cudaFuncAttributeMaxDynamicSharedMemorySize, SMEM_TOT_S);
    cudaFuncSetAttribute(tgemm<false, true,  3, true>,  cudaFuncAttributeMaxDynamicSharedMemorySize, SMEM_TOT_S);
    cudaFuncSetAttribute(tgemm<false, false, 0, false>, cudaFuncAttributeMaxDynamicSharedMemorySize, SMEM_TOT_P);
    cudaFuncSetAttribute(tgemm<false, true,  0, false>, cudaFuncAttributeMaxDynamicSharedMemorySize, SMEM_TOT_P);
    cudaFuncSetAttribute(tgemm<false, true,  2, false>, cudaFuncAttributeMaxDynamicSharedMemorySize, SMEM_TOT_P);

    // grouping + weight pre-pack (per launch; deterministic)
    k_group<<<1, 256>>>(task);
    k_pack<true ><<<dim3(4, 13, NT), 256>>>(eW1,  IN_DIM, HID,   pE1);
    k_pack<true ><<<dim3(4, 16, NT), 256>>>(eW2,  HID,    HID,   pE2);
    k_pack<true ><<<dim3(4, 16, NT), 256>>>(eW3,  HID,    HID,   pE3);
    k_pack<true ><<<dim3(1, 16, NT), 256>>>(eW4,  HID,    2*LAT, pE4);
    k_pack<false><<<dim3(4, 4,  1 ), 256>>>(dWs1, LAT,    HID,   pD1);
    k_pack<false><<<dim3(4, 32, 1 ), 256>>>(dWs2, HID,    HID,   pD2);
    k_pack<false><<<dim3(4, 32, NT), 256>>>(dWh1, HID,    HID,   pD3);
    k_pack<false><<<dim3(4, 32, NT), 256>>>(dWh2, HID,    IN_DIM, pD4);

    // encoder — bf16x3 with pre-packed B
    tgemm<true,  true, 0, true><<<dim3(4, YMAX), 256, SMEM_TOT_S>>>(x,    IN_DIM, eW1, pE1, IN_DIM, HID,   eb1, bufA, HID, nullptr, nullptr);
    tgemm<false, true, 0, true><<<dim3(4, YMAX), 256, SMEM_TOT_S>>>(bufA, HID,    eW2, pE2, HID,    HID,   eb2, bufB, HID, nullptr, nullptr);
    tgemm<false, true, 0, true><<<dim3(4, YMAX), 256, SMEM_TOT_S>>>(bufB, HID,    eW3, pE3, HID,    HID,   eb3, bufA, HID, nullptr, nullptr);
    tgemm<false, true, 3, true><<<dim3(1, YMAX), 256, SMEM_TOT_S>>>(bufA, HID,    eW4, pE4, HID,    2*LAT, eb4, bufB, LAT, eps, out);

    // decoder — plain TF32 with pre-packed B
    tgemm<false, false, 0, false><<<dim3(4, 64),   256, SMEM_TOT_P>>>(bufB, LAT, dWs1, pD1, LAT, HID,    dbs1, bufA, HID, nullptr, nullptr);
    tgemm<false, false, 0, false><<<dim3(4, 64),   256, SMEM_TOT_P>>>(bufA, HID, dWs2, pD2, HID, HID,    dbs2, bufB, HID, nullptr, nullptr);
    tgemm<false, true,  0, false><<<dim3(4, YMAX), 256, SMEM_TOT_P>>>(bufB, HID, dWh1, pD3, HID, HID,    dbh1, bufA, HID, nullptr, nullptr);
    tgemm<false, true,  2, false><<<dim3(4, YMAX), 256, SMEM_TOT_P>>>(bufA, HID, dWh2, pD4, HID, IN_DIM, dbh2, out, IN_DIM, nullptr, nullptr);
}

// round 15
// speedup vs baseline: 5.2235x; 1.0743x over previous
#include <cuda_runtime.h>
#include <cuda_bf16.h>
#include <math.h>
#include <cstdint>

#define BB      8192
#define IN_DIM  784
#define HID     1024
#define LAT     128
#define NT      10
#define YMAX    74   // tight bound on sum ceil(cnt_t/128): 64 + NT partials

#if defined(__CUDA_ARCH__) && (__CUDA_ARCH__ == 1030) && \
    (defined(__CUDA_ARCH_FEAT_SM103_ALL) || \
     (defined(__CUDA_ARCH_SPECIFIC__) && (__CUDA_ARCH_SPECIFIC__ >= 1030)))
#define HAS_TC 1
#else
#define HAS_TC 0
#endif

// ---- scratch (static device globals; no allocation) ----
__device__ float g_bufA[BB * HID];
__device__ float g_bufB[BB * HID];
__device__ int   g_idx[BB];
__device__ int   g_off[NT + 1];
__device__ int   g_blk[YMAX + 8];   // packed: task | (yblock<<8)
__device__ int   g_nblk;

// ---- pre-packed weight tiles (byte-exact SMEM tile images) ----
// encoder (bf16 hi||lo, SW128 swizzled, 64KB/tile):
__device__ char g_pE1[(size_t)4 * 13 * 10 * 65536];   // 33.25 MB
__device__ char g_pE2[(size_t)4 * 16 * 10 * 65536];   // 40 MB
__device__ char g_pE3[(size_t)4 * 16 * 10 * 65536];   // 40 MB
__device__ char g_pE4[(size_t)1 * 16 * 10 * 65536];   // 10 MB
// decoder (fp32, SW128 swizzled, 32KB/tile):
__device__ char g_pD1[(size_t)4 * 4  * 1  * 32768];   // 0.5 MB
__device__ char g_pD2[(size_t)4 * 32 * 1  * 32768];   // 4 MB
__device__ char g_pD3[(size_t)4 * 32 * 10 * 32768];   // 40 MB
__device__ char g_pD4[(size_t)4 * 32 * 10 * 32768];   // 40 MB

#define SWZ(o) ((o) ^ (((o) >> 3) & 0x70))

// pack (v0, v1) -> bf16x2 hi pair + residual lo pair (v0 at lower address)
__device__ __forceinline__ void bf16_split2(float v0, float v1,
                                            uint32_t& hp, uint32_t& lp) {
    asm("cvt.rn.bf16x2.f32 %0, %1, %2;" : "=r"(hp) : "f"(v1), "f"(v0));
    float h0 = __uint_as_float(hp << 16);
    float h1 = __uint_as_float(hp & 0xFFFF0000u);
    float l0 = v0 - h0, l1 = v1 - h1;
    asm("cvt.rn.bf16x2.f32 %0, %1, %2;" : "=r"(lp) : "f"(l1), "f"(l0));
}

// ---- single-launch task grouping + block map ----
__global__ void k_group(const int* __restrict__ task) {
    __shared__ int cnt[NT];
    __shared__ int fil[NT];
    int tid = threadIdx.x;
    if (tid < NT) cnt[tid] = 0;
    __syncthreads();
    for (int i = tid; i < BB; i += blockDim.x) atomicAdd(&cnt[task[i]], 1);
    __syncthreads();
    if (tid == 0) {
        int s = 0, nb = 0;
        for (int t = 0; t < NT; t++) {
            g_off[t] = s;
            fil[t] = s;
            int nby = (cnt[t] + 127) >> 7;
            for (int y = 0; y < nby; y++) g_blk[nb++] = t | (y << 8);
            s += cnt[t];
        }
        g_off[NT] = s;
        g_nblk = nb;
    }
    __syncthreads();
    for (int i = tid; i < BB; i += blockDim.x) {
        int t = task[i];
        int p = atomicAdd(&fil[t], 1);
        g_idx[p] = i;
    }
}

// ---- weight pre-pack: W[t][k][n] -> swizzled [n][k] tile images ----
// Stages the tile in SMEM so the final GMEM writes are a linear coalesced
// stream (the direct swizzled STG pattern was 128B-strided -> 1/8 write
// efficiency -> packs ran at 2 TB/s; this is the round-15 fix).
template <bool SPLIT>
__global__ void k_pack(const float* __restrict__ W, int K, int N,
                       char* __restrict__ dst) {
    extern __shared__ char sm[];
    int tid = threadIdx.x;
    int nb = blockIdx.x, c = blockIdx.y, t = blockIdx.z;
    int NB = gridDim.x, NC = gridDim.y;
    const int tilesz = SPLIT ? 65536 : 32768;
    char* tb = dst + (((size_t)t * NB + nb) * NC + c) * (size_t)tilesz;
    int n = nb * 256 + tid;
    bool nv = n < N;
    const float* Wc = W + (size_t)t * K * N + n;
    int k0 = c * (SPLIT ? 64 : 32);
#pragma unroll
    for (int u = 0; u < 8; u++) {
        uint32_t off = SWZ((uint32_t)(tid * 128 + u * 16));
        if (SPLIT) {
            float v[8];
#pragma unroll
            for (int q = 0; q < 8; q++) {
                int k = k0 + u * 8 + q;
                v[q] = (nv && k < K) ? Wc[(size_t)k * N] : 0.f;
            }
            uint32_t h[4], l[4];
            bf16_split2(v[0], v[1], h[0], l[0]);
            bf16_split2(v[2], v[3], h[1], l[1]);
            bf16_split2(v[4], v[5], h[2], l[2]);
            bf16_split2(v[6], v[7], h[3], l[3]);
            *(uint4*)(sm + off)         = make_uint4(h[0], h[1], h[2], h[3]);
            *(uint4*)(sm + 32768 + off) = make_uint4(l[0], l[1], l[2], l[3]);
        } else {
            float v[4];
#pragma unroll
            for (int q = 0; q < 4; q++) {
                int k = k0 + u * 4 + q;
                v[q] = (nv && k < K) ? Wc[(size_t)k * N] : 0.f;
            }
            *(float4*)(sm + off) = make_float4(v[0], v[1], v[2], v[3]);
        }
    }
    __syncthreads();
    // linear coalesced copy SMEM -> GMEM
    const int NQ = tilesz / 4096;   // 16 (split) / 8 (plain)
#pragma unroll
    for (int q = 0; q < NQ; q++) {
        uint4 v = *(const uint4*)(sm + (q * 256 + tid) * 16);
        *(uint4*)(tb + (q * 256 + tid) * 16) = v;
    }
}

// ---------- tcgen05 helpers (arch-specific branch only) ----------
#if HAS_TC
__device__ __forceinline__ uint32_t smem_u32(const void* p) {
    uint32_t a;
    asm("{ .reg .u64 t; cvta.to.shared.u64 t, %1; cvt.u32.u64 %0, t; }" : "=r"(a) : "l"(p));
    return a;
}
__device__ __forceinline__ uint32_t elect1() {
    uint32_t r;
    asm volatile("{ .reg .pred p; elect.sync _|p, 0xFFFFFFFF; selp.b32 %0, 1, 0, p; }" : "=r"(r));
    return r;
}
__device__ __forceinline__ void mbar_init(uint32_t mbar, uint32_t cnt) {
    asm volatile("mbarrier.init.shared.b64 [%0], %1;" :: "r"(mbar), "r"(cnt) : "memory");
}
__device__ __forceinline__ void mbar_wait(uint32_t mbar, uint32_t parity) {
    asm volatile(
        "{\n\t.reg .pred P1;\n\t"
        "WAIT_%=:\n\t"
        "mbarrier.try_wait.parity.acquire.cta.shared::cta.b64 P1, [%0], %1, 0x989680;\n\t"
        "@P1 bra.uni DONE_%=;\n\t"
        "bra.uni WAIT_%=;\n\t"
        "DONE_%=:\n\t}"
        :: "r"(mbar), "r"(parity) : "memory");
}
__device__ __forceinline__ void mma_tf32(uint32_t d, uint64_t ad, uint64_t bd,
                                         uint32_t idesc, uint32_t en) {
    asm volatile(
        "{\n\t.reg .pred p;\n\t"
        "setp.ne.u32 p, %4, 0;\n\t"
        "tcgen05.mma.cta_group::1.kind::tf32 [%0], %1, %2, %3, {%5, %5, %5, %5}, p;\n\t}"
        :: "r"(d), "l"(ad), "l"(bd), "r"(idesc), "r"(en), "r"(0u) : "memory");
}
__device__ __forceinline__ void mma_f16(uint32_t d, uint64_t ad, uint64_t bd,
                                        uint32_t idesc, uint32_t en) {
    asm volatile(
        "{\n\t.reg .pred p;\n\t"
        "setp.ne.u32 p, %4, 0;\n\t"
        "tcgen05.mma.cta_group::1.kind::f16 [%0], %1, %2, %3, {%5, %5, %5, %5}, p;\n\t}"
        :: "r"(d), "l"(ad), "l"(bd), "r"(idesc), "r"(en), "r"(0u) : "memory");
}
__device__ __forceinline__ void tc_commit(uint32_t mbar) {
    asm volatile("tcgen05.commit.cta_group::1.mbarrier::arrive::one.shared::cluster.b64 [%0];"
                 :: "r"(mbar) : "memory");
}

#define TC_LD32(r, addr) \
    asm volatile( \
        "tcgen05.ld.sync.aligned.32x32b.x32.b32 " \
        "{%0, %1, %2, %3, %4, %5, %6, %7, " \
        " %8, %9, %10, %11, %12, %13, %14, %15, " \
        " %16, %17, %18, %19, %20, %21, %22, %23, " \
        " %24, %25, %26, %27, %28, %29, %30, %31}, [%32];" \
        : "=r"((r)[0]),  "=r"((r)[1]),  "=r"((r)[2]),  "=r"((r)[3]), \
          "=r"((r)[4]),  "=r"((r)[5]),  "=r"((r)[6]),  "=r"((r)[7]), \
          "=r"((r)[8]),  "=r"((r)[9]),  "=r"((r)[10]), "=r"((r)[11]), \
          "=r"((r)[12]), "=r"((r)[13]), "=r"((r)[14]), "=r"((r)[15]), \
          "=r"((r)[16]), "=r"((r)[17]), "=r"((r)[18]), "=r"((r)[19]), \
          "=r"((r)[20]), "=r"((r)[21]), "=r"((r)[22]), "=r"((r)[23]), \
          "=r"((r)[24]), "=r"((r)[25]), "=r"((r)[26]), "=r"((r)[27]), \
          "=r"((r)[28]), "=r"((r)[29]), "=r"((r)[30]), "=r"((r)[31]) \
        : "r"(addr))

static constexpr uint64_t DESC_BASE =
    (2ull << 61) | (1ull << 46) | (64ull << 32) | (1ull << 16);
__device__ __forceinline__ uint64_t mkdesc(uint32_t a) {
    return DESC_BASE | ((uint64_t)(a >> 4) & 0x3FFF);
}
#endif  // HAS_TC

// ---------- grouped GEMM: 128 x 256 tile per CTA ----------
#define NTILE 256
#define KC    32
#define KCB   64
#define SMEM_TMEM 0
#define SMEM_MB   16
#define SA_OFF    1024
#define STAGE_P   49152
#define STAGE_S   98304
#define SMEM_TOT_P (SA_OFF + 2 * STAGE_P)   //  99328
#define SMEM_TOT_S (SA_OFF + 2 * STAGE_S)   // 197632
#define EPI_PITCH 132
#define EPI_PITCH3 260

static constexpr uint32_t IDESC_TF32 =
    (1u << 4) | (2u << 7) | (2u << 10) | ((NTILE / 8) << 17) | ((128 / 16) << 24);
static constexpr uint32_t IDESC_BF16 =
    (1u << 4) | (1u << 7) | (1u << 10) | ((NTILE / 8) << 17) | ((128 / 16) << 24);

// EPI: 0 bias+relu, 2 bias+sigmoid+row-scatter, 3 fused reparam (enc4)
// SPLIT: bf16x3 emulated-fp32 (pre-packed hi/lo tiles)
template <bool GATHER, bool PERTASK, int EPI, bool SPLIT>
__global__ __launch_bounds__(256, SPLIT ? 1 : 2) void tgemm(
    const float* __restrict__ A, int lda,
    const float* __restrict__ W, const char* __restrict__ Wpk, int K, int N,
    const float* __restrict__ bias,
    float* __restrict__ C, int ldc,
    const float* __restrict__ eps, float* __restrict__ out2)
{
    extern __shared__ __align__(1024) char smem[];

    int t = 0, seg0 = 0, seg1 = BB, m0;
    if (PERTASK) {
        if ((int)blockIdx.y >= g_nblk) return;
        int bv = g_blk[blockIdx.y];
        t    = bv & 255;
        seg0 = g_off[t];
        seg1 = g_off[t + 1];
        m0   = seg0 + (bv >> 8) * 128;
    } else {
        m0 = blockIdx.y * 128;
    }
    int n0 = blockIdx.x * NTILE;

    const float* bp = bias + (PERTASK ? (size_t)t * N : 0);

    int tid = threadIdx.x;

#if HAS_TC
    // ================= tcgen05 path =================
    const int STAGE_B = SPLIT ? STAGE_S : STAGE_P;
    const int KCC     = SPLIT ? KCB : KC;
    uint32_t sb = smem_u32(smem);
    int wid = tid >> 5;
    int lid = tid & 31;

    if (wid == 0) {
        asm volatile("tcgen05.alloc.cta_group::1.sync.aligned.shared::cta.b32 [%0], %1;"
                     :: "r"(sb + SMEM_TMEM), "r"(256u) : "memory");
        asm volatile("tcgen05.relinquish_alloc_permit.cta_group::1.sync.aligned;");
    }
    if (tid == 0) { mbar_init(sb + SMEM_MB, 1); mbar_init(sb + SMEM_MB + 8, 1); }
    __syncthreads();
    uint32_t tmem;
    asm volatile("ld.shared.b32 %0, [%1];" : "=r"(tmem) : "r"(sb + SMEM_TMEM));

    int nch = (K + KCC - 1) / KCC;
    int ph[2] = {0, 0};

    int a_ke = (tid & 7) * (SPLIT ? 8 : 4);
    int a_mb = tid >> 3;
    const float* Ar[4];
#pragma unroll
    for (int p = 0; p < 4; p++) {
        int gs = m0 + p * 32 + a_mb;
        int src = (gs < seg1) ? (GATHER ? g_idx[gs] : gs)
                              : (GATHER ? g_idx[seg0] : seg0);
        Ar[p] = A + (size_t)src * lda + a_ke;
    }
    // packed-weight tile base for this (t, n-block)
    const size_t tilesz = SPLIT ? 65536 : 32768;
    const char* tb0 = Wpk + (((size_t)t * gridDim.x + blockIdx.x) * (size_t)nch) * tilesz;

    for (int c = 0; c < nch; c++) {
        int s = c & 1;
        if (c >= 2) { mbar_wait(sb + SMEM_MB + 8 * s, ph[s]); ph[s] ^= 1; }
        int k0 = c * KCC;
        char* sAh = smem + SA_OFF + s * STAGE_B;
        char* sAl = sAh + 16384;
        char* sBh = smem + SA_OFF + (SPLIT ? 32768 : 16384) + s * STAGE_B;

        if (SPLIT) {
            // A tile [m=128][k=64] bf16 hi/lo (on-the-fly split of activations)
#pragma unroll
            for (int p = 0; p < 4; p++) {
                int m = p * 32 + a_mb;
                float4 v0 = make_float4(0.f, 0.f, 0.f, 0.f);
                float4 v1 = make_float4(0.f, 0.f, 0.f, 0.f);
                if (k0 + a_ke < K)     v0 = *(const float4*)(Ar[p] + k0);
                if (k0 + a_ke + 4 < K) v1 = *(const float4*)(Ar[p] + k0 + 4);
                uint32_t h[4], l[4];
                bf16_split2(v0.x, v0.y, h[0], l[0]);
                bf16_split2(v0.z, v0.w, h[1], l[1]);
                bf16_split2(v1.x, v1.y, h[2], l[2]);
                bf16_split2(v1.z, v1.w, h[3], l[3]);
                uint32_t off = SWZ((uint32_t)(m * 128 + a_ke * 2));
                *(uint4*)(sAh + off) = make_uint4(h[0], h[1], h[2], h[3]);
                *(uint4*)(sAl + off) = make_uint4(l[0], l[1], l[2], l[3]);
            }
            // B tile: linear 64KB copy of pre-packed hi||lo image
            const char* tb = tb0 + (size_t)c * 65536;
#pragma unroll
            for (int q = 0; q < 16; q++) {
                uint4 v = *(const uint4*)(tb + (q * 256 + tid) * 16);
                *(uint4*)(sBh + (q * 256 + tid) * 16) = v;
            }
        } else {
            // A tile [m=128][k=32] fp32
#pragma unroll
            for (int p = 0; p < 4; p++) {
                int m = p * 32 + a_mb;
                float4 v = make_float4(0.f, 0.f, 0.f, 0.f);
                if (k0 + a_ke < K)
                    v = *(const float4*)(Ar[p] + k0);
                *(float4*)(sAh + SWZ((uint32_t)(m * KC + a_ke) * 4)) = v;
            }
            // B tile: linear 32KB copy of pre-packed fp32 image
            const char* tb = tb0 + (size_t)c * 32768;
#pragma unroll
            for (int q = 0; q < 8; q++) {
                uint4 v = *(const uint4*)(tb + (q * 256 + tid) * 16);
                *(uint4*)(sBh + (q * 256 + tid) * 16) = v;
            }
        }
        __syncthreads();

        if (wid == 0) {
            asm volatile("fence.proxy.async.shared::cta;" ::: "memory");
            if (elect1()) {
                uint64_t adh = mkdesc(smem_u32(sAh));
                uint64_t bdh = mkdesc(smem_u32(sBh));
                if (SPLIT) {
                    uint64_t adl = mkdesc(smem_u32(sAl));
                    uint64_t bdl = bdh + 2048;   // lo plane at +32768 bytes = +2048 units
#pragma unroll
                    for (int j = 0; j < 4; j++) {
                        mma_f16(tmem, adl + j * 2, bdh + j * 2, IDESC_BF16,
                                (c > 0 || j > 0) ? 1u : 0u);
                        mma_f16(tmem, adh + j * 2, bdl + j * 2, IDESC_BF16, 1u);
                        mma_f16(tmem, adh + j * 2, bdh + j * 2, IDESC_BF16, 1u);
                    }
                } else {
#pragma unroll
                    for (int j = 0; j < 4; j++)
                        mma_tf32(tmem, adh + j * 2, bdh + j * 2, IDESC_TF32,
                                 (c > 0 || j > 0) ? 1u : 0u);
                }
                tc_commit(sb + SMEM_MB + 8 * s);
            }
        }
    }

    int sl = (nch - 1) & 1;
    mbar_wait(sb + SMEM_MB + 8 * sl, ph[sl]);
    asm volatile("tcgen05.fence::after_thread_sync;" ::: "memory");
    __syncthreads();

    float* stg = (float*)(smem + SA_OFF);
    int rw = wid & 3;
    int cq = wid >> 2;

    if (EPI == 3) {
        // ---- fused reparameterization epilogue (enc4: N == 256 == 2*LAT) ----
#pragma unroll
        for (int half = 0; half < 2; half++)
#pragma unroll
            for (int i = 0; i < 2; i++) {
                uint32_t r[32];
                TC_LD32(r, tmem + half * 128 + cq * 64 + i * 32);
                asm volatile("tcgen05.wait::ld.sync.aligned;" ::: "memory");
                float* dst = stg + (rw * 32 + lid) * EPI_PITCH3 + half * 128 + cq * 64 + i * 32;
#pragma unroll
                for (int q = 0; q < 8; q++)
                    *(float4*)(dst + q * 4) = make_float4(
                        __uint_as_float(r[q * 4 + 0]), __uint_as_float(r[q * 4 + 1]),
                        __uint_as_float(r[q * 4 + 2]), __uint_as_float(r[q * 4 + 3]));
            }
        __syncthreads();

        int nb = lid * 4;
        float4 bmu = *(const float4*)(bp + nb);
        float4 bls = *(const float4*)(bp + 128 + nb);
        size_t mu_off = (size_t)BB * IN_DIM;
        size_t ls_off = mu_off + (size_t)BB * LAT;
#pragma unroll
        for (int rr = 0; rr < 16; rr++) {
            int r = wid * 16 + rr;
            int grow = m0 + r;
            if (grow < seg1) {
                float4 mu = *(float4*)(stg + r * EPI_PITCH3 + nb);
                float4 lv = *(float4*)(stg + r * EPI_PITCH3 + 128 + nb);
                mu.x += bmu.x; mu.y += bmu.y; mu.z += bmu.z; mu.w += bmu.w;
                lv.x += bls.x; lv.y += bls.y; lv.z += bls.z; lv.w += bls.w;
                int orig = g_idx[grow];
                float4 ep = *(const float4*)(eps + (size_t)orig * LAT + nb);
                float4 z;
                z.x = mu.x + expf(lv.x) * ep.x;
                z.y = mu.y + expf(lv.y) * ep.y;
                z.z = mu.z + expf(lv.z) * ep.z;
                z.w = mu.w + expf(lv.w) * ep.w;
                *(float4*)(out2 + mu_off + (size_t)orig * LAT + nb) = mu;
                *(float4*)(out2 + ls_off + (size_t)orig * LAT + nb) = lv;
                *(float4*)(C + (size_t)grow * ldc + nb) = z;
            }
        }
        __syncthreads();
    } else {
        // ---- staged transpose epilogue (coalesced STG) ----
        for (int half = 0; half < 2; half++) {
#pragma unroll
            for (int i = 0; i < 2; i++) {
                uint32_t r[32];
                TC_LD32(r, tmem + half * 128 + cq * 64 + i * 32);
                asm volatile("tcgen05.wait::ld.sync.aligned;" ::: "memory");
                float* dst = stg + (rw * 32 + lid) * EPI_PITCH + cq * 64 + i * 32;
#pragma unroll
                for (int q = 0; q < 8; q++)
                    *(float4*)(dst + q * 4) = make_float4(
                        __uint_as_float(r[q * 4 + 0]), __uint_as_float(r[q * 4 + 1]),
                        __uint_as_float(r[q * 4 + 2]), __uint_as_float(r[q * 4 + 3]));
            }
            __syncthreads();

            int nb = n0 + half * 128 + lid * 4;
            bool nv = nb < N;
            float4 bz = make_float4(0.f, 0.f, 0.f, 0.f);
            if (nv) bz = *(const float4*)(bp + nb);
#pragma unroll
            for (int rr = 0; rr < 16; rr++) {
                int r = wid * 16 + rr;
                int grow = m0 + r;
                if (grow < seg1 && nv) {
                    float4 v = *(float4*)(stg + r * EPI_PITCH + lid * 4);
                    v.x += bz.x; v.y += bz.y; v.z += bz.z; v.w += bz.w;
                    if (EPI == 0) {
                        v.x = fmaxf(v.x, 0.f); v.y = fmaxf(v.y, 0.f);
                        v.z = fmaxf(v.z, 0.f); v.w = fmaxf(v.w, 0.f);
                    } else if (EPI == 2) {
                        v.x = 1.f / (1.f + expf(-v.x));
                        v.y = 1.f / (1.f + expf(-v.y));
                        v.z = 1.f / (1.f + expf(-v.z));
                        v.w = 1.f / (1.f + expf(-v.w));
                    }
                    size_t orow = (EPI == 2) ? (size_t)g_idx[grow] : (size_t)grow;
                    *(float4*)(C + orow * ldc + nb) = v;
                }
            }
            __syncthreads();
        }
    }

    asm volatile("tcgen05.fence::before_thread_sync;" ::: "memory");
    __syncthreads();
    if (wid == 0)
        asm volatile("tcgen05.dealloc.cta_group::1.sync.aligned.b32 %0, %1;"
                     :: "r"(tmem), "r"(256u));

#else
    // ================= fp32 SIMT fallback (uses original W layout) =================
    const float* Wp = W + (PERTASK ? (size_t)t * K * N : 0);
    const int BK = 16;
    float* As = (float*)smem;
    float* Bs = (float*)(smem + BK * 128 * 4);

    int ar = tid & 127;
    int ak = (tid >> 7) * 8;
    int as_ = m0 + ar;
    bool avalid = (as_ < seg1);
    const float* Arow = nullptr;
    if (avalid) {
        int src = GATHER ? g_idx[as_] : as_;
        Arow = A + (size_t)src * lda;
    }
    int bk = tid >> 4;
    int bn = (tid & 15) * 8;
    int ty = tid >> 4;
    int tx = tid & 15;

    float muv[8][8];

    for (int half = 0; half < 2; half++) {
        int n0h = n0 + half * 128;
        if (n0h >= N) break;

        float acc[8][8];
#pragma unroll
        for (int i = 0; i < 8; i++)
#pragma unroll
            for (int j = 0; j < 8; j++) acc[i][j] = 0.f;

        for (int k0 = 0; k0 < K; k0 += BK) {
            if (avalid) {
                float4 a0 = *(const float4*)(Arow + k0 + ak);
                float4 a1 = *(const float4*)(Arow + k0 + ak + 4);
                As[(ak + 0) * 128 + ar] = a0.x; As[(ak + 1) * 128 + ar] = a0.y;
                As[(ak + 2) * 128 + ar] = a0.z; As[(ak + 3) * 128 + ar] = a0.w;
                As[(ak + 4) * 128 + ar] = a1.x; As[(ak + 5) * 128 + ar] = a1.y;
                As[(ak + 6) * 128 + ar] = a1.z; As[(ak + 7) * 128 + ar] = a1.w;
            } else {
#pragma unroll
                for (int q = 0; q < 8; q++) As[(ak + q) * 128 + ar] = 0.f;
            }
            {
                const float* Wrow = Wp + (size_t)(k0 + bk) * N + n0h + bn;
                if (n0h + bn + 7 < N) {
                    float4 b0 = *(const float4*)(Wrow);
                    float4 b1 = *(const float4*)(Wrow + 4);
                    Bs[bk * 128 + bn + 0] = b0.x; Bs[bk * 128 + bn + 1] = b0.y;
                    Bs[bk * 128 + bn + 2] = b0.z; Bs[bk * 128 + bn + 3] = b0.w;
                    Bs[bk * 128 + bn + 4] = b1.x; Bs[bk * 128 + bn + 5] = b1.y;
                    Bs[bk * 128 + bn + 6] = b1.z; Bs[bk * 128 + bn + 7] = b1.w;
                } else {
#pragma unroll
                    for (int q = 0; q < 8; q++)
                        Bs[bk * 128 + bn + q] = (n0h + bn + q < N) ? Wrow[q] : 0.f;
                }
            }
            __syncthreads();
#pragma unroll
            for (int k = 0; k < BK; k++) {
                float a[8], b[8];
                *(float4*)&a[0] = *(const float4*)&As[k * 128 + ty * 4];
                *(float4*)&a[4] = *(const float4*)&As[k * 128 + 64 + ty * 4];
                *(float4*)&b[0] = *(const float4*)&Bs[k * 128 + tx * 4];
                *(float4*)&b[4] = *(const float4*)&Bs[k * 128 + 64 + tx * 4];
#pragma unroll
                for (int i = 0; i < 8; i++)
#pragma unroll
                    for (int j = 0; j < 8; j++)
                        acc[i][j] = fmaf(a[i], b[j], acc[i][j]);
            }
            __syncthreads();
        }

#pragma unroll
        for (int i = 0; i < 8; i++) {
            int s = m0 + ((i < 4) ? (ty * 4 + i) : (64 + ty * 4 + i - 4));
            if (s >= seg1) continue;
#pragma unroll
            for (int j = 0; j < 8; j++) {
                int n = n0h + ((j < 4) ? (tx * 4 + j) : (64 + tx * 4 + j - 4));
                if (n >= N) continue;
                float v = acc[i][j] + bp[n];
                if (EPI == 3) {
                    int orig = g_idx[s];
                    int nl = n & 127;
                    size_t mu_off = (size_t)BB * IN_DIM;
                    size_t ls_off = mu_off + (size_t)BB * LAT;
                    if (half == 0) {
                        muv[i][j] = v;
                        out2[mu_off + (size_t)orig * LAT + nl] = v;
                    } else {
                        out2[ls_off + (size_t)orig * LAT + nl] = v;
                        float z = muv[i][j] + expf(v) * eps[(size_t)orig * LAT + nl];
                        C[(size_t)s * ldc + nl] = z;
                    }
                } else {
                    if (EPI == 0)      v = fmaxf(v, 0.f);
                    else if (EPI == 2) v = 1.f / (1.f + expf(-v));
                    size_t orow = (EPI == 2) ? (size_t)g_idx[s] : (size_t)s;
                    C[orow * ldc + n] = v;
                }
            }
        }
        __syncthreads();
    }
#endif
}

extern "C" void kernel_launch(void* const* d_in, const int* in_sizes, int n_in,
                              void* d_out, int out_size) {
    const float* x    = (const float*)d_in[0];
    const int*   task = (const int*)  d_in[1];
    const float* eps  = (const float*)d_in[2];
    const float* eW1  = (const float*)d_in[3];
    const float* eb1  = (const float*)d_in[4];
    const float* eW2  = (const float*)d_in[5];
    const float* eb2  = (const float*)d_in[6];
    const float* eW3  = (const float*)d_in[7];
    const float* eb3  = (const float*)d_in[8];
    const float* eW4  = (const float*)d_in[9];
    const float* eb4  = (const float*)d_in[10];
    const float* dWs1 = (const float*)d_in[11];
    const float* dbs1 = (const float*)d_in[12];
    const float* dWs2 = (const float*)d_in[13];
    const float* dbs2 = (const float*)d_in[14];
    const float* dWh1 = (const float*)d_in[15];
    const float* dbh1 = (const float*)d_in[16];
    const float* dWh2 = (const float*)d_in[17];
    const float* dbh2 = (const float*)d_in[18];
    float* out = (float*)d_out;

    float *bufA, *bufB;
    cudaGetSymbolAddress((void**)&bufA, g_bufA);
    cudaGetSymbolAddress((void**)&bufB, g_bufB);
    char *pE1, *pE2, *pE3, *pE4, *pD1, *pD2, *pD3, *pD4;
    cudaGetSymbolAddress((void**)&pE1, g_pE1);
    cudaGetSymbolAddress((void**)&pE2, g_pE2);
    cudaGetSymbolAddress((void**)&pE3, g_pE3);
    cudaGetSymbolAddress((void**)&pE4, g_pE4);
    cudaGetSymbolAddress((void**)&pD1, g_pD1);
    cudaGetSymbolAddress((void**)&pD2, g_pD2);
    cudaGetSymbolAddress((void**)&pD3, g_pD3);
    cudaGetSymbolAddress((void**)&pD4, g_pD4);

    cudaFuncSetAttribute(tgemm<true,  true,  0, true>,  cudaFuncAttributeMaxDynamicSharedMemorySize, SMEM_TOT_S);
    cudaFuncSetAttribute(tgemm<false, true,  0, true>,  cudaFuncAttributeMaxDynamicSharedMemorySize, SMEM_TOT_S);
    cudaFuncSetAttribute(tgemm<false, true,  3, true>,  cudaFuncAttributeMaxDynamicSharedMemorySize, SMEM_TOT_S);
    cudaFuncSetAttribute(tgemm<false, false, 0, false>, cudaFuncAttributeMaxDynamicSharedMemorySize, SMEM_TOT_P);
    cudaFuncSetAttribute(tgemm<false, true,  0, false>, cudaFuncAttributeMaxDynamicSharedMemorySize, SMEM_TOT_P);
    cudaFuncSetAttribute(tgemm<false, true,  2, false>, cudaFuncAttributeMaxDynamicSharedMemorySize, SMEM_TOT_P);
    cudaFuncSetAttribute(k_pack<true>,  cudaFuncAttributeMaxDynamicSharedMemorySize, 65536);
    cudaFuncSetAttribute(k_pack<false>, cudaFuncAttributeMaxDynamicSharedMemorySize, 32768);

    // grouping + weight pre-pack (per launch; deterministic)
    k_group<<<1, 256>>>(task);
    k_pack<true ><<<dim3(4, 13, NT), 256, 65536>>>(eW1,  IN_DIM, HID,   pE1);
    k_pack<true ><<<dim3(4, 16, NT), 256, 65536>>>(eW2,  HID,    HID,   pE2);
    k_pack<true ><<<dim3(4, 16, NT), 256, 65536>>>(eW3,  HID,    HID,   pE3);
    k_pack<true ><<<dim3(1, 16, NT), 256, 65536>>>(eW4,  HID,    2*LAT, pE4);
    k_pack<false><<<dim3(4, 4,  1 ), 256, 32768>>>(dWs1, LAT,    HID,   pD1);
    k_pack<false><<<dim3(4, 32, 1 ), 256, 32768>>>(dWs2, HID,    HID,   pD2);
    k_pack<false><<<dim3(4, 32, NT), 256, 32768>>>(dWh1, HID,    HID,   pD3);
    k_pack<false><<<dim3(4, 32, NT), 256, 32768>>>(dWh2, HID,    IN_DIM, pD4);

    // encoder — bf16x3 with pre-packed B
    tgemm<true,  true, 0, true><<<dim3(4, YMAX), 256, SMEM_TOT_S>>>(x,    IN_DIM, eW1, pE1, IN_DIM, HID,   eb1, bufA, HID, nullptr, nullptr);
    tgemm<false, true, 0, true><<<dim3(4, YMAX), 256, SMEM_TOT_S>>>(bufA, HID,    eW2, pE2, HID,    HID,   eb2, bufB, HID, nullptr, nullptr);
    tgemm<false, true, 0, true><<<dim3(4, YMAX), 256, SMEM_TOT_S>>>(bufB, HID,    eW3, pE3, HID,    HID,   eb3, bufA, HID, nullptr, nullptr);
    tgemm<false, true, 3, true><<<dim3(1, YMAX), 256, SMEM_TOT_S>>>(bufA, HID,    eW4, pE4, HID,    2*LAT, eb4, bufB, LAT, eps, out);

    // decoder — plain TF32 with pre-packed B
    tgemm<false, false, 0, false><<<dim3(4, 64),   256, SMEM_TOT_P>>>(bufB, LAT, dWs1, pD1, LAT, HID,    dbs1, bufA, HID, nullptr, nullptr);
    tgemm<false, false, 0, false><<<dim3(4, 64),   256, SMEM_TOT_P>>>(bufA, HID, dWs2, pD2, HID, HID,    dbs2, bufB, HID, nullptr, nullptr);
    tgemm<false, true,  0, false><<<dim3(4, YMAX), 256, SMEM_TOT_P>>>(bufB, HID, dWh1, pD3, HID, HID,    dbh1, bufA, HID, nullptr, nullptr);
    tgemm<false, true,  2, false><<<dim3(4, YMAX), 256, SMEM_TOT_P>>>(bufA, HID, dWh2, pD4, HID, IN_DIM, dbh2, out, IN_DIM, nullptr, nullptr);
}

// round 17
// speedup vs baseline: 5.2937x; 1.0134x over previous
#include <cuda_runtime.h>
#include <cuda_bf16.h>
#include <math.h>
#include <cstdint>

#define BB      8192
#define IN_DIM  784
#define HID     1024
#define LAT     128
#define NT      10
#define YMAX    74   // tight bound on sum ceil(cnt_t/128): 64 + NT partials

#if defined(__CUDA_ARCH__) && (__CUDA_ARCH__ == 1030) && \
    (defined(__CUDA_ARCH_FEAT_SM103_ALL) || \
     (defined(__CUDA_ARCH_SPECIFIC__) && (__CUDA_ARCH_SPECIFIC__ >= 1030)))
#define HAS_TC 1
#else
#define HAS_TC 0
#endif

// ---- scratch (static device globals; no allocation) ----
__device__ float g_bufA[BB * HID];
__device__ float g_bufB[BB * HID];
__device__ int   g_idx[BB];
__device__ int   g_off[NT + 1];
__device__ int   g_blk[YMAX + 8];   // packed: task | (yblock<<8)
__device__ int   g_nblk;

// ---- pre-packed weight tiles (byte-exact SMEM tile images) ----
// encoder (bf16 hi||lo, SW128 swizzled, 64KB/tile):
__device__ char g_pE1[(size_t)4 * 13 * 10 * 65536];   // 33.25 MB
__device__ char g_pE2[(size_t)4 * 16 * 10 * 65536];   // 40 MB
__device__ char g_pE3[(size_t)4 * 16 * 10 * 65536];   // 40 MB
__device__ char g_pE4[(size_t)1 * 16 * 10 * 65536];   // 10 MB
// decoder (fp32, SW128 swizzled, 32KB/tile):
__device__ char g_pD1[(size_t)4 * 4  * 1  * 32768];   // 0.5 MB
__device__ char g_pD2[(size_t)4 * 32 * 1  * 32768];   // 4 MB
__device__ char g_pD3[(size_t)4 * 32 * 10 * 32768];   // 40 MB
__device__ char g_pD4[(size_t)4 * 32 * 10 * 32768];   // 40 MB

#define SWZ(o) ((o) ^ (((o) >> 3) & 0x70))

// pack (v0, v1) -> bf16x2 hi pair + residual lo pair (v0 at lower address)
__device__ __forceinline__ void bf16_split2(float v0, float v1,
                                            uint32_t& hp, uint32_t& lp) {
    asm("cvt.rn.bf16x2.f32 %0, %1, %2;" : "=r"(hp) : "f"(v1), "f"(v0));
    float h0 = __uint_as_float(hp << 16);
    float h1 = __uint_as_float(hp & 0xFFFF0000u);
    float l0 = v0 - h0, l1 = v1 - h1;
    asm("cvt.rn.bf16x2.f32 %0, %1, %2;" : "=r"(lp) : "f"(l1), "f"(l0));
}

// ---- single-launch task grouping + block map ----
__global__ void k_group(const int* __restrict__ task) {
    __shared__ int cnt[NT];
    __shared__ int fil[NT];
    int tid = threadIdx.x;
    if (tid < NT) cnt[tid] = 0;
    __syncthreads();
    for (int i = tid; i < BB; i += blockDim.x) atomicAdd(&cnt[task[i]], 1);
    __syncthreads();
    if (tid == 0) {
        int s = 0, nb = 0;
        for (int t = 0; t < NT; t++) {
            g_off[t] = s;
            fil[t] = s;
            int nby = (cnt[t] + 127) >> 7;
            for (int y = 0; y < nby; y++) g_blk[nb++] = t | (y << 8);
            s += cnt[t];
        }
        g_off[NT] = s;
        g_nblk = nb;
    }
    __syncthreads();
    for (int i = tid; i < BB; i += blockDim.x) {
        int t = task[i];
        int p = atomicAdd(&fil[t], 1);
        g_idx[p] = i;
    }
}

// ---- weight pre-pack: W[t][k][n] -> swizzled [n][k] tile images ----
// Stages the tile in SMEM so the final GMEM writes are a linear coalesced
// stream (the direct swizzled STG pattern was 128B-strided -> 1/8 write
// efficiency -> packs ran at 2 TB/s; this is the round-15 fix).
template <bool SPLIT>
__global__ void k_pack(const float* __restrict__ W, int K, int N,
                       char* __restrict__ dst) {
    extern __shared__ char sm[];
    int tid = threadIdx.x;
    int nb = blockIdx.x, c = blockIdx.y, t = blockIdx.z;
    int NB = gridDim.x, NC = gridDim.y;
    const int tilesz = SPLIT ? 65536 : 32768;
    char* tb = dst + (((size_t)t * NB + nb) * NC + c) * (size_t)tilesz;
    int n = nb * 256 + tid;
    bool nv = n < N;
    const float* Wc = W + (size_t)t * K * N + n;
    int k0 = c * (SPLIT ? 64 : 32);
#pragma unroll
    for (int u = 0; u < 8; u++) {
        uint32_t off = SWZ((uint32_t)(tid * 128 + u * 16));
        if (SPLIT) {
            float v[8];
#pragma unroll
            for (int q = 0; q < 8; q++) {
                int k = k0 + u * 8 + q;
                v[q] = (nv && k < K) ? Wc[(size_t)k * N] : 0.f;
            }
            uint32_t h[4], l[4];
            bf16_split2(v[0], v[1], h[0], l[0]);
            bf16_split2(v[2], v[3], h[1], l[1]);
            bf16_split2(v[4], v[5], h[2], l[2]);
            bf16_split2(v[6], v[7], h[3], l[3]);
            *(uint4*)(sm + off)         = make_uint4(h[0], h[1], h[2], h[3]);
            *(uint4*)(sm + 32768 + off) = make_uint4(l[0], l[1], l[2], l[3]);
        } else {
            float v[4];
#pragma unroll
            for (int q = 0; q < 4; q++) {
                int k = k0 + u * 4 + q;
                v[q] = (nv && k < K) ? Wc[(size_t)k * N] : 0.f;
            }
            *(float4*)(sm + off) = make_float4(v[0], v[1], v[2], v[3]);
        }
    }
    __syncthreads();
    // linear coalesced copy SMEM -> GMEM
    const int NQ = tilesz / 4096;   // 16 (split) / 8 (plain)
#pragma unroll
    for (int q = 0; q < NQ; q++) {
        uint4 v = *(const uint4*)(sm + (q * 256 + tid) * 16);
        *(uint4*)(tb + (q * 256 + tid) * 16) = v;
    }
}

// ---------- tcgen05 helpers (arch-specific branch only) ----------
#if HAS_TC
__device__ __forceinline__ uint32_t smem_u32(const void* p) {
    uint32_t a;
    asm("{ .reg .u64 t; cvta.to.shared.u64 t, %1; cvt.u32.u64 %0, t; }" : "=r"(a) : "l"(p));
    return a;
}
__device__ __forceinline__ uint32_t elect1() {
    uint32_t r;
    asm volatile("{ .reg .pred p; elect.sync _|p, 0xFFFFFFFF; selp.b32 %0, 1, 0, p; }" : "=r"(r));
    return r;
}
__device__ __forceinline__ void mbar_init(uint32_t mbar, uint32_t cnt) {
    asm volatile("mbarrier.init.shared.b64 [%0], %1;" :: "r"(mbar), "r"(cnt) : "memory");
}
__device__ __forceinline__ void mbar_wait(uint32_t mbar, uint32_t parity) {
    asm volatile(
        "{\n\t.reg .pred P1;\n\t"
        "WAIT_%=:\n\t"
        "mbarrier.try_wait.parity.acquire.cta.shared::cta.b64 P1, [%0], %1, 0x989680;\n\t"
        "@P1 bra.uni DONE_%=;\n\t"
        "bra.uni WAIT_%=;\n\t"
        "DONE_%=:\n\t}"
        :: "r"(mbar), "r"(parity) : "memory");
}
__device__ __forceinline__ void mma_tf32(uint32_t d, uint64_t ad, uint64_t bd,
                                         uint32_t idesc, uint32_t en) {
    asm volatile(
        "{\n\t.reg .pred p;\n\t"
        "setp.ne.u32 p, %4, 0;\n\t"
        "tcgen05.mma.cta_group::1.kind::tf32 [%0], %1, %2, %3, {%5, %5, %5, %5}, p;\n\t}"
        :: "r"(d), "l"(ad), "l"(bd), "r"(idesc), "r"(en), "r"(0u) : "memory");
}
__device__ __forceinline__ void mma_f16(uint32_t d, uint64_t ad, uint64_t bd,
                                        uint32_t idesc, uint32_t en) {
    asm volatile(
        "{\n\t.reg .pred p;\n\t"
        "setp.ne.u32 p, %4, 0;\n\t"
        "tcgen05.mma.cta_group::1.kind::f16 [%0], %1, %2, %3, {%5, %5, %5, %5}, p;\n\t}"
        :: "r"(d), "l"(ad), "l"(bd), "r"(idesc), "r"(en), "r"(0u) : "memory");
}
__device__ __forceinline__ void tc_commit(uint32_t mbar) {
    asm volatile("tcgen05.commit.cta_group::1.mbarrier::arrive::one.shared::cluster.b64 [%0];"
                 :: "r"(mbar) : "memory");
}

#define TC_LD32(r, addr) \
    asm volatile( \
        "tcgen05.ld.sync.aligned.32x32b.x32.b32 " \
        "{%0, %1, %2, %3, %4, %5, %6, %7, " \
        " %8, %9, %10, %11, %12, %13, %14, %15, " \
        " %16, %17, %18, %19, %20, %21, %22, %23, " \
        " %24, %25, %26, %27, %28, %29, %30, %31}, [%32];" \
        : "=r"((r)[0]),  "=r"((r)[1]),  "=r"((r)[2]),  "=r"((r)[3]), \
          "=r"((r)[4]),  "=r"((r)[5]),  "=r"((r)[6]),  "=r"((r)[7]), \
          "=r"((r)[8]),  "=r"((r)[9]),  "=r"((r)[10]), "=r"((r)[11]), \
          "=r"((r)[12]), "=r"((r)[13]), "=r"((r)[14]), "=r"((r)[15]), \
          "=r"((r)[16]), "=r"((r)[17]), "=r"((r)[18]), "=r"((r)[19]), \
          "=r"((r)[20]), "=r"((r)[21]), "=r"((r)[22]), "=r"((r)[23]), \
          "=r"((r)[24]), "=r"((r)[25]), "=r"((r)[26]), "=r"((r)[27]), \
          "=r"((r)[28]), "=r"((r)[29]), "=r"((r)[30]), "=r"((r)[31]) \
        : "r"(addr))

static constexpr uint64_t DESC_BASE =
    (2ull << 61) | (1ull << 46) | (64ull << 32) | (1ull << 16);
__device__ __forceinline__ uint64_t mkdesc(uint32_t a) {
    return DESC_BASE | ((uint64_t)(a >> 4) & 0x3FFF);
}
#endif  // HAS_TC

// ---------- grouped GEMM: 128 x 256 tile per CTA ----------
#define NTILE 256
#define KC    32
#define KCB   64
#define SMEM_TMEM 0
#define SMEM_MB   16
#define SA_OFF    1024
#define STAGE_P   49152
#define STAGE_S   98304
#define SMEM_TOT_P (SA_OFF + 2 * STAGE_P)   //  99328
#define SMEM_TOT_S (SA_OFF + 2 * STAGE_S)   // 197632
#define EPI_PITCH 132
#define EPI_PITCH3 260

static constexpr uint32_t IDESC_TF32 =
    (1u << 4) | (2u << 7) | (2u << 10) | ((NTILE / 8) << 17) | ((128 / 16) << 24);
static constexpr uint32_t IDESC_BF16 =
    (1u << 4) | (1u << 7) | (1u << 10) | ((NTILE / 8) << 17) | ((128 / 16) << 24);

// EPI: 0 bias+relu, 2 bias+sigmoid+row-scatter, 3 fused reparam (enc4)
// SPLIT: bf16x3 emulated-fp32 (pre-packed hi/lo tiles)
template <bool GATHER, bool PERTASK, int EPI, bool SPLIT>
__global__ __launch_bounds__(256, SPLIT ? 1 : 2) void tgemm(
    const float* __restrict__ A, int lda,
    const float* __restrict__ W, const char* __restrict__ Wpk, int K, int N,
    const float* __restrict__ bias,
    float* __restrict__ C, int ldc,
    const float* __restrict__ eps, float* __restrict__ out2)
{
    extern __shared__ __align__(1024) char smem[];

    int t = 0, seg0 = 0, seg1 = BB, m0;
    if (PERTASK) {
        if ((int)blockIdx.y >= g_nblk) return;
        int bv = g_blk[blockIdx.y];
        t    = bv & 255;
        seg0 = g_off[t];
        seg1 = g_off[t + 1];
        m0   = seg0 + (bv >> 8) * 128;
    } else {
        m0 = blockIdx.y * 128;
    }
    int n0 = blockIdx.x * NTILE;

    const float* bp = bias + (PERTASK ? (size_t)t * N : 0);

    int tid = threadIdx.x;

#if HAS_TC
    // ================= tcgen05 path =================
    const int STAGE_B = SPLIT ? STAGE_S : STAGE_P;
    const int KCC     = SPLIT ? KCB : KC;
    uint32_t sb = smem_u32(smem);
    int wid = tid >> 5;
    int lid = tid & 31;

    if (wid == 0) {
        asm volatile("tcgen05.alloc.cta_group::1.sync.aligned.shared::cta.b32 [%0], %1;"
                     :: "r"(sb + SMEM_TMEM), "r"(256u) : "memory");
        asm volatile("tcgen05.relinquish_alloc_permit.cta_group::1.sync.aligned;");
    }
    if (tid == 0) { mbar_init(sb + SMEM_MB, 1); mbar_init(sb + SMEM_MB + 8, 1); }
    __syncthreads();
    uint32_t tmem;
    asm volatile("ld.shared.b32 %0, [%1];" : "=r"(tmem) : "r"(sb + SMEM_TMEM));

    int nch = (K + KCC - 1) / KCC;
    int ph[2] = {0, 0};

    int a_ke = (tid & 7) * (SPLIT ? 8 : 4);
    int a_mb = tid >> 3;
    const float* Ar[4];
#pragma unroll
    for (int p = 0; p < 4; p++) {
        int gs = m0 + p * 32 + a_mb;
        int src = (gs < seg1) ? (GATHER ? g_idx[gs] : gs)
                              : (GATHER ? g_idx[seg0] : seg0);
        Ar[p] = A + (size_t)src * lda + a_ke;
    }
    // packed-weight tile base for this (t, n-block)
    const size_t tilesz = SPLIT ? 65536 : 32768;
    const char* tb0 = Wpk + (((size_t)t * gridDim.x + blockIdx.x) * (size_t)nch) * tilesz;

    for (int c = 0; c < nch; c++) {
        int s = c & 1;
        if (c >= 2) { mbar_wait(sb + SMEM_MB + 8 * s, ph[s]); ph[s] ^= 1; }
        int k0 = c * KCC;
        char* sAh = smem + SA_OFF + s * STAGE_B;
        char* sAl = sAh + 16384;
        char* sBh = smem + SA_OFF + (SPLIT ? 32768 : 16384) + s * STAGE_B;

        if (SPLIT) {
            // A tile [m=128][k=64] bf16 hi/lo (on-the-fly split of activations)
#pragma unroll
            for (int p = 0; p < 4; p++) {
                int m = p * 32 + a_mb;
                float4 v0 = make_float4(0.f, 0.f, 0.f, 0.f);
                float4 v1 = make_float4(0.f, 0.f, 0.f, 0.f);
                if (k0 + a_ke < K)     v0 = *(const float4*)(Ar[p] + k0);
                if (k0 + a_ke + 4 < K) v1 = *(const float4*)(Ar[p] + k0 + 4);
                uint32_t h[4], l[4];
                bf16_split2(v0.x, v0.y, h[0], l[0]);
                bf16_split2(v0.z, v0.w, h[1], l[1]);
                bf16_split2(v1.x, v1.y, h[2], l[2]);
                bf16_split2(v1.z, v1.w, h[3], l[3]);
                uint32_t off = SWZ((uint32_t)(m * 128 + a_ke * 2));
                *(uint4*)(sAh + off) = make_uint4(h[0], h[1], h[2], h[3]);
                *(uint4*)(sAl + off) = make_uint4(l[0], l[1], l[2], l[3]);
            }
            // B tile: linear 64KB copy of pre-packed hi||lo image
            const char* tb = tb0 + (size_t)c * 65536;
#pragma unroll
            for (int q = 0; q < 16; q++) {
                uint4 v = *(const uint4*)(tb + (q * 256 + tid) * 16);
                *(uint4*)(sBh + (q * 256 + tid) * 16) = v;
            }
        } else {
            // A tile [m=128][k=32] fp32
#pragma unroll
            for (int p = 0; p < 4; p++) {
                int m = p * 32 + a_mb;
                float4 v = make_float4(0.f, 0.f, 0.f, 0.f);
                if (k0 + a_ke < K)
                    v = *(const float4*)(Ar[p] + k0);
                *(float4*)(sAh + SWZ((uint32_t)(m * KC + a_ke) * 4)) = v;
            }
            // B tile: linear 32KB copy of pre-packed fp32 image
            const char* tb = tb0 + (size_t)c * 32768;
#pragma unroll
            for (int q = 0; q < 8; q++) {
                uint4 v = *(const uint4*)(tb + (q * 256 + tid) * 16);
                *(uint4*)(sBh + (q * 256 + tid) * 16) = v;
            }
        }
        __syncthreads();

        if (wid == 0) {
            asm volatile("fence.proxy.async.shared::cta;" ::: "memory");
            if (elect1()) {
                uint64_t adh = mkdesc(smem_u32(sAh));
                uint64_t bdh = mkdesc(smem_u32(sBh));
                if (SPLIT) {
                    uint64_t adl = mkdesc(smem_u32(sAl));
                    uint64_t bdl = bdh + 2048;   // lo plane at +32768 bytes = +2048 units
#pragma unroll
                    for (int j = 0; j < 4; j++) {
                        mma_f16(tmem, adl + j * 2, bdh + j * 2, IDESC_BF16,
                                (c > 0 || j > 0) ? 1u : 0u);
                        mma_f16(tmem, adh + j * 2, bdl + j * 2, IDESC_BF16, 1u);
                        mma_f16(tmem, adh + j * 2, bdh + j * 2, IDESC_BF16, 1u);
                    }
                } else {
#pragma unroll
                    for (int j = 0; j < 4; j++)
                        mma_tf32(tmem, adh + j * 2, bdh + j * 2, IDESC_TF32,
                                 (c > 0 || j > 0) ? 1u : 0u);
                }
                tc_commit(sb + SMEM_MB + 8 * s);
            }
        }
    }

    int sl = (nch - 1) & 1;
    mbar_wait(sb + SMEM_MB + 8 * sl, ph[sl]);
    asm volatile("tcgen05.fence::after_thread_sync;" ::: "memory");
    __syncthreads();

    float* stg = (float*)(smem + SA_OFF);
    int rw = wid & 3;
    int cq = wid >> 2;

    if (EPI == 3) {
        // ---- fused reparameterization epilogue (enc4: N == 256 == 2*LAT) ----
#pragma unroll
        for (int half = 0; half < 2; half++)
#pragma unroll
            for (int i = 0; i < 2; i++) {
                uint32_t r[32];
                TC_LD32(r, tmem + half * 128 + cq * 64 + i * 32);
                asm volatile("tcgen05.wait::ld.sync.aligned;" ::: "memory");
                float* dst = stg + (rw * 32 + lid) * EPI_PITCH3 + half * 128 + cq * 64 + i * 32;
#pragma unroll
                for (int q = 0; q < 8; q++)
                    *(float4*)(dst + q * 4) = make_float4(
                        __uint_as_float(r[q * 4 + 0]), __uint_as_float(r[q * 4 + 1]),
                        __uint_as_float(r[q * 4 + 2]), __uint_as_float(r[q * 4 + 3]));
            }
        __syncthreads();

        int nb = lid * 4;
        float4 bmu = *(const float4*)(bp + nb);
        float4 bls = *(const float4*)(bp + 128 + nb);
        size_t mu_off = (size_t)BB * IN_DIM;
        size_t ls_off = mu_off + (size_t)BB * LAT;
#pragma unroll
        for (int rr = 0; rr < 16; rr++) {
            int r = wid * 16 + rr;
            int grow = m0 + r;
            if (grow < seg1) {
                float4 mu = *(float4*)(stg + r * EPI_PITCH3 + nb);
                float4 lv = *(float4*)(stg + r * EPI_PITCH3 + 128 + nb);
                mu.x += bmu.x; mu.y += bmu.y; mu.z += bmu.z; mu.w += bmu.w;
                lv.x += bls.x; lv.y += bls.y; lv.z += bls.z; lv.w += bls.w;
                int orig = g_idx[grow];
                float4 ep = *(const float4*)(eps + (size_t)orig * LAT + nb);
                float4 z;
                z.x = mu.x + expf(lv.x) * ep.x;
                z.y = mu.y + expf(lv.y) * ep.y;
                z.z = mu.z + expf(lv.z) * ep.z;
                z.w = mu.w + expf(lv.w) * ep.w;
                *(float4*)(out2 + mu_off + (size_t)orig * LAT + nb) = mu;
                *(float4*)(out2 + ls_off + (size_t)orig * LAT + nb) = lv;
                *(float4*)(C + (size_t)grow * ldc + nb) = z;
            }
        }
        __syncthreads();
    } else {
        // ---- staged transpose epilogue (coalesced STG) ----
        for (int half = 0; half < 2; half++) {
#pragma unroll
            for (int i = 0; i < 2; i++) {
                uint32_t r[32];
                TC_LD32(r, tmem + half * 128 + cq * 64 + i * 32);
                asm volatile("tcgen05.wait::ld.sync.aligned;" ::: "memory");
                float* dst = stg + (rw * 32 + lid) * EPI_PITCH + cq * 64 + i * 32;
#pragma unroll
                for (int q = 0; q < 8; q++)
                    *(float4*)(dst + q * 4) = make_float4(
                        __uint_as_float(r[q * 4 + 0]), __uint_as_float(r[q * 4 + 1]),
                        __uint_as_float(r[q * 4 + 2]), __uint_as_float(r[q * 4 + 3]));
            }
            __syncthreads();

            int nb = n0 + half * 128 + lid * 4;
            bool nv = nb < N;
            float4 bz = make_float4(0.f, 0.f, 0.f, 0.f);
            if (nv) bz = *(const float4*)(bp + nb);
#pragma unroll
            for (int rr = 0; rr < 16; rr++) {
                int r = wid * 16 + rr;
                int grow = m0 + r;
                if (grow < seg1 && nv) {
                    float4 v = *(float4*)(stg + r * EPI_PITCH + lid * 4);
                    v.x += bz.x; v.y += bz.y; v.z += bz.z; v.w += bz.w;
                    if (EPI == 0) {
                        v.x = fmaxf(v.x, 0.f); v.y = fmaxf(v.y, 0.f);
                        v.z = fmaxf(v.z, 0.f); v.w = fmaxf(v.w, 0.f);
                    } else if (EPI == 2) {
                        v.x = 1.f / (1.f + expf(-v.x));
                        v.y = 1.f / (1.f + expf(-v.y));
                        v.z = 1.f / (1.f + expf(-v.z));
                        v.w = 1.f / (1.f + expf(-v.w));
                    }
                    size_t orow = (EPI == 2) ? (size_t)g_idx[grow] : (size_t)grow;
                    *(float4*)(C + orow * ldc + nb) = v;
                }
            }
            __syncthreads();
        }
    }

    asm volatile("tcgen05.fence::before_thread_sync;" ::: "memory");
    __syncthreads();
    if (wid == 0)
        asm volatile("tcgen05.dealloc.cta_group::1.sync.aligned.b32 %0, %1;"
                     :: "r"(tmem), "r"(256u));

#else
    // ================= fp32 SIMT fallback (uses original W layout) =================
    const float* Wp = W + (PERTASK ? (size_t)t * K * N : 0);
    const int BK = 16;
    float* As = (float*)smem;
    float* Bs = (float*)(smem + BK * 128 * 4);

    int ar = tid & 127;
    int ak = (tid >> 7) * 8;
    int as_ = m0 + ar;
    bool avalid = (as_ < seg1);
    const float* Arow = nullptr;
    if (avalid) {
        int src = GATHER ? g_idx[as_] : as_;
        Arow = A + (size_t)src * lda;
    }
    int bk = tid >> 4;
    int bn = (tid & 15) * 8;
    int ty = tid >> 4;
    int tx = tid & 15;

    float muv[8][8];

    for (int half = 0; half < 2; half++) {
        int n0h = n0 + half * 128;
        if (n0h >= N) break;

        float acc[8][8];
#pragma unroll
        for (int i = 0; i < 8; i++)
#pragma unroll
            for (int j = 0; j < 8; j++) acc[i][j] = 0.f;

        for (int k0 = 0; k0 < K; k0 += BK) {
            if (avalid) {
                float4 a0 = *(const float4*)(Arow + k0 + ak);
                float4 a1 = *(const float4*)(Arow + k0 + ak + 4);
                As[(ak + 0) * 128 + ar] = a0.x; As[(ak + 1) * 128 + ar] = a0.y;
                As[(ak + 2) * 128 + ar] = a0.z; As[(ak + 3) * 128 + ar] = a0.w;
                As[(ak + 4) * 128 + ar] = a1.x; As[(ak + 5) * 128 + ar] = a1.y;
                As[(ak + 6) * 128 + ar] = a1.z; As[(ak + 7) * 128 + ar] = a1.w;
            } else {
#pragma unroll
                for (int q = 0; q < 8; q++) As[(ak + q) * 128 + ar] = 0.f;
            }
            {
                const float* Wrow = Wp + (size_t)(k0 + bk) * N + n0h + bn;
                if (n0h + bn + 7 < N) {
                    float4 b0 = *(const float4*)(Wrow);
                    float4 b1 = *(const float4*)(Wrow + 4);
                    Bs[bk * 128 + bn + 0] = b0.x; Bs[bk * 128 + bn + 1] = b0.y;
                    Bs[bk * 128 + bn + 2] = b0.z; Bs[bk * 128 + bn + 3] = b0.w;
                    Bs[bk * 128 + bn + 4] = b1.x; Bs[bk * 128 + bn + 5] = b1.y;
                    Bs[bk * 128 + bn + 6] = b1.z; Bs[bk * 128 + bn + 7] = b1.w;
                } else {
#pragma unroll
                    for (int q = 0; q < 8; q++)
                        Bs[bk * 128 + bn + q] = (n0h + bn + q < N) ? Wrow[q] : 0.f;
                }
            }
            __syncthreads();
#pragma unroll
            for (int k = 0; k < BK; k++) {
                float a[8], b[8];
                *(float4*)&a[0] = *(const float4*)&As[k * 128 + ty * 4];
                *(float4*)&a[4] = *(const float4*)&As[k * 128 + 64 + ty * 4];
                *(float4*)&b[0] = *(const float4*)&Bs[k * 128 + tx * 4];
                *(float4*)&b[4] = *(const float4*)&Bs[k * 128 + 64 + tx * 4];
#pragma unroll
                for (int i = 0; i < 8; i++)
#pragma unroll
                    for (int j = 0; j < 8; j++)
                        acc[i][j] = fmaf(a[i], b[j], acc[i][j]);
            }
            __syncthreads();
        }

#pragma unroll
        for (int i = 0; i < 8; i++) {
            int s = m0 + ((i < 4) ? (ty * 4 + i) : (64 + ty * 4 + i - 4));
            if (s >= seg1) continue;
#pragma unroll
            for (int j = 0; j < 8; j++) {
                int n = n0h + ((j < 4) ? (tx * 4 + j) : (64 + tx * 4 + j - 4));
                if (n >= N) continue;
                float v = acc[i][j] + bp[n];
                if (EPI == 3) {
                    int orig = g_idx[s];
                    int nl = n & 127;
                    size_t mu_off = (size_t)BB * IN_DIM;
                    size_t ls_off = mu_off + (size_t)BB * LAT;
                    if (half == 0) {
                        muv[i][j] = v;
                        out2[mu_off + (size_t)orig * LAT + nl] = v;
                    } else {
                        out2[ls_off + (size_t)orig * LAT + nl] = v;
                        float z = muv[i][j] + expf(v) * eps[(size_t)orig * LAT + nl];
                        C[(size_t)s * ldc + nl] = z;
                    }
                } else {
                    if (EPI == 0)      v = fmaxf(v, 0.f);
                    else if (EPI == 2) v = 1.f / (1.f + expf(-v));
                    size_t orow = (EPI == 2) ? (size_t)g_idx[s] : (size_t)s;
                    C[orow * ldc + n] = v;
                }
            }
        }
        __syncthreads();
    }
#endif
}

extern "C" void kernel_launch(void* const* d_in, const int* in_sizes, int n_in,
                              void* d_out, int out_size) {
    const float* x    = (const float*)d_in[0];
    const int*   task = (const int*)  d_in[1];
    const float* eps  = (const float*)d_in[2];
    const float* eW1  = (const float*)d_in[3];
    const float* eb1  = (const float*)d_in[4];
    const float* eW2  = (const float*)d_in[5];
    const float* eb2  = (const float*)d_in[6];
    const float* eW3  = (const float*)d_in[7];
    const float* eb3  = (const float*)d_in[8];
    const float* eW4  = (const float*)d_in[9];
    const float* eb4  = (const float*)d_in[10];
    const float* dWs1 = (const float*)d_in[11];
    const float* dbs1 = (const float*)d_in[12];
    const float* dWs2 = (const float*)d_in[13];
    const float* dbs2 = (const float*)d_in[14];
    const float* dWh1 = (const float*)d_in[15];
    const float* dbh1 = (const float*)d_in[16];
    const float* dWh2 = (const float*)d_in[17];
    const float* dbh2 = (const float*)d_in[18];
    float* out = (float*)d_out;

    float *bufA, *bufB;
    cudaGetSymbolAddress((void**)&bufA, g_bufA);
    cudaGetSymbolAddress((void**)&bufB, g_bufB);
    char *pE1, *pE2, *pE3, *pE4, *pD1, *pD2, *pD3, *pD4;
    cudaGetSymbolAddress((void**)&pE1, g_pE1);
    cudaGetSymbolAddress((void**)&pE2, g_pE2);
    cudaGetSymbolAddress((void**)&pE3, g_pE3);
    cudaGetSymbolAddress((void**)&pE4, g_pE4);
    cudaGetSymbolAddress((void**)&pD1, g_pD1);
    cudaGetSymbolAddress((void**)&pD2, g_pD2);
    cudaGetSymbolAddress((void**)&pD3, g_pD3);
    cudaGetSymbolAddress((void**)&pD4, g_pD4);

    cudaFuncSetAttribute(tgemm<true,  true,  0, true>,  cudaFuncAttributeMaxDynamicSharedMemorySize, SMEM_TOT_S);
    cudaFuncSetAttribute(tgemm<false, true,  0, true>,  cudaFuncAttributeMaxDynamicSharedMemorySize, SMEM_TOT_S);
    cudaFuncSetAttribute(tgemm<false, true,  3, true>,  cudaFuncAttributeMaxDynamicSharedMemorySize, SMEM_TOT_S);
    cudaFuncSetAttribute(tgemm<false, false, 0, false>, cudaFuncAttributeMaxDynamicSharedMemorySize, SMEM_TOT_P);
    cudaFuncSetAttribute(tgemm<false, true,  0, false>, cudaFuncAttributeMaxDynamicSharedMemorySize, SMEM_TOT_P);
    cudaFuncSetAttribute(tgemm<false, true,  2, false>, cudaFuncAttributeMaxDynamicSharedMemorySize, SMEM_TOT_P);
    cudaFuncSetAttribute(k_pack<true>,  cudaFuncAttributeMaxDynamicSharedMemorySize, 65536);
    cudaFuncSetAttribute(k_pack<false>, cudaFuncAttributeMaxDynamicSharedMemorySize, 32768);

    // grouping + weight pre-pack (per launch; deterministic)
    k_group<<<1, 256>>>(task);
    k_pack<true ><<<dim3(4, 13, NT), 256, 65536>>>(eW1,  IN_DIM, HID,   pE1);
    k_pack<true ><<<dim3(4, 16, NT), 256, 65536>>>(eW2,  HID,    HID,   pE2);
    k_pack<true ><<<dim3(4, 16, NT), 256, 65536>>>(eW3,  HID,    HID,   pE3);
    k_pack<true ><<<dim3(1, 16, NT), 256, 65536>>>(eW4,  HID,    2*LAT, pE4);
    k_pack<false><<<dim3(4, 4,  1 ), 256, 32768>>>(dWs1, LAT,    HID,   pD1);
    k_pack<false><<<dim3(4, 32, 1 ), 256, 32768>>>(dWs2, HID,    HID,   pD2);
    k_pack<false><<<dim3(4, 32, NT), 256, 32768>>>(dWh1, HID,    HID,   pD3);
    k_pack<false><<<dim3(4, 32, NT), 256, 32768>>>(dWh2, HID,    IN_DIM, pD4);

    // encoder — bf16x3 with pre-packed B
    tgemm<true,  true, 0, true><<<dim3(4, YMAX), 256, SMEM_TOT_S>>>(x,    IN_DIM, eW1, pE1, IN_DIM, HID,   eb1, bufA, HID, nullptr, nullptr);
    tgemm<false, true, 0, true><<<dim3(4, YMAX), 256, SMEM_TOT_S>>>(bufA, HID,    eW2, pE2, HID,    HID,   eb2, bufB, HID, nullptr, nullptr);
    tgemm<false, true, 0, true><<<dim3(4, YMAX), 256, SMEM_TOT_S>>>(bufB, HID,    eW3, pE3, HID,    HID,   eb3, bufA, HID, nullptr, nullptr);
    tgemm<false, true, 3, true><<<dim3(1, YMAX), 256, SMEM_TOT_S>>>(bufA, HID,    eW4, pE4, HID,    2*LAT, eb4, bufB, LAT, eps, out);

    // decoder — plain TF32 with pre-packed B
    tgemm<false, false, 0, false><<<dim3(4, 64),   256, SMEM_TOT_P>>>(bufB, LAT, dWs1, pD1, LAT, HID,    dbs1, bufA, HID, nullptr, nullptr);
    tgemm<false, false, 0, false><<<dim3(4, 64),   256, SMEM_TOT_P>>>(bufA, HID, dWs2, pD2, HID, HID,    dbs2, bufB, HID, nullptr, nullptr);
    tgemm<false, true,  0, false><<<dim3(4, YMAX), 256, SMEM_TOT_P>>>(bufB, HID, dWh1, pD3, HID, HID,    dbh1, bufA, HID, nullptr, nullptr);
    tgemm<false, true,  2, false><<<dim3(4, YMAX), 256, SMEM_TOT_P>>>(bufA, HID, dWh2, pD4, HID, IN_DIM, dbh2, out, IN_DIM, nullptr, nullptr);
}